// round 2
// baseline (speedup 1.0000x reference)
#include <cuda_runtime.h>
#include <math.h>
#include <stdint.h>

// Shapes (fixed by the problem)
// B=2, C=128, M=4, K=4, V=64, D=1024, H=16, A=64, L=4, HF=2048, E=8, S=C*E=1024
// rows = B*S = 2048

// ---------------- scratch (no allocations allowed) ----------------
// Offsets (floats):
//  x      : 2*1024*1024 = 2097152
//  xn     : 2097152
//  x1     : 2097152
//  qkv    : 2048*3072   = 6291456
//  qr     : 2097152
//  kt     : 2097152
//  vr     : 2097152
//  attn   : 2097152
//  up     : 2048*4096   = 8388608
//  hb     : 2048*2048   = 4194304
//  tmp1   : 1024*256    = 262144
//  u      : 262144
//  xdec   : 1024*1024   = 1048576
// total = 35127296 floats (~140.5 MB)
__device__ float g_scratch[35127296];

static const size_t OFF_X    = 0;
static const size_t OFF_XN   = 2097152;
static const size_t OFF_X1   = 4194304;
static const size_t OFF_QKV  = 6291456;
static const size_t OFF_QR   = 12582912;
static const size_t OFF_KT   = 14680064;
static const size_t OFF_VR   = 16777216;
static const size_t OFF_ATTN = 18874368;
static const size_t OFF_UP   = 20971520;
static const size_t OFF_HB   = 29360128;
static const size_t OFF_TMP1 = 33554432;
static const size_t OFF_U    = 33816576;
static const size_t OFF_XDEC = 34078720;

// ---------------- SGEMM: C[m,n] = sum_k A[m,k]*B[n,k] (+ R[m,n]) ----------------
// A: MxK row-major, B: NxK row-major (weight layout), tile 128x128x16, 256 thr, 8x8/thread.
__global__ void __launch_bounds__(256) sgemm_k(
    const float* __restrict__ A, const float* __restrict__ Bm,
    float* __restrict__ C, const float* __restrict__ Radd,
    int M, int N, int K)
{
    __shared__ float As[16][132];
    __shared__ float Bs[16][132];
    const int tid = threadIdx.x;
    const int m0 = blockIdx.y * 128;
    const int n0 = blockIdx.x * 128;
    const int tx = tid & 15;        // n-direction
    const int ty = tid >> 4;        // m-direction
    const int lr = tid >> 2;        // 0..63  (load row)
    const int lc = (tid & 3) << 2;  // 0,4,8,12 (load col, float4)
    const float* Ag = A + (size_t)(m0 + lr) * K + lc;
    const float* Bg = Bm + (size_t)(n0 + lr) * K + lc;
    const size_t stride64 = (size_t)64 * K;

    float acc[8][8];
    #pragma unroll
    for (int i = 0; i < 8; i++)
        #pragma unroll
        for (int j = 0; j < 8; j++) acc[i][j] = 0.f;

    for (int k0 = 0; k0 < K; k0 += 16) {
        float4 a0 = *(const float4*)(Ag + k0);
        float4 a1 = *(const float4*)(Ag + k0 + stride64);
        float4 b0 = *(const float4*)(Bg + k0);
        float4 b1 = *(const float4*)(Bg + k0 + stride64);
        __syncthreads();
        As[lc+0][lr]    = a0.x; As[lc+1][lr]    = a0.y; As[lc+2][lr]    = a0.z; As[lc+3][lr]    = a0.w;
        As[lc+0][lr+64] = a1.x; As[lc+1][lr+64] = a1.y; As[lc+2][lr+64] = a1.z; As[lc+3][lr+64] = a1.w;
        Bs[lc+0][lr]    = b0.x; Bs[lc+1][lr]    = b0.y; Bs[lc+2][lr]    = b0.z; Bs[lc+3][lr]    = b0.w;
        Bs[lc+0][lr+64] = b1.x; Bs[lc+1][lr+64] = b1.y; Bs[lc+2][lr+64] = b1.z; Bs[lc+3][lr+64] = b1.w;
        __syncthreads();
        #pragma unroll
        for (int kk = 0; kk < 16; kk++) {
            float av[8], bv[8];
            *(float4*)(av)     = *(const float4*)&As[kk][ty*8];
            *(float4*)(av + 4) = *(const float4*)&As[kk][ty*8 + 4];
            *(float4*)(bv)     = *(const float4*)&Bs[kk][tx*8];
            *(float4*)(bv + 4) = *(const float4*)&Bs[kk][tx*8 + 4];
            #pragma unroll
            for (int i = 0; i < 8; i++)
                #pragma unroll
                for (int j = 0; j < 8; j++)
                    acc[i][j] += av[i] * bv[j];
        }
    }

    #pragma unroll
    for (int i = 0; i < 8; i++) {
        int m = m0 + ty*8 + i;
        #pragma unroll
        for (int j = 0; j < 8; j += 4) {
            int n = n0 + tx*8 + j;
            float4 v;
            v.x = acc[i][j]; v.y = acc[i][j+1]; v.z = acc[i][j+2]; v.w = acc[i][j+3];
            if (Radd) {
                float4 r = *(const float4*)&Radd[(size_t)m * N + n];
                v.x += r.x; v.y += r.y; v.z += r.z; v.w += r.w;
            }
            *(float4*)&C[(size_t)m * N + n] = v;
        }
    }
}

// ---------------- RMSNorm (one block per row, D=1024) ----------------
__global__ void __launch_bounds__(256) rmsnorm_k(
    const float* __restrict__ x, const float* __restrict__ w, float* __restrict__ y)
{
    const int row = blockIdx.x;
    const float* xr = x + (size_t)row * 1024;
    float s = 0.f;
    for (int i = threadIdx.x; i < 1024; i += 256) { float v = xr[i]; s += v * v; }
    #pragma unroll
    for (int o = 16; o; o >>= 1) s += __shfl_xor_sync(0xffffffffu, s, o);
    __shared__ float red[8];
    const int warp = threadIdx.x >> 5, lane = threadIdx.x & 31;
    if (lane == 0) red[warp] = s;
    __syncthreads();
    float tot = 0.f;
    #pragma unroll
    for (int i = 0; i < 8; i++) tot += red[i];
    const float inv = rsqrtf(tot * (1.f / 1024.f) + 1e-5f);
    float* yr = y + (size_t)row * 1024;
    for (int i = threadIdx.x; i < 1024; i += 256) yr[i] = xr[i] * inv * w[i];
}

// ---------------- l2norm + RoPE + layout shuffle ----------------
// grid (H=16, S=1024, B=2), 64 threads (one per head-dim element)
__global__ void __launch_bounds__(64) qkrope_k(
    const float* __restrict__ qkv, float* __restrict__ qr,
    float* __restrict__ kt, float* __restrict__ vr)
{
    const int h = blockIdx.x, s = blockIdx.y, b = blockIdx.z;
    const int a = threadIdx.x;
    const float* base = qkv + ((size_t)b * 1024 + s) * 3072 + h * 64 + a;
    float q = base[0];
    float k = base[1024];
    float v = base[2048];

    float sq = q * q, sk = k * k;
    #pragma unroll
    for (int o = 16; o; o >>= 1) {
        sq += __shfl_xor_sync(0xffffffffu, sq, o);
        sk += __shfl_xor_sync(0xffffffffu, sk, o);
    }
    __shared__ float red[4];
    __shared__ float sqv[64], skv[64];
    const int warp = a >> 5;
    if ((a & 31) == 0) { red[warp * 2] = sq; red[warp * 2 + 1] = sk; }
    __syncthreads();
    const float nq = sqrtf(red[0] + red[2]);
    const float nk = sqrtf(red[1] + red[3]);
    q = q / fmaxf(nq, 1e-5f);
    k = k / fmaxf(nk, 1e-5f);
    sqv[a] = q; skv[a] = k;
    __syncthreads();

    const int i = a & 31;
    const double ang = (double)s * pow(10000.0, -(double)i / 32.0);
    const float cz = (float)cos(ang), sz = (float)sin(ang);
    const float qp = sqv[a ^ 32], kp = skv[a ^ 32];
    const float qo = (a < 32) ? (q * cz + qp * sz) : (q * cz - qp * sz);
    const float ko = (a < 32) ? (k * cz + kp * sz) : (k * cz - kp * sz);

    const size_t bh = (size_t)b * 16 + h;
    qr[(bh * 1024 + s) * 64 + a] = qo;
    kt[(bh * 64 + a) * 1024 + s] = ko;       // K transposed: (b,h,a,s)
    vr[(bh * 1024 + s) * 64 + a] = v;
}

// ---------------- attention: block per (b,h, 8-query tile) ----------------
__global__ void __launch_bounds__(256) attn_k(
    const float* __restrict__ qr, const float* __restrict__ kt,
    const float* __restrict__ vr, const int* __restrict__ doc,
    float* __restrict__ attn)
{
    const int qt = blockIdx.x, h = blockIdx.y, b = blockIdx.z;
    const int q0 = qt * 8;
    __shared__ float sQ[8][64];
    __shared__ float sS[8][1024];
    __shared__ float sRed[4][8][64];
    __shared__ int sDoc[128];
    const int tid = threadIdx.x;
    if (tid < 128) sDoc[tid] = doc[b * 128 + tid];
    const size_t bh = (size_t)b * 16 + h;
    for (int i = tid; i < 8 * 64; i += 256) {
        int q = i >> 6, a = i & 63;
        sQ[q][a] = qr[(bh * 1024 + q0 + q) * 64 + a];
    }
    __syncthreads();

    // Q@K^T: thread handles keys k = tid + 256*j (j=0..3); kt read once per block.
    const float* ktp = kt + bh * 64 * 1024;
    float s[8][4];
    #pragma unroll
    for (int q = 0; q < 8; q++)
        #pragma unroll
        for (int j = 0; j < 4; j++) s[q][j] = 0.f;
    for (int a = 0; a < 64; a++) {
        float kv[4];
        #pragma unroll
        for (int j = 0; j < 4; j++) kv[j] = ktp[a * 1024 + tid + j * 256];
        #pragma unroll
        for (int q = 0; q < 8; q++) {
            const float qa = sQ[q][a];
            #pragma unroll
            for (int j = 0; j < 4; j++) s[q][j] += qa * kv[j];
        }
    }

    // mask + scale, write scores to smem
    #pragma unroll
    for (int q = 0; q < 8; q++) {
        const int blkq = (q0 + q) >> 3;
        const int dq = sDoc[blkq];
        #pragma unroll
        for (int j = 0; j < 4; j++) {
            const int k = tid + j * 256;
            const int blkk = k >> 3;
            const bool ok = (blkq == blkk) ||
                            ((blkq >= blkk) && ((k & 7) < 4) && (dq == sDoc[blkk]));
            sS[q][k] = ok ? s[q][j] * 0.125f : -1e30f;
        }
    }
    __syncthreads();

    // softmax: warp w handles query w
    {
        const int q = tid >> 5, lane = tid & 31;
        float mx = -3.4e38f;
        for (int k = lane; k < 1024; k += 32) mx = fmaxf(mx, sS[q][k]);
        #pragma unroll
        for (int o = 16; o; o >>= 1) mx = fmaxf(mx, __shfl_xor_sync(0xffffffffu, mx, o));
        float sum = 0.f;
        for (int k = lane; k < 1024; k += 32) {
            const float e = expf(sS[q][k] - mx);
            sS[q][k] = e;
            sum += e;
        }
        #pragma unroll
        for (int o = 16; o; o >>= 1) sum += __shfl_xor_sync(0xffffffffu, sum, o);
        const float inv = 1.f / sum;
        for (int k = lane; k < 1024; k += 32) sS[q][k] *= inv;
    }
    __syncthreads();

    // P@V: thread = (a = tid&63, chunk = tid>>6); V read once per block.
    const float* vp = vr + bh * 1024 * 64;
    const int a = tid & 63, chunk = tid >> 6;
    float acc[8];
    #pragma unroll
    for (int q = 0; q < 8; q++) acc[q] = 0.f;
    for (int kk = 0; kk < 256; kk++) {
        const int k = chunk * 256 + kk;
        const float v = vp[(size_t)k * 64 + a];
        #pragma unroll
        for (int q = 0; q < 8; q++) acc[q] += sS[q][k] * v;
    }
    #pragma unroll
    for (int q = 0; q < 8; q++) sRed[chunk][q][a] = acc[q];
    __syncthreads();
    for (int i = tid; i < 8 * 64; i += 256) {
        const int q = i >> 6, a2 = i & 63;
        const float o = sRed[0][q][a2] + sRed[1][q][a2] + sRed[2][q][a2] + sRed[3][q][a2];
        attn[((size_t)b * 1024 + q0 + q) * 1024 + h * 64 + a2] = o;
    }
}

// ---------------- small elementwise kernels ----------------
__global__ void build_u_k(const float* __restrict__ t1, float* __restrict__ u)
{
    const int idx = blockIdx.x * blockDim.x + threadIdx.x;
    if (idx >= 1024 * 256) return;
    const int col = idx & 255;
    const int ru  = idx >> 8;
    const int m = col >> 6, v = col & 63;
    const int k = ru & 3, bc = ru >> 2;
    u[idx] = t1[((size_t)bc * 4 + m) * 256 + k * 64 + v];
}

__global__ void assemble_k(const float* __restrict__ xin, const float* __restrict__ xdec,
                           const float* __restrict__ pe, float* __restrict__ x)
{
    const int idx = blockIdx.x * blockDim.x + threadIdx.x;
    if (idx >= 2 * 1024 * 1024) return;
    const int d  = idx & 1023;
    const int sb = idx >> 10;
    const int s_ = sb & 1023;
    const int b  = sb >> 10;
    const int c  = s_ >> 3, e = s_ & 7;
    float v;
    if (e < 4) v = xin[((size_t)(b * 512 + c * 4 + e)) * 1024 + d];
    else       v = xdec[((size_t)((b * 128 + c) * 4 + (e - 4))) * 1024 + d]
                   + pe[(e - 4) * 1024 + d];
    x[idx] = v;
}

__global__ void swiglu_k(const float* __restrict__ up, float* __restrict__ hb)
{
    const int idx = blockIdx.x * blockDim.x + threadIdx.x;
    if (idx >= 2048 * 2048) return;
    const int m = idx >> 11;
    const int j = idx & 2047;
    const float a = up[(size_t)m * 4096 + j];
    const float b = up[(size_t)m * 4096 + 2048 + j];
    hb[idx] = (a / (1.f + expf(-a))) * b;
}

__global__ void gather_k(const float* __restrict__ x, float* __restrict__ out)
{
    const int idx = blockIdx.x * blockDim.x + threadIdx.x;
    if (idx >= 256 * 4 * 1024) return;
    const int d = idx & 1023;
    const int t = idx >> 10;
    const int k = t & 3;
    const int g = t >> 2;
    const int c = g & 127;
    const int b = g >> 7;
    out[idx] = x[((size_t)(b * 1024 + c * 8 + 4 + k)) * 1024 + d];
}

// ---------------- launch ----------------
extern "C" void kernel_launch(void* const* d_in, const int* in_sizes, int n_in,
                              void* d_out, int out_size)
{
    const float* x_input     = (const float*)d_in[0];
    const int*   doc         = (const int*)d_in[1];
    const float* dec_w1      = (const float*)d_in[2];
    const float* dec_w2      = (const float*)d_in[3];
    const float* pos_emb     = (const float*)d_in[4];
    const float* Wqkv        = (const float*)d_in[5];
    const float* Wo          = (const float*)d_in[6];
    const float* Wup         = (const float*)d_in[7];
    const float* Wdown       = (const float*)d_in[8];
    const float* attn_norm_w = (const float*)d_in[9];
    const float* ffn_norm_w  = (const float*)d_in[10];

    float* S = nullptr;
    cudaGetSymbolAddress((void**)&S, g_scratch);
    float* x    = S + OFF_X;
    float* xn   = S + OFF_XN;
    float* x1   = S + OFF_X1;
    float* qkv  = S + OFF_QKV;
    float* qr   = S + OFF_QR;
    float* kt   = S + OFF_KT;
    float* vr   = S + OFF_VR;
    float* atb  = S + OFF_ATTN;
    float* up   = S + OFF_UP;
    float* hb   = S + OFF_HB;
    float* tmp1 = S + OFF_TMP1;
    float* u    = S + OFF_U;
    float* xdec = S + OFF_XDEC;

    const dim3 blk(256);

    // decoder front-end
    sgemm_k<<<dim3(256 / 128, 1024 / 128), blk>>>(x_input, dec_w1, tmp1, nullptr, 1024, 256, 1024);
    build_u_k<<<(262144 + 255) / 256, 256>>>(tmp1, u);
    sgemm_k<<<dim3(1024 / 128, 1024 / 128), blk>>>(u, dec_w2, xdec, nullptr, 1024, 1024, 256);
    assemble_k<<<(2097152 + 255) / 256, 256>>>(x_input, xdec, pos_emb, x);

    for (int li = 0; li < 4; li++) {
        rmsnorm_k<<<2048, 256>>>(x, attn_norm_w + (size_t)li * 1024, xn);
        sgemm_k<<<dim3(3072 / 128, 2048 / 128), blk>>>(
            xn, Wqkv + (size_t)li * 3072 * 1024, qkv, nullptr, 2048, 3072, 1024);
        qkrope_k<<<dim3(16, 1024, 2), 64>>>(qkv, qr, kt, vr);
        attn_k<<<dim3(128, 16, 2), 256>>>(qr, kt, vr, doc, atb);
        sgemm_k<<<dim3(1024 / 128, 2048 / 128), blk>>>(
            atb, Wo + (size_t)li * 1024 * 1024, x1, x, 2048, 1024, 1024);
        rmsnorm_k<<<2048, 256>>>(x1, ffn_norm_w + (size_t)li * 1024, xn);
        sgemm_k<<<dim3(4096 / 128, 2048 / 128), blk>>>(
            xn, Wup + (size_t)li * 4096 * 1024, up, nullptr, 2048, 4096, 1024);
        swiglu_k<<<(4194304 + 255) / 256, 256>>>(up, hb);
        sgemm_k<<<dim3(1024 / 128, 2048 / 128), blk>>>(
            hb, Wdown + (size_t)li * 1024 * 2048, x, x1, 2048, 1024, 2048);
    }

    gather_k<<<(1048576 + 255) / 256, 256>>>(x, (float*)d_out);
}

// round 4
// speedup vs baseline: 1.5346x; 1.5346x over previous
#include <cuda_runtime.h>
#include <math.h>
#include <stdint.h>

// Shapes (fixed): B=2, C=128, M=4, K=4, V=64, D=1024, H=16, A=64, L=4, HF=2048,
// E=8, S=1024, rows=2048

// ---------------- scratch (no allocations allowed) ----------------
__device__ float g_scratch[35127296];

static const size_t OFF_X    = 0;
static const size_t OFF_XN   = 2097152;
static const size_t OFF_X1   = 4194304;
static const size_t OFF_QKV  = 6291456;
static const size_t OFF_QR   = 12582912;
static const size_t OFF_KT   = 14680064;
static const size_t OFF_VR   = 16777216;
static const size_t OFF_ATTN = 18874368;
static const size_t OFF_UP   = 20971520;
static const size_t OFF_HB   = 29360128;
static const size_t OFF_TMP1 = 33554432;
static const size_t OFF_U    = 33816576;
static const size_t OFF_XDEC = 34078720;

// ---------------- TF32 tensor-core GEMM ----------------
// C[m,n] = sum_k A[m,k] * B[n,k] (+ R[m,n])
// A: MxK row-major, B: NxK row-major. M%128==0, N%128==0, K%32==0.
// Block tile 128x128x32, 256 threads (8 warps, 2x4), warp tile 64x32.
// mma.sync.aligned.m16n8k8.row.col.f32.tf32.tf32.f32

__device__ __forceinline__ uint32_t f2tf32(float x) {
    uint32_t r;
    asm("cvt.rna.tf32.f32 %0, %1;" : "=r"(r) : "f"(x));
    return r;
}

__global__ void __launch_bounds__(256, 2) gemm_tf32_k(
    const float* __restrict__ A, const float* __restrict__ Bm,
    float* __restrict__ C, const float* __restrict__ Radd,
    int M, int N, int K)
{
    // row stride 36 floats -> fragment banks (4g+t)%32, conflict-free
    __shared__ uint32_t As[128][36];
    __shared__ uint32_t Bs[128][36];

    const int tid  = threadIdx.x;
    const int lane = tid & 31, warp = tid >> 5;
    const int wm = warp >> 2;          // 0..1 -> 64-row slab
    const int wn = warp & 3;           // 0..3 -> 32-col slab
    const int g  = lane >> 2;          // 0..7
    const int t  = lane & 3;           // 0..3
    const int m0 = blockIdx.y * 128;
    const int n0 = blockIdx.x * 128;

    float acc[4][4][4];
    #pragma unroll
    for (int mf = 0; mf < 4; mf++)
        #pragma unroll
        for (int nf = 0; nf < 4; nf++)
            #pragma unroll
            for (int i = 0; i < 4; i++) acc[mf][nf][i] = 0.f;

    // global load mapping: 1024 float4 slots per tile, 4 per thread
    // slot l = tid + 256*i : row = l>>3, c4 = l&7
    const int lrow = tid >> 3;         // rows: tid part; +32 rows per i
    const int lc4  = (tid & 7) << 2;   // float col 0,4,..,28

    for (int k0 = 0; k0 < K; k0 += 32) {
        float4 av[4], bv[4];
        #pragma unroll
        for (int i = 0; i < 4; i++) {
            const int r = lrow + i * 32;
            av[i] = *(const float4*)(A  + (size_t)(m0 + r) * K + k0 + lc4);
            bv[i] = *(const float4*)(Bm + (size_t)(n0 + r) * K + k0 + lc4);
        }
        __syncthreads();
        #pragma unroll
        for (int i = 0; i < 4; i++) {
            const int r = lrow + i * 32;
            uint4 at, bt;
            at.x = f2tf32(av[i].x); at.y = f2tf32(av[i].y);
            at.z = f2tf32(av[i].z); at.w = f2tf32(av[i].w);
            bt.x = f2tf32(bv[i].x); bt.y = f2tf32(bv[i].y);
            bt.z = f2tf32(bv[i].z); bt.w = f2tf32(bv[i].w);
            *(uint4*)&As[r][lc4] = at;
            *(uint4*)&Bs[r][lc4] = bt;
        }
        __syncthreads();

        #pragma unroll
        for (int kk = 0; kk < 32; kk += 8) {
            uint32_t af[4][4];
            #pragma unroll
            for (int mf = 0; mf < 4; mf++) {
                const int r = wm * 64 + mf * 16 + g;
                af[mf][0] = As[r][kk + t];
                af[mf][1] = As[r + 8][kk + t];
                af[mf][2] = As[r][kk + t + 4];
                af[mf][3] = As[r + 8][kk + t + 4];
            }
            uint32_t bf[4][2];
            #pragma unroll
            for (int nf = 0; nf < 4; nf++) {
                const int n = wn * 32 + nf * 8 + g;
                bf[nf][0] = Bs[n][kk + t];
                bf[nf][1] = Bs[n][kk + t + 4];
            }
            #pragma unroll
            for (int mf = 0; mf < 4; mf++)
                #pragma unroll
                for (int nf = 0; nf < 4; nf++) {
                    asm volatile(
                        "mma.sync.aligned.m16n8k8.row.col.f32.tf32.tf32.f32 "
                        "{%0,%1,%2,%3}, {%4,%5,%6,%7}, {%8,%9}, {%0,%1,%2,%3};\n"
                        : "+f"(acc[mf][nf][0]), "+f"(acc[mf][nf][1]),
                          "+f"(acc[mf][nf][2]), "+f"(acc[mf][nf][3])
                        : "r"(af[mf][0]), "r"(af[mf][1]), "r"(af[mf][2]), "r"(af[mf][3]),
                          "r"(bf[nf][0]), "r"(bf[nf][1]));
                }
        }
    }

    // epilogue
    #pragma unroll
    for (int mf = 0; mf < 4; mf++) {
        const int r0 = m0 + wm * 64 + mf * 16 + g;
        #pragma unroll
        for (int nf = 0; nf < 4; nf++) {
            const int col = n0 + wn * 32 + nf * 8 + 2 * t;
            float2 v0 = make_float2(acc[mf][nf][0], acc[mf][nf][1]);
            float2 v1 = make_float2(acc[mf][nf][2], acc[mf][nf][3]);
            if (Radd) {
                float2 r0v = *(const float2*)&Radd[(size_t)r0 * N + col];
                float2 r1v = *(const float2*)&Radd[(size_t)(r0 + 8) * N + col];
                v0.x += r0v.x; v0.y += r0v.y;
                v1.x += r1v.x; v1.y += r1v.y;
            }
            *(float2*)&C[(size_t)r0 * N + col]       = v0;
            *(float2*)&C[(size_t)(r0 + 8) * N + col] = v1;
        }
    }
}

// ---------------- RMSNorm (one block per row, D=1024) ----------------
__global__ void __launch_bounds__(256) rmsnorm_k(
    const float* __restrict__ x, const float* __restrict__ w, float* __restrict__ y)
{
    const int row = blockIdx.x;
    const float* xr = x + (size_t)row * 1024;
    float s = 0.f;
    for (int i = threadIdx.x; i < 1024; i += 256) { float v = xr[i]; s += v * v; }
    #pragma unroll
    for (int o = 16; o; o >>= 1) s += __shfl_xor_sync(0xffffffffu, s, o);
    __shared__ float red[8];
    const int warp = threadIdx.x >> 5, lane = threadIdx.x & 31;
    if (lane == 0) red[warp] = s;
    __syncthreads();
    float tot = 0.f;
    #pragma unroll
    for (int i = 0; i < 8; i++) tot += red[i];
    const float inv = rsqrtf(tot * (1.f / 1024.f) + 1e-5f);
    float* yr = y + (size_t)row * 1024;
    for (int i = threadIdx.x; i < 1024; i += 256) yr[i] = xr[i] * inv * w[i];
}

// ---------------- l2norm + RoPE + layout shuffle ----------------
__global__ void __launch_bounds__(64) qkrope_k(
    const float* __restrict__ qkv, float* __restrict__ qr,
    float* __restrict__ kt, float* __restrict__ vr)
{
    const int h = blockIdx.x, s = blockIdx.y, b = blockIdx.z;
    const int a = threadIdx.x;
    const float* base = qkv + ((size_t)b * 1024 + s) * 3072 + h * 64 + a;
    float q = base[0];
    float k = base[1024];
    float v = base[2048];

    float sq = q * q, sk = k * k;
    #pragma unroll
    for (int o = 16; o; o >>= 1) {
        sq += __shfl_xor_sync(0xffffffffu, sq, o);
        sk += __shfl_xor_sync(0xffffffffu, sk, o);
    }
    __shared__ float red[4];
    __shared__ float sqv[64], skv[64];
    const int warp = a >> 5;
    if ((a & 31) == 0) { red[warp * 2] = sq; red[warp * 2 + 1] = sk; }
    __syncthreads();
    const float nq = sqrtf(red[0] + red[2]);
    const float nk = sqrtf(red[1] + red[3]);
    q = q / fmaxf(nq, 1e-5f);
    k = k / fmaxf(nk, 1e-5f);
    sqv[a] = q; skv[a] = k;
    __syncthreads();

    const int i = a & 31;
    const double ang = (double)s * pow(10000.0, -(double)i / 32.0);
    const float cz = (float)cos(ang), sz = (float)sin(ang);
    const float qp = sqv[a ^ 32], kp = skv[a ^ 32];
    const float qo = (a < 32) ? (q * cz + qp * sz) : (q * cz - qp * sz);
    const float ko = (a < 32) ? (k * cz + kp * sz) : (k * cz - kp * sz);

    const size_t bh = (size_t)b * 16 + h;
    qr[(bh * 1024 + s) * 64 + a] = qo;
    kt[(bh * 64 + a) * 1024 + s] = ko;       // K transposed: (b,h,a,s)
    vr[(bh * 1024 + s) * 64 + a] = v;
}

// ---------------- attention: block per (b,h, 8-query tile) ----------------
__global__ void __launch_bounds__(256) attn_k(
    const float* __restrict__ qr, const float* __restrict__ kt,
    const float* __restrict__ vr, const int* __restrict__ doc,
    float* __restrict__ attn)
{
    const int qt = blockIdx.x, h = blockIdx.y, b = blockIdx.z;
    const int q0 = qt * 8;
    __shared__ float sQ[8][64];
    __shared__ float sS[8][1024];
    __shared__ float sRed[4][8][64];
    __shared__ int sDoc[128];
    const int tid = threadIdx.x;
    if (tid < 128) sDoc[tid] = doc[b * 128 + tid];
    const size_t bh = (size_t)b * 16 + h;
    for (int i = tid; i < 8 * 64; i += 256) {
        int q = i >> 6, a = i & 63;
        sQ[q][a] = qr[(bh * 1024 + q0 + q) * 64 + a];
    }
    __syncthreads();

    const float* ktp = kt + bh * 64 * 1024;
    float s[8][4];
    #pragma unroll
    for (int q = 0; q < 8; q++)
        #pragma unroll
        for (int j = 0; j < 4; j++) s[q][j] = 0.f;
    for (int a = 0; a < 64; a++) {
        float kv[4];
        #pragma unroll
        for (int j = 0; j < 4; j++) kv[j] = ktp[a * 1024 + tid + j * 256];
        #pragma unroll
        for (int q = 0; q < 8; q++) {
            const float qa = sQ[q][a];
            #pragma unroll
            for (int j = 0; j < 4; j++) s[q][j] += qa * kv[j];
        }
    }

    #pragma unroll
    for (int q = 0; q < 8; q++) {
        const int blkq = (q0 + q) >> 3;
        const int dq = sDoc[blkq];
        #pragma unroll
        for (int j = 0; j < 4; j++) {
            const int k = tid + j * 256;
            const int blkk = k >> 3;
            const bool ok = (blkq == blkk) ||
                            ((blkq >= blkk) && ((k & 7) < 4) && (dq == sDoc[blkk]));
            sS[q][k] = ok ? s[q][j] * 0.125f : -1e30f;
        }
    }
    __syncthreads();

    {
        const int q = tid >> 5, lane = tid & 31;
        float mx = -3.4e38f;
        for (int k = lane; k < 1024; k += 32) mx = fmaxf(mx, sS[q][k]);
        #pragma unroll
        for (int o = 16; o; o >>= 1) mx = fmaxf(mx, __shfl_xor_sync(0xffffffffu, mx, o));
        float sum = 0.f;
        for (int k = lane; k < 1024; k += 32) {
            const float e = expf(sS[q][k] - mx);
            sS[q][k] = e;
            sum += e;
        }
        #pragma unroll
        for (int o = 16; o; o >>= 1) sum += __shfl_xor_sync(0xffffffffu, sum, o);
        const float inv = 1.f / sum;
        for (int k = lane; k < 1024; k += 32) sS[q][k] *= inv;
    }
    __syncthreads();

    const float* vp = vr + bh * 1024 * 64;
    const int a = tid & 63, chunk = tid >> 6;
    float acc[8];
    #pragma unroll
    for (int q = 0; q < 8; q++) acc[q] = 0.f;
    for (int kk = 0; kk < 256; kk++) {
        const int k = chunk * 256 + kk;
        const float v = vp[(size_t)k * 64 + a];
        #pragma unroll
        for (int q = 0; q < 8; q++) acc[q] += sS[q][k] * v;
    }
    #pragma unroll
    for (int q = 0; q < 8; q++) sRed[chunk][q][a] = acc[q];
    __syncthreads();
    for (int i = tid; i < 8 * 64; i += 256) {
        const int q = i >> 6, a2 = i & 63;
        const float o = sRed[0][q][a2] + sRed[1][q][a2] + sRed[2][q][a2] + sRed[3][q][a2];
        attn[((size_t)b * 1024 + q0 + q) * 1024 + h * 64 + a2] = o;
    }
}

// ---------------- small elementwise kernels ----------------
__global__ void build_u_k(const float* __restrict__ t1, float* __restrict__ u)
{
    const int idx = blockIdx.x * blockDim.x + threadIdx.x;
    if (idx >= 1024 * 256) return;
    const int col = idx & 255;
    const int ru  = idx >> 8;
    const int m = col >> 6, v = col & 63;
    const int k = ru & 3, bc = ru >> 2;
    u[idx] = t1[((size_t)bc * 4 + m) * 256 + k * 64 + v];
}

__global__ void assemble_k(const float* __restrict__ xin, const float* __restrict__ xdec,
                           const float* __restrict__ pe, float* __restrict__ x)
{
    const int idx = blockIdx.x * blockDim.x + threadIdx.x;
    if (idx >= 2 * 1024 * 1024) return;
    const int d  = idx & 1023;
    const int sb = idx >> 10;
    const int s_ = sb & 1023;
    const int b  = sb >> 10;
    const int c  = s_ >> 3, e = s_ & 7;
    float v;
    if (e < 4) v = xin[((size_t)(b * 512 + c * 4 + e)) * 1024 + d];
    else       v = xdec[((size_t)((b * 128 + c) * 4 + (e - 4))) * 1024 + d]
                   + pe[(e - 4) * 1024 + d];
    x[idx] = v;
}

__global__ void swiglu_k(const float* __restrict__ up, float* __restrict__ hb)
{
    const int idx = blockIdx.x * blockDim.x + threadIdx.x;
    if (idx >= 2048 * 2048) return;
    const int m = idx >> 11;
    const int j = idx & 2047;
    const float a = up[(size_t)m * 4096 + j];
    const float b = up[(size_t)m * 4096 + 2048 + j];
    hb[idx] = (a / (1.f + expf(-a))) * b;
}

__global__ void gather_k(const float* __restrict__ x, float* __restrict__ out)
{
    const int idx = blockIdx.x * blockDim.x + threadIdx.x;
    if (idx >= 256 * 4 * 1024) return;
    const int d = idx & 1023;
    const int t = idx >> 10;
    const int k = t & 3;
    const int g = t >> 2;
    const int c = g & 127;
    const int b = g >> 7;
    out[idx] = x[((size_t)(b * 1024 + c * 8 + 4 + k)) * 1024 + d];
}

// ---------------- launch ----------------
extern "C" void kernel_launch(void* const* d_in, const int* in_sizes, int n_in,
                              void* d_out, int out_size)
{
    const float* x_input     = (const float*)d_in[0];
    const int*   doc         = (const int*)d_in[1];
    const float* dec_w1      = (const float*)d_in[2];
    const float* dec_w2      = (const float*)d_in[3];
    const float* pos_emb     = (const float*)d_in[4];
    const float* Wqkv        = (const float*)d_in[5];
    const float* Wo          = (const float*)d_in[6];
    const float* Wup         = (const float*)d_in[7];
    const float* Wdown       = (const float*)d_in[8];
    const float* attn_norm_w = (const float*)d_in[9];
    const float* ffn_norm_w  = (const float*)d_in[10];

    float* S = nullptr;
    cudaGetSymbolAddress((void**)&S, g_scratch);
    float* x    = S + OFF_X;
    float* xn   = S + OFF_XN;
    float* x1   = S + OFF_X1;
    float* qkv  = S + OFF_QKV;
    float* qr   = S + OFF_QR;
    float* kt   = S + OFF_KT;
    float* vr   = S + OFF_VR;
    float* atb  = S + OFF_ATTN;
    float* up   = S + OFF_UP;
    float* hb   = S + OFF_HB;
    float* tmp1 = S + OFF_TMP1;
    float* u    = S + OFF_U;
    float* xdec = S + OFF_XDEC;

    const dim3 blk(256);

    // decoder front-end
    gemm_tf32_k<<<dim3(256 / 128, 1024 / 128), blk>>>(x_input, dec_w1, tmp1, nullptr, 1024, 256, 1024);
    build_u_k<<<(262144 + 255) / 256, 256>>>(tmp1, u);
    gemm_tf32_k<<<dim3(1024 / 128, 1024 / 128), blk>>>(u, dec_w2, xdec, nullptr, 1024, 1024, 256);
    assemble_k<<<(2097152 + 255) / 256, 256>>>(x_input, xdec, pos_emb, x);

    for (int li = 0; li < 4; li++) {
        rmsnorm_k<<<2048, 256>>>(x, attn_norm_w + (size_t)li * 1024, xn);
        gemm_tf32_k<<<dim3(3072 / 128, 2048 / 128), blk>>>(
            xn, Wqkv + (size_t)li * 3072 * 1024, qkv, nullptr, 2048, 3072, 1024);
        qkrope_k<<<dim3(16, 1024, 2), 64>>>(qkv, qr, kt, vr);
        attn_k<<<dim3(128, 16, 2), 256>>>(qr, kt, vr, doc, atb);
        gemm_tf32_k<<<dim3(1024 / 128, 2048 / 128), blk>>>(
            atb, Wo + (size_t)li * 1024 * 1024, x1, x, 2048, 1024, 1024);
        rmsnorm_k<<<2048, 256>>>(x1, ffn_norm_w + (size_t)li * 1024, xn);
        gemm_tf32_k<<<dim3(4096 / 128, 2048 / 128), blk>>>(
            xn, Wup + (size_t)li * 4096 * 1024, up, nullptr, 2048, 4096, 1024);
        swiglu_k<<<(4194304 + 255) / 256, 256>>>(up, hb);
        gemm_tf32_k<<<dim3(1024 / 128, 2048 / 128), blk>>>(
            hb, Wdown + (size_t)li * 1024 * 2048, x, x1, 2048, 1024, 2048);
    }

    gather_k<<<(1048576 + 255) / 256, 256>>>(x, (float*)d_out);
}

// round 6
// speedup vs baseline: 2.4053x; 1.5673x over previous
#include <cuda_runtime.h>
#include <math.h>
#include <stdint.h>

// Shapes (fixed): B=2, C=128, M=4, K=4, V=64, D=1024, H=16, A=64, L=4, HF=2048,
// E=8, S=1024, rows=2048

// ---------------- scratch (no allocations allowed) ----------------
__device__ float g_scratch[81854464];

static const size_t OFF_X    = 0;
static const size_t OFF_XN   = 2097152;
static const size_t OFF_X1   = 4194304;
static const size_t OFF_QKV  = 6291456;
static const size_t OFF_QR   = 12582912;
static const size_t OFF_KT   = 14680064;
static const size_t OFF_VR   = 16777216;
static const size_t OFF_ATTN = 18874368;
static const size_t OFF_UP   = 20971520;
static const size_t OFF_HB   = 29360128;
static const size_t OFF_TMP1 = 33554432;
static const size_t OFF_U    = 33816576;
static const size_t OFF_XDEC = 34078720;
// packed tf32 buffers
static const size_t OFF_APACK = 35127296;   // 4194304 (max A = 2048x2048)
static const size_t OFF_W1P   = 39321600;   // 262144
static const size_t OFF_W2P   = 39583744;   // 262144
static const size_t OFF_QKVP  = 39845888;   // 4 * 3145728
static const size_t OFF_WOP   = 52428800;   // 4 * 1048576
static const size_t OFF_UPP   = 56623104;   // 4 * 4194304
static const size_t OFF_DWNP  = 73400320;   // 4 * 2097152
static const size_t OFF_COS   = 81788928;   // 32768
static const size_t OFF_SIN   = 81821696;   // 32768

__device__ __forceinline__ uint32_t f2tf32(float x) {
    uint32_t r;
    asm("cvt.rna.tf32.f32 %0, %1;" : "=r"(r) : "f"(x));
    return r;
}

// ---------------- pack: row-major fp32 [R][K] -> tf32 fragment-packed ----------------
// Layout: for each (rblk=row/128, kt16=k/16): 512 uint4 words.
// word slot = (kb*8 + mgi)*32 + g*4 + t   (kb=k8-within-16, mgi=16-row group,
// g=row-within-8, t=col-within-4) ; word = {X[r][c], X[r+8][c], X[r][c+4], X[r+8][c+4]}
// with r = rblk*128+mgi*16+g, c = kt16*16+kb*8+t. Stored UNswizzled (natural t order);
// the XOR swizzle is applied on the cp.async destination inside the GEMM.
__global__ void __launch_bounds__(256) pack_tf32_k(
    const float* __restrict__ X, float* __restrict__ P, int K)
{
    const int tid  = threadIdx.x;
    const int rblk = blockIdx.y, ktb = blockIdx.x;   // ktb = 32-col block
    const int g    = tid & 7;
    const int u32i = tid >> 3;        // 0..31
    const int kbb  = u32i >> 3;       // 0..3 (8-col group within 32)
    const int mgi  = u32i & 7;        // 16-row group
    const int r0   = rblk * 128 + mgi * 16 + g;
    const int c0   = ktb * 32 + kbb * 8;

    const float4 a0  = *(const float4*)(X + (size_t)r0 * K + c0);
    const float4 a0h = *(const float4*)(X + (size_t)r0 * K + c0 + 4);
    const float4 a1  = *(const float4*)(X + (size_t)(r0 + 8) * K + c0);
    const float4 a1h = *(const float4*)(X + (size_t)(r0 + 8) * K + c0 + 4);

    const int kt16 = ktb * 2 + (kbb >> 1);
    const int kb   = kbb & 1;
    uint4* dst = (uint4*)P + ((size_t)rblk * (K >> 4) + kt16) * 512
               + (kb * 8 + mgi) * 32 + g * 4;
    uint4 w;
    w.x = f2tf32(a0.x); w.y = f2tf32(a1.x); w.z = f2tf32(a0h.x); w.w = f2tf32(a1h.x); dst[0] = w;
    w.x = f2tf32(a0.y); w.y = f2tf32(a1.y); w.z = f2tf32(a0h.y); w.w = f2tf32(a1h.y); dst[1] = w;
    w.x = f2tf32(a0.z); w.y = f2tf32(a1.z); w.z = f2tf32(a0h.z); w.w = f2tf32(a1h.z); dst[2] = w;
    w.x = f2tf32(a0.w); w.y = f2tf32(a1.w); w.z = f2tf32(a0h.w); w.w = f2tf32(a1h.w); dst[3] = w;
}

// ---------------- TF32 tensor-core GEMM on packed operands ----------------
// C[m,n] = sum_k A[m,k]*B[n,k] (+R[m,n]). Ap/Bp fragment-packed (see pack_tf32_k).
// 128x128 block tile, 16-K stages, 3-stage cp.async ring, 256 threads (8 warps 2x4).
__global__ void __launch_bounds__(256, 2) gemm_tc_k(
    const float* __restrict__ Ap, const float* __restrict__ Bp,
    float* __restrict__ C, const float* __restrict__ Radd,
    int M, int N, int K)
{
    __shared__ uint4 smA[3][512];
    __shared__ uint4 smB[3][512];

    const int tid = threadIdx.x, lane = tid & 31, warp = tid >> 5;
    const int wm = warp >> 2, wn = warp & 3;
    const int g = lane >> 2, t = lane & 3;
    const int slotoff = g * 4 + (t ^ ((g >> 1) & 3));
    const int NT = K >> 4;

    const uint4* gA = (const uint4*)Ap + (size_t)blockIdx.y * NT * 512;
    const uint4* gB = (const uint4*)Bp + (size_t)blockIdx.x * NT * 512;

    // copier: threads 0..127 -> A quads, 128..255 -> B quads
    const int  cq  = tid & 127;
    const int  cs  = (cq >> 1) & 3;          // swizzle key = (g>>1)&3 of this quad
    const bool isB = tid >= 128;
    const uint4* gsrc = (isB ? gB : gA) + cq * 4;
    unsigned sAu = (unsigned)__cvta_generic_to_shared(&smA[0][0]);
    unsigned sBu = (unsigned)__cvta_generic_to_shared(&smB[0][0]);
    const unsigned dbase = (isB ? sBu : sAu) + cq * 64;

    float acc[4][4][4];
    #pragma unroll
    for (int mf = 0; mf < 4; mf++)
        #pragma unroll
        for (int nf = 0; nf < 4; nf++)
            #pragma unroll
            for (int i = 0; i < 4; i++) acc[mf][nf][i] = 0.f;

    #define ISSUE(KT, ST) do {                                              \
        const uint4* _s = gsrc + (size_t)(KT) * 512;                        \
        unsigned _d = dbase + (ST) * 8192;                                  \
        asm volatile("cp.async.cg.shared.global [%0], [%1], 16;" ::         \
            "r"(_d + ((0 ^ cs) << 4)), "l"(_s + 0));                        \
        asm volatile("cp.async.cg.shared.global [%0], [%1], 16;" ::         \
            "r"(_d + ((1 ^ cs) << 4)), "l"(_s + 1));                        \
        asm volatile("cp.async.cg.shared.global [%0], [%1], 16;" ::         \
            "r"(_d + ((2 ^ cs) << 4)), "l"(_s + 2));                        \
        asm volatile("cp.async.cg.shared.global [%0], [%1], 16;" ::         \
            "r"(_d + ((3 ^ cs) << 4)), "l"(_s + 3));                        \
    } while (0)

    ISSUE(0, 0);
    asm volatile("cp.async.commit_group;");
    ISSUE(1, 1);
    asm volatile("cp.async.commit_group;");

    int st = 0;
    for (int kt = 0; kt < NT; kt++) {
        asm volatile("cp.async.wait_group 1;");
        __syncthreads();
        const uint4* sa = smA[st];
        const uint4* sb = smB[st];
        #pragma unroll
        for (int kb = 0; kb < 2; kb++) {
            uint4 wa[4];
            #pragma unroll
            for (int mf = 0; mf < 4; mf++)
                wa[mf] = sa[(kb * 8 + wm * 4 + mf) * 32 + slotoff];
            const uint4 wb0 = sb[(kb * 8 + wn * 2 + 0) * 32 + slotoff];
            const uint4 wb1 = sb[(kb * 8 + wn * 2 + 1) * 32 + slotoff];
            const uint32_t bf[4][2] = {
                {wb0.x, wb0.z}, {wb0.y, wb0.w}, {wb1.x, wb1.z}, {wb1.y, wb1.w}};
            #pragma unroll
            for (int mf = 0; mf < 4; mf++)
                #pragma unroll
                for (int nf = 0; nf < 4; nf++) {
                    asm volatile(
                        "mma.sync.aligned.m16n8k8.row.col.f32.tf32.tf32.f32 "
                        "{%0,%1,%2,%3}, {%4,%5,%6,%7}, {%8,%9}, {%0,%1,%2,%3};\n"
                        : "+f"(acc[mf][nf][0]), "+f"(acc[mf][nf][1]),
                          "+f"(acc[mf][nf][2]), "+f"(acc[mf][nf][3])
                        : "r"(wa[mf].x), "r"(wa[mf].y), "r"(wa[mf].z), "r"(wa[mf].w),
                          "r"(bf[nf][0]), "r"(bf[nf][1]));
                }
        }
        const int ktn = kt + 2;
        int stn = st + 2; if (stn >= 3) stn -= 3;
        if (ktn < NT) ISSUE(ktn, stn);
        asm volatile("cp.async.commit_group;");
        st++; if (st == 3) st = 0;
    }
    #undef ISSUE

    const int m0 = blockIdx.y * 128;
    const int n0 = blockIdx.x * 128;
    #pragma unroll
    for (int mf = 0; mf < 4; mf++) {
        const int r0 = m0 + wm * 64 + mf * 16 + g;
        #pragma unroll
        for (int nf = 0; nf < 4; nf++) {
            const int col = n0 + wn * 32 + nf * 8 + 2 * t;
            float2 v0 = make_float2(acc[mf][nf][0], acc[mf][nf][1]);
            float2 v1 = make_float2(acc[mf][nf][2], acc[mf][nf][3]);
            if (Radd) {
                float2 r0v = *(const float2*)&Radd[(size_t)r0 * N + col];
                float2 r1v = *(const float2*)&Radd[(size_t)(r0 + 8) * N + col];
                v0.x += r0v.x; v0.y += r0v.y;
                v1.x += r1v.x; v1.y += r1v.y;
            }
            *(float2*)&C[(size_t)r0 * N + col]       = v0;
            *(float2*)&C[(size_t)(r0 + 8) * N + col] = v1;
        }
    }
}

// ---------------- RoPE table (once per launch) ----------------
__global__ void rope_table_k(float* __restrict__ ct, float* __restrict__ st_)
{
    const int idx = blockIdx.x * 256 + threadIdx.x;
    if (idx >= 32768) return;
    const int s = idx >> 5, i = idx & 31;
    const double ang = (double)s * pow(10000.0, -(double)i / 32.0);
    ct[idx]  = (float)cos(ang);
    st_[idx] = (float)sin(ang);
}

// ---------------- RMSNorm (one block per row, D=1024) ----------------
__global__ void __launch_bounds__(256) rmsnorm_k(
    const float* __restrict__ x, const float* __restrict__ w, float* __restrict__ y)
{
    const int row = blockIdx.x;
    const float* xr = x + (size_t)row * 1024;
    float s = 0.f;
    for (int i = threadIdx.x; i < 1024; i += 256) { float v = xr[i]; s += v * v; }
    #pragma unroll
    for (int o = 16; o; o >>= 1) s += __shfl_xor_sync(0xffffffffu, s, o);
    __shared__ float red[8];
    const int warp = threadIdx.x >> 5, lane = threadIdx.x & 31;
    if (lane == 0) red[warp] = s;
    __syncthreads();
    float tot = 0.f;
    #pragma unroll
    for (int i = 0; i < 8; i++) tot += red[i];
    const float inv = rsqrtf(tot * (1.f / 1024.f) + 1e-5f);
    float* yr = y + (size_t)row * 1024;
    for (int i = threadIdx.x; i < 1024; i += 256) yr[i] = xr[i] * inv * w[i];
}

// ---------------- l2norm + RoPE + layout shuffle ----------------
__global__ void __launch_bounds__(64) qkrope_k(
    const float* __restrict__ qkv, const float* __restrict__ cosT,
    const float* __restrict__ sinT, float* __restrict__ qr,
    float* __restrict__ kt, float* __restrict__ vr)
{
    const int h = blockIdx.x, s = blockIdx.y, b = blockIdx.z;
    const int a = threadIdx.x;
    const float* base = qkv + ((size_t)b * 1024 + s) * 3072 + h * 64 + a;
    float q = base[0];
    float k = base[1024];
    float v = base[2048];

    float sq = q * q, sk = k * k;
    #pragma unroll
    for (int o = 16; o; o >>= 1) {
        sq += __shfl_xor_sync(0xffffffffu, sq, o);
        sk += __shfl_xor_sync(0xffffffffu, sk, o);
    }
    __shared__ float red[4];
    __shared__ float sqv[64], skv[64];
    const int warp = a >> 5;
    if ((a & 31) == 0) { red[warp * 2] = sq; red[warp * 2 + 1] = sk; }
    __syncthreads();
    const float nq = sqrtf(red[0] + red[2]);
    const float nk = sqrtf(red[1] + red[3]);
    q = q / fmaxf(nq, 1e-5f);
    k = k / fmaxf(nk, 1e-5f);
    sqv[a] = q; skv[a] = k;
    __syncthreads();

    const int i = a & 31;
    const float cz = cosT[s * 32 + i];
    const float sz = sinT[s * 32 + i];
    const float qp = sqv[a ^ 32], kp = skv[a ^ 32];
    const float qo = (a < 32) ? (q * cz + qp * sz) : (q * cz - qp * sz);
    const float ko = (a < 32) ? (k * cz + kp * sz) : (k * cz - kp * sz);

    const size_t bh = (size_t)b * 16 + h;
    qr[(bh * 1024 + s) * 64 + a] = qo;
    kt[(bh * 64 + a) * 1024 + s] = ko;       // K transposed: (b,h,a,s)
    vr[(bh * 1024 + s) * 64 + a] = v;
}

// ---------------- attention: block per (b,h, 8-query tile) ----------------
__global__ void __launch_bounds__(256) attn_k(
    const float* __restrict__ qr, const float* __restrict__ kt,
    const float* __restrict__ vr, const int* __restrict__ doc,
    float* __restrict__ attn)
{
    const int qt = blockIdx.x, h = blockIdx.y, b = blockIdx.z;
    const int q0 = qt * 8;
    __shared__ float sQ[8][64];
    __shared__ float sS[8][1024];
    __shared__ float sRed[4][8][64];
    __shared__ int sDoc[128];
    const int tid = threadIdx.x;
    if (tid < 128) sDoc[tid] = doc[b * 128 + tid];
    const size_t bh = (size_t)b * 16 + h;
    for (int i = tid; i < 8 * 64; i += 256) {
        int q = i >> 6, a = i & 63;
        sQ[q][a] = qr[(bh * 1024 + q0 + q) * 64 + a];
    }
    __syncthreads();

    const float* ktp = kt + bh * 64 * 1024;
    float s[8][4];
    #pragma unroll
    for (int q = 0; q < 8; q++)
        #pragma unroll
        for (int j = 0; j < 4; j++) s[q][j] = 0.f;
    for (int a = 0; a < 64; a++) {
        float kv[4];
        #pragma unroll
        for (int j = 0; j < 4; j++) kv[j] = ktp[a * 1024 + tid + j * 256];
        #pragma unroll
        for (int q = 0; q < 8; q++) {
            const float qa = sQ[q][a];
            #pragma unroll
            for (int j = 0; j < 4; j++) s[q][j] += qa * kv[j];
        }
    }

    #pragma unroll
    for (int q = 0; q < 8; q++) {
        const int blkq = (q0 + q) >> 3;
        const int dq = sDoc[blkq];
        #pragma unroll
        for (int j = 0; j < 4; j++) {
            const int k = tid + j * 256;
            const int blkk = k >> 3;
            const bool ok = (blkq == blkk) ||
                            ((blkq >= blkk) && ((k & 7) < 4) && (dq == sDoc[blkk]));
            sS[q][k] = ok ? s[q][j] * 0.125f : -1e30f;
        }
    }
    __syncthreads();

    {
        const int q = tid >> 5, lane = tid & 31;
        float mx = -3.4e38f;
        for (int k = lane; k < 1024; k += 32) mx = fmaxf(mx, sS[q][k]);
        #pragma unroll
        for (int o = 16; o; o >>= 1) mx = fmaxf(mx, __shfl_xor_sync(0xffffffffu, mx, o));
        float sum = 0.f;
        for (int k = lane; k < 1024; k += 32) {
            const float e = expf(sS[q][k] - mx);
            sS[q][k] = e;
            sum += e;
        }
        #pragma unroll
        for (int o = 16; o; o >>= 1) sum += __shfl_xor_sync(0xffffffffu, sum, o);
        const float inv = 1.f / sum;
        for (int k = lane; k < 1024; k += 32) sS[q][k] *= inv;
    }
    __syncthreads();

    const float* vp = vr + bh * 1024 * 64;
    const int a = tid & 63, chunk = tid >> 6;
    float acc[8];
    #pragma unroll
    for (int q = 0; q < 8; q++) acc[q] = 0.f;
    for (int kk = 0; kk < 256; kk++) {
        const int k = chunk * 256 + kk;
        const float v = vp[(size_t)k * 64 + a];
        #pragma unroll
        for (int q = 0; q < 8; q++) acc[q] += sS[q][k] * v;
    }
    #pragma unroll
    for (int q = 0; q < 8; q++) sRed[chunk][q][a] = acc[q];
    __syncthreads();
    for (int i = tid; i < 8 * 64; i += 256) {
        const int q = i >> 6, a2 = i & 63;
        const float o = sRed[0][q][a2] + sRed[1][q][a2] + sRed[2][q][a2] + sRed[3][q][a2];
        attn[((size_t)b * 1024 + q0 + q) * 1024 + h * 64 + a2] = o;
    }
}

// ---------------- small elementwise kernels ----------------
__global__ void build_u_k(const float* __restrict__ t1, float* __restrict__ u)
{
    const int idx = blockIdx.x * blockDim.x + threadIdx.x;
    if (idx >= 1024 * 256) return;
    const int col = idx & 255;
    const int ru  = idx >> 8;
    const int m = col >> 6, v = col & 63;
    const int k = ru & 3, bc = ru >> 2;
    u[idx] = t1[((size_t)bc * 4 + m) * 256 + k * 64 + v];
}

__global__ void assemble_k(const float* __restrict__ xin, const float* __restrict__ xdec,
                           const float* __restrict__ pe, float* __restrict__ x)
{
    const int idx = blockIdx.x * blockDim.x + threadIdx.x;
    if (idx >= 2 * 1024 * 1024) return;
    const int d  = idx & 1023;
    const int sb = idx >> 10;
    const int s_ = sb & 1023;
    const int b  = sb >> 10;
    const int c  = s_ >> 3, e = s_ & 7;
    float v;
    if (e < 4) v = xin[((size_t)(b * 512 + c * 4 + e)) * 1024 + d];
    else       v = xdec[((size_t)((b * 128 + c) * 4 + (e - 4))) * 1024 + d]
                   + pe[(e - 4) * 1024 + d];
    x[idx] = v;
}

__global__ void swiglu_k(const float* __restrict__ up, float* __restrict__ hb)
{
    const int idx = blockIdx.x * blockDim.x + threadIdx.x;
    if (idx >= 2048 * 2048) return;
    const int m = idx >> 11;
    const int j = idx & 2047;
    const float a = up[(size_t)m * 4096 + j];
    const float b = up[(size_t)m * 4096 + 2048 + j];
    hb[idx] = (a / (1.f + expf(-a))) * b;
}

__global__ void gather_k(const float* __restrict__ x, float* __restrict__ out)
{
    const int idx = blockIdx.x * blockDim.x + threadIdx.x;
    if (idx >= 256 * 4 * 1024) return;
    const int d = idx & 1023;
    const int t = idx >> 10;
    const int k = t & 3;
    const int g = t >> 2;
    const int c = g & 127;
    const int b = g >> 7;
    out[idx] = x[((size_t)(b * 1024 + c * 8 + 4 + k)) * 1024 + d];
}

// ---------------- launch ----------------
extern "C" void kernel_launch(void* const* d_in, const int* in_sizes, int n_in,
                              void* d_out, int out_size)
{
    const float* x_input     = (const float*)d_in[0];
    const int*   doc         = (const int*)d_in[1];
    const float* dec_w1      = (const float*)d_in[2];
    const float* dec_w2      = (const float*)d_in[3];
    const float* pos_emb     = (const float*)d_in[4];
    const float* Wqkv        = (const float*)d_in[5];
    const float* Wo          = (const float*)d_in[6];
    const float* Wup         = (const float*)d_in[7];
    const float* Wdown       = (const float*)d_in[8];
    const float* attn_norm_w = (const float*)d_in[9];
    const float* ffn_norm_w  = (const float*)d_in[10];

    float* S = nullptr;
    cudaGetSymbolAddress((void**)&S, g_scratch);
    float* x    = S + OFF_X;
    float* xn   = S + OFF_XN;
    float* x1   = S + OFF_X1;
    float* qkv  = S + OFF_QKV;
    float* qr   = S + OFF_QR;
    float* ktb_ = S + OFF_KT;
    float* vr   = S + OFF_VR;
    float* atb  = S + OFF_ATTN;
    float* up   = S + OFF_UP;
    float* hb   = S + OFF_HB;
    float* tmp1 = S + OFF_TMP1;
    float* u    = S + OFF_U;
    float* xdec = S + OFF_XDEC;
    float* apk  = S + OFF_APACK;
    float* w1p  = S + OFF_W1P;
    float* w2p  = S + OFF_W2P;
    float* qkvp = S + OFF_QKVP;
    float* wop  = S + OFF_WOP;
    float* upp  = S + OFF_UPP;
    float* dwnp = S + OFF_DWNP;
    float* cosT = S + OFF_COS;
    float* sinT = S + OFF_SIN;

    const dim3 blk(256);

    // one-time per launch: rope table + weight packs
    rope_table_k<<<128, 256>>>(cosT, sinT);
    pack_tf32_k<<<dim3(32, 2),  blk>>>(dec_w1, w1p, 1024);
    pack_tf32_k<<<dim3(8, 8),   blk>>>(dec_w2, w2p, 256);
    for (int li = 0; li < 4; li++) {
        pack_tf32_k<<<dim3(32, 24), blk>>>(Wqkv  + (size_t)li * 3145728, qkvp + (size_t)li * 3145728, 1024);
        pack_tf32_k<<<dim3(32, 8),  blk>>>(Wo    + (size_t)li * 1048576, wop  + (size_t)li * 1048576, 1024);
        pack_tf32_k<<<dim3(32, 32), blk>>>(Wup   + (size_t)li * 4194304, upp  + (size_t)li * 4194304, 1024);
        pack_tf32_k<<<dim3(64, 8),  blk>>>(Wdown + (size_t)li * 2097152, dwnp + (size_t)li * 2097152, 2048);
    }

    // decoder front-end
    pack_tf32_k<<<dim3(32, 8), blk>>>(x_input, apk, 1024);
    gemm_tc_k<<<dim3(2, 8), blk>>>(apk, w1p, tmp1, nullptr, 1024, 256, 1024);
    build_u_k<<<(262144 + 255) / 256, 256>>>(tmp1, u);
    pack_tf32_k<<<dim3(8, 8), blk>>>(u, apk, 256);
    gemm_tc_k<<<dim3(8, 8), blk>>>(apk, w2p, xdec, nullptr, 1024, 1024, 256);
    assemble_k<<<(2097152 + 255) / 256, 256>>>(x_input, xdec, pos_emb, x);

    for (int li = 0; li < 4; li++) {
        rmsnorm_k<<<2048, 256>>>(x, attn_norm_w + (size_t)li * 1024, xn);
        pack_tf32_k<<<dim3(32, 16), blk>>>(xn, apk, 1024);
        gemm_tc_k<<<dim3(24, 16), blk>>>(apk, qkvp + (size_t)li * 3145728, qkv, nullptr, 2048, 3072, 1024);
        qkrope_k<<<dim3(16, 1024, 2), 64>>>(qkv, cosT, sinT, qr, ktb_, vr);
        attn_k<<<dim3(128, 16, 2), 256>>>(qr, ktb_, vr, doc, atb);
        pack_tf32_k<<<dim3(32, 16), blk>>>(atb, apk, 1024);
        gemm_tc_k<<<dim3(8, 16), blk>>>(apk, wop + (size_t)li * 1048576, x1, x, 2048, 1024, 1024);
        rmsnorm_k<<<2048, 256>>>(x1, ffn_norm_w + (size_t)li * 1024, xn);
        pack_tf32_k<<<dim3(32, 16), blk>>>(xn, apk, 1024);
        gemm_tc_k<<<dim3(32, 16), blk>>>(apk, upp + (size_t)li * 4194304, up, nullptr, 2048, 4096, 1024);
        swiglu_k<<<(4194304 + 255) / 256, 256>>>(up, hb);
        pack_tf32_k<<<dim3(64, 16), blk>>>(hb, apk, 2048);
        gemm_tc_k<<<dim3(8, 16), blk>>>(apk, dwnp + (size_t)li * 2097152, x, x1, 2048, 1024, 2048);
    }

    gather_k<<<(1048576 + 255) / 256, 256>>>(x, (float*)d_out);
}

// round 7
// speedup vs baseline: 3.6295x; 1.5090x over previous
#include <cuda_runtime.h>
#include <math.h>
#include <stdint.h>

// Shapes (fixed): B=2, C=128, M=4, K=4, V=64, D=1024, H=16, A=64, L=4, HF=2048,
// E=8, S=1024, rows=2048

// ---------------- scratch (no allocations allowed) ----------------
__device__ float g_scratch[81854464];

static const size_t OFF_X    = 0;
static const size_t OFF_XN   = 2097152;
static const size_t OFF_X1   = 4194304;
static const size_t OFF_QKV  = 6291456;
static const size_t OFF_QR   = 12582912;
static const size_t OFF_KT   = 14680064;
static const size_t OFF_VR   = 16777216;
static const size_t OFF_ATTN = 18874368;
static const size_t OFF_UP   = 20971520;
static const size_t OFF_HB   = 29360128;
static const size_t OFF_TMP1 = 33554432;
static const size_t OFF_U    = 33816576;
static const size_t OFF_XDEC = 34078720;
// packed tf32 buffers
static const size_t OFF_APACK = 35127296;
static const size_t OFF_W1P   = 39321600;
static const size_t OFF_W2P   = 39583744;
static const size_t OFF_QKVP  = 39845888;
static const size_t OFF_WOP   = 52428800;
static const size_t OFF_UPP   = 56623104;
static const size_t OFF_DWNP  = 73400320;
static const size_t OFF_COS   = 81788928;
static const size_t OFF_SIN   = 81821696;

__device__ __forceinline__ uint32_t f2tf32(float x) {
    uint32_t r;
    asm("cvt.rna.tf32.f32 %0, %1;" : "=r"(r) : "f"(x));
    return r;
}

// ---------------- pack: row-major fp32 [R][K] -> tf32 fragment-packed ----------------
__global__ void __launch_bounds__(256) pack_tf32_k(
    const float* __restrict__ X, float* __restrict__ P, int K)
{
    const int tid  = threadIdx.x;
    const int rblk = blockIdx.y, ktb = blockIdx.x;
    const int g    = tid & 7;
    const int u32i = tid >> 3;
    const int kbb  = u32i >> 3;
    const int mgi  = u32i & 7;
    const int r0   = rblk * 128 + mgi * 16 + g;
    const int c0   = ktb * 32 + kbb * 8;

    const float4 a0  = *(const float4*)(X + (size_t)r0 * K + c0);
    const float4 a0h = *(const float4*)(X + (size_t)r0 * K + c0 + 4);
    const float4 a1  = *(const float4*)(X + (size_t)(r0 + 8) * K + c0);
    const float4 a1h = *(const float4*)(X + (size_t)(r0 + 8) * K + c0 + 4);

    const int kt16 = ktb * 2 + (kbb >> 1);
    const int kb   = kbb & 1;
    uint4* dst = (uint4*)P + ((size_t)rblk * (K >> 4) + kt16) * 512
               + (kb * 8 + mgi) * 32 + g * 4;
    uint4 w;
    w.x = f2tf32(a0.x); w.y = f2tf32(a1.x); w.z = f2tf32(a0h.x); w.w = f2tf32(a1h.x); dst[0] = w;
    w.x = f2tf32(a0.y); w.y = f2tf32(a1.y); w.z = f2tf32(a0h.y); w.w = f2tf32(a1h.y); dst[1] = w;
    w.x = f2tf32(a0.z); w.y = f2tf32(a1.z); w.z = f2tf32(a0h.z); w.w = f2tf32(a1h.z); dst[2] = w;
    w.x = f2tf32(a0.w); w.y = f2tf32(a1.w); w.z = f2tf32(a0h.w); w.w = f2tf32(a1h.w); dst[3] = w;
}

// ---------------- TF32 tensor-core GEMM on packed operands ----------------
// 128x128 block tile, 16-K stages, 4-stage cp.async ring (64KB dyn smem), 256 thr.
__global__ void __launch_bounds__(256, 2) gemm_tc_k(
    const float* __restrict__ Ap, const float* __restrict__ Bp,
    float* __restrict__ C, const float* __restrict__ Radd,
    int M, int N, int K)
{
    extern __shared__ uint4 dynsm[];
    uint4* smA = dynsm;              // [4][512]
    uint4* smB = dynsm + 4 * 512;    // [4][512]

    const int tid = threadIdx.x, lane = tid & 31, warp = tid >> 5;
    const int wm = warp >> 2, wn = warp & 3;
    const int g = lane >> 2, t = lane & 3;
    const int slotoff = g * 4 + (t ^ ((g >> 1) & 3));
    const int NT = K >> 4;

    const uint4* gA = (const uint4*)Ap + (size_t)blockIdx.y * NT * 512;
    const uint4* gB = (const uint4*)Bp + (size_t)blockIdx.x * NT * 512;

    const int  cq  = tid & 127;
    const int  cs  = (cq >> 1) & 3;
    const bool isB = tid >= 128;
    const uint4* gsrc = (isB ? gB : gA) + cq * 4;
    unsigned sAu = (unsigned)__cvta_generic_to_shared(smA);
    unsigned sBu = (unsigned)__cvta_generic_to_shared(smB);
    const unsigned dbase = (isB ? sBu : sAu) + cq * 64;

    float acc[4][4][4];
    #pragma unroll
    for (int mf = 0; mf < 4; mf++)
        #pragma unroll
        for (int nf = 0; nf < 4; nf++)
            #pragma unroll
            for (int i = 0; i < 4; i++) acc[mf][nf][i] = 0.f;

    #define ISSUE(KT, ST) do {                                              \
        const uint4* _s = gsrc + (size_t)(KT) * 512;                        \
        unsigned _d = dbase + (ST) * 8192;                                  \
        asm volatile("cp.async.cg.shared.global [%0], [%1], 16;" ::         \
            "r"(_d + ((0 ^ cs) << 4)), "l"(_s + 0));                        \
        asm volatile("cp.async.cg.shared.global [%0], [%1], 16;" ::         \
            "r"(_d + ((1 ^ cs) << 4)), "l"(_s + 1));                        \
        asm volatile("cp.async.cg.shared.global [%0], [%1], 16;" ::         \
            "r"(_d + ((2 ^ cs) << 4)), "l"(_s + 2));                        \
        asm volatile("cp.async.cg.shared.global [%0], [%1], 16;" ::         \
            "r"(_d + ((3 ^ cs) << 4)), "l"(_s + 3));                        \
    } while (0)

    ISSUE(0, 0);
    asm volatile("cp.async.commit_group;");
    ISSUE(1, 1);
    asm volatile("cp.async.commit_group;");
    ISSUE(2, 2);
    asm volatile("cp.async.commit_group;");

    int st = 0;
    for (int kt = 0; kt < NT; kt++) {
        asm volatile("cp.async.wait_group 2;");
        __syncthreads();
        const uint4* sa = smA + st * 512;
        const uint4* sb = smB + st * 512;
        #pragma unroll
        for (int kb = 0; kb < 2; kb++) {
            uint4 wa[4];
            #pragma unroll
            for (int mf = 0; mf < 4; mf++)
                wa[mf] = sa[(kb * 8 + wm * 4 + mf) * 32 + slotoff];
            const uint4 wb0 = sb[(kb * 8 + wn * 2 + 0) * 32 + slotoff];
            const uint4 wb1 = sb[(kb * 8 + wn * 2 + 1) * 32 + slotoff];
            const uint32_t bf[4][2] = {
                {wb0.x, wb0.z}, {wb0.y, wb0.w}, {wb1.x, wb1.z}, {wb1.y, wb1.w}};
            #pragma unroll
            for (int mf = 0; mf < 4; mf++)
                #pragma unroll
                for (int nf = 0; nf < 4; nf++) {
                    asm volatile(
                        "mma.sync.aligned.m16n8k8.row.col.f32.tf32.tf32.f32 "
                        "{%0,%1,%2,%3}, {%4,%5,%6,%7}, {%8,%9}, {%0,%1,%2,%3};\n"
                        : "+f"(acc[mf][nf][0]), "+f"(acc[mf][nf][1]),
                          "+f"(acc[mf][nf][2]), "+f"(acc[mf][nf][3])
                        : "r"(wa[mf].x), "r"(wa[mf].y), "r"(wa[mf].z), "r"(wa[mf].w),
                          "r"(bf[nf][0]), "r"(bf[nf][1]));
                }
        }
        const int ktn = kt + 3;
        const int stn = (st + 3) & 3;
        if (ktn < NT) ISSUE(ktn, stn);
        asm volatile("cp.async.commit_group;");
        st = (st + 1) & 3;
    }
    #undef ISSUE

    const int m0 = blockIdx.y * 128;
    const int n0 = blockIdx.x * 128;
    #pragma unroll
    for (int mf = 0; mf < 4; mf++) {
        const int r0 = m0 + wm * 64 + mf * 16 + g;
        #pragma unroll
        for (int nf = 0; nf < 4; nf++) {
            const int col = n0 + wn * 32 + nf * 8 + 2 * t;
            float2 v0 = make_float2(acc[mf][nf][0], acc[mf][nf][1]);
            float2 v1 = make_float2(acc[mf][nf][2], acc[mf][nf][3]);
            if (Radd) {
                float2 r0v = *(const float2*)&Radd[(size_t)r0 * N + col];
                float2 r1v = *(const float2*)&Radd[(size_t)(r0 + 8) * N + col];
                v0.x += r0v.x; v0.y += r0v.y;
                v1.x += r1v.x; v1.y += r1v.y;
            }
            *(float2*)&C[(size_t)r0 * N + col]       = v0;
            *(float2*)&C[(size_t)(r0 + 8) * N + col] = v1;
        }
    }
}

// ---------------- RoPE table (once per launch) ----------------
__global__ void rope_table_k(float* __restrict__ ct, float* __restrict__ st_)
{
    const int idx = blockIdx.x * 256 + threadIdx.x;
    if (idx >= 32768) return;
    const int s = idx >> 5, i = idx & 31;
    const double ang = (double)s * pow(10000.0, -(double)i / 32.0);
    ct[idx]  = (float)cos(ang);
    st_[idx] = (float)sin(ang);
}

// ---------------- RMSNorm (one block per row, D=1024) ----------------
__global__ void __launch_bounds__(256) rmsnorm_k(
    const float* __restrict__ x, const float* __restrict__ w, float* __restrict__ y)
{
    const int row = blockIdx.x;
    const float* xr = x + (size_t)row * 1024;
    float s = 0.f;
    for (int i = threadIdx.x; i < 1024; i += 256) { float v = xr[i]; s += v * v; }
    #pragma unroll
    for (int o = 16; o; o >>= 1) s += __shfl_xor_sync(0xffffffffu, s, o);
    __shared__ float red[8];
    const int warp = threadIdx.x >> 5, lane = threadIdx.x & 31;
    if (lane == 0) red[warp] = s;
    __syncthreads();
    float tot = 0.f;
    #pragma unroll
    for (int i = 0; i < 8; i++) tot += red[i];
    const float inv = rsqrtf(tot * (1.f / 1024.f) + 1e-5f);
    float* yr = y + (size_t)row * 1024;
    for (int i = threadIdx.x; i < 1024; i += 256) yr[i] = xr[i] * inv * w[i];
}

// ---------------- l2norm + RoPE + layout shuffle ----------------
__global__ void __launch_bounds__(64) qkrope_k(
    const float* __restrict__ qkv, const float* __restrict__ cosT,
    const float* __restrict__ sinT, float* __restrict__ qr,
    float* __restrict__ kt, float* __restrict__ vr)
{
    const int h = blockIdx.x, s = blockIdx.y, b = blockIdx.z;
    const int a = threadIdx.x;
    const float* base = qkv + ((size_t)b * 1024 + s) * 3072 + h * 64 + a;
    float q = base[0];
    float k = base[1024];
    float v = base[2048];

    float sq = q * q, sk = k * k;
    #pragma unroll
    for (int o = 16; o; o >>= 1) {
        sq += __shfl_xor_sync(0xffffffffu, sq, o);
        sk += __shfl_xor_sync(0xffffffffu, sk, o);
    }
    __shared__ float red[4];
    __shared__ float sqv[64], skv[64];
    const int warp = a >> 5;
    if ((a & 31) == 0) { red[warp * 2] = sq; red[warp * 2 + 1] = sk; }
    __syncthreads();
    const float nq = sqrtf(red[0] + red[2]);
    const float nk = sqrtf(red[1] + red[3]);
    q = q / fmaxf(nq, 1e-5f);
    k = k / fmaxf(nk, 1e-5f);
    sqv[a] = q; skv[a] = k;
    __syncthreads();

    const int i = a & 31;
    const float cz = cosT[s * 32 + i];
    const float sz = sinT[s * 32 + i];
    const float qp = sqv[a ^ 32], kp = skv[a ^ 32];
    const float qo = (a < 32) ? (q * cz + qp * sz) : (q * cz - qp * sz);
    const float ko = (a < 32) ? (k * cz + kp * sz) : (k * cz - kp * sz);

    const size_t bh = (size_t)b * 16 + h;
    qr[(bh * 1024 + s) * 64 + a] = qo;
    kt[(bh * 64 + a) * 1024 + s] = ko;       // K transposed: (b,h,a,s)
    vr[(bh * 1024 + s) * 64 + a] = v;
}

// ---------------- attention with compact key list ----------------
// Mask structure: for query block qt, admissible keys = own block (8 keys) +
// {prior blocks with equal doc id} x {kv slots k%8<4}. Everything else is an
// exact-zero softmax term; skip it.
__global__ void __launch_bounds__(256) attn_k(
    const float* __restrict__ qr, const float* __restrict__ kt,
    const float* __restrict__ vr, const int* __restrict__ doc,
    float* __restrict__ attn)
{
    const int qt = blockIdx.x, h = blockIdx.y, b = blockIdx.z;
    const int q0 = qt * 8;
    __shared__ float sQ[8][64];
    __shared__ float sS[8][520];
    __shared__ float sRed[4][8][64];
    __shared__ int   sDoc[128];
    __shared__ int   mbArr[128];
    __shared__ int   warpCnt[4];
    const int tid = threadIdx.x;
    if (tid < 128) sDoc[tid] = doc[b * 128 + tid];
    const size_t bh = (size_t)b * 16 + h;
    for (int i = tid; i < 8 * 64; i += 256) {
        int q = i >> 6, a = i & 63;
        sQ[q][a] = qr[(bh * 1024 + q0 + q) * 64 + a];
    }
    __syncthreads();

    // build compact list of matched prior blocks
    const int dq = sDoc[qt];
    int flag = 0, pre = 0;
    if (tid < 128) {
        flag = (tid < qt && sDoc[tid] == dq) ? 1 : 0;
        unsigned bal = __ballot_sync(0xffffffffu, flag);
        const int l = tid & 31;
        pre = __popc(bal & ((1u << l) - 1u));
        if (l == 31) warpCnt[tid >> 5] = pre + flag;
    }
    __syncthreads();
    int nc = warpCnt[0] + warpCnt[1] + warpCnt[2] + warpCnt[3];
    if (tid < 128 && flag) {
        const int w = tid >> 5;
        int base = 0;
        for (int i = 0; i < w; i++) base += warpCnt[i];
        mbArr[base + pre] = tid;
    }
    __syncthreads();
    const int nk = nc * 4 + 8;

    // QK^T over compact keys
    const float* ktp = kt + bh * 64 * 1024;
    for (int s = tid; s < nk; s += 256) {
        const int key = (s < nc * 4) ? (mbArr[s >> 2] * 8 + (s & 3))
                                     : (q0 + s - nc * 4);
        float acc[8];
        #pragma unroll
        for (int q = 0; q < 8; q++) acc[q] = 0.f;
        #pragma unroll 8
        for (int a = 0; a < 64; a++) {
            const float kv = ktp[a * 1024 + key];
            #pragma unroll
            for (int q = 0; q < 8; q++) acc[q] += sQ[q][a] * kv;
        }
        #pragma unroll
        for (int q = 0; q < 8; q++) sS[q][s] = acc[q] * 0.125f;
    }
    __syncthreads();

    // softmax: warp w handles query w, over nk entries (all unmasked)
    {
        const int q = tid >> 5, lane = tid & 31;
        float mx = -3.4e38f;
        for (int s = lane; s < nk; s += 32) mx = fmaxf(mx, sS[q][s]);
        #pragma unroll
        for (int o = 16; o; o >>= 1) mx = fmaxf(mx, __shfl_xor_sync(0xffffffffu, mx, o));
        float sum = 0.f;
        for (int s = lane; s < nk; s += 32) {
            const float e = expf(sS[q][s] - mx);
            sS[q][s] = e;
            sum += e;
        }
        #pragma unroll
        for (int o = 16; o; o >>= 1) sum += __shfl_xor_sync(0xffffffffu, sum, o);
        const float inv = 1.f / sum;
        for (int s = lane; s < nk; s += 32) sS[q][s] *= inv;
    }
    __syncthreads();

    // P@V over compact keys: thread = (a = tid&63, chunk = tid>>6)
    const float* vp = vr + bh * 1024 * 64;
    const int a = tid & 63, chunk = tid >> 6;
    const int csz = (nk + 3) >> 2;
    const int jlo = chunk * csz;
    const int jhi = min(nk, jlo + csz);
    float acc[8];
    #pragma unroll
    for (int q = 0; q < 8; q++) acc[q] = 0.f;
    for (int j = jlo; j < jhi; j++) {
        const int key = (j < nc * 4) ? (mbArr[j >> 2] * 8 + (j & 3))
                                     : (q0 + j - nc * 4);
        const float v = vp[(size_t)key * 64 + a];
        #pragma unroll
        for (int q = 0; q < 8; q++) acc[q] += sS[q][j] * v;
    }
    #pragma unroll
    for (int q = 0; q < 8; q++) sRed[chunk][q][a] = acc[q];
    __syncthreads();
    for (int i = tid; i < 8 * 64; i += 256) {
        const int q = i >> 6, a2 = i & 63;
        const float o = sRed[0][q][a2] + sRed[1][q][a2] + sRed[2][q][a2] + sRed[3][q][a2];
        attn[((size_t)b * 1024 + q0 + q) * 1024 + h * 64 + a2] = o;
    }
}

// ---------------- small elementwise kernels ----------------
__global__ void build_u_k(const float* __restrict__ t1, float* __restrict__ u)
{
    const int idx = blockIdx.x * blockDim.x + threadIdx.x;
    if (idx >= 1024 * 256) return;
    const int col = idx & 255;
    const int ru  = idx >> 8;
    const int m = col >> 6, v = col & 63;
    const int k = ru & 3, bc = ru >> 2;
    u[idx] = t1[((size_t)bc * 4 + m) * 256 + k * 64 + v];
}

__global__ void assemble_k(const float* __restrict__ xin, const float* __restrict__ xdec,
                           const float* __restrict__ pe, float* __restrict__ x)
{
    const int idx = blockIdx.x * blockDim.x + threadIdx.x;
    if (idx >= 2 * 1024 * 1024) return;
    const int d  = idx & 1023;
    const int sb = idx >> 10;
    const int s_ = sb & 1023;
    const int b  = sb >> 10;
    const int c  = s_ >> 3, e = s_ & 7;
    float v;
    if (e < 4) v = xin[((size_t)(b * 512 + c * 4 + e)) * 1024 + d];
    else       v = xdec[((size_t)((b * 128 + c) * 4 + (e - 4))) * 1024 + d]
                   + pe[(e - 4) * 1024 + d];
    x[idx] = v;
}

__global__ void swiglu_k(const float* __restrict__ up, float* __restrict__ hb)
{
    const int idx = blockIdx.x * blockDim.x + threadIdx.x;
    if (idx >= 2048 * 2048) return;
    const int m = idx >> 11;
    const int j = idx & 2047;
    const float a = up[(size_t)m * 4096 + j];
    const float b = up[(size_t)m * 4096 + 2048 + j];
    hb[idx] = (a / (1.f + expf(-a))) * b;
}

__global__ void gather_k(const float* __restrict__ x, float* __restrict__ out)
{
    const int idx = blockIdx.x * blockDim.x + threadIdx.x;
    if (idx >= 256 * 4 * 1024) return;
    const int d = idx & 1023;
    const int t = idx >> 10;
    const int k = t & 3;
    const int g = t >> 2;
    const int c = g & 127;
    const int b = g >> 7;
    out[idx] = x[((size_t)(b * 1024 + c * 8 + 4 + k)) * 1024 + d];
}

// ---------------- launch ----------------
extern "C" void kernel_launch(void* const* d_in, const int* in_sizes, int n_in,
                              void* d_out, int out_size)
{
    const float* x_input     = (const float*)d_in[0];
    const int*   doc         = (const int*)d_in[1];
    const float* dec_w1      = (const float*)d_in[2];
    const float* dec_w2      = (const float*)d_in[3];
    const float* pos_emb     = (const float*)d_in[4];
    const float* Wqkv        = (const float*)d_in[5];
    const float* Wo          = (const float*)d_in[6];
    const float* Wup         = (const float*)d_in[7];
    const float* Wdown       = (const float*)d_in[8];
    const float* attn_norm_w = (const float*)d_in[9];
    const float* ffn_norm_w  = (const float*)d_in[10];

    float* S = nullptr;
    cudaGetSymbolAddress((void**)&S, g_scratch);
    float* x    = S + OFF_X;
    float* xn   = S + OFF_XN;
    float* x1   = S + OFF_X1;
    float* qkv  = S + OFF_QKV;
    float* qr   = S + OFF_QR;
    float* ktb_ = S + OFF_KT;
    float* vr   = S + OFF_VR;
    float* atb  = S + OFF_ATTN;
    float* up   = S + OFF_UP;
    float* hb   = S + OFF_HB;
    float* tmp1 = S + OFF_TMP1;
    float* u    = S + OFF_U;
    float* xdec = S + OFF_XDEC;
    float* apk  = S + OFF_APACK;
    float* w1p  = S + OFF_W1P;
    float* w2p  = S + OFF_W2P;
    float* qkvp = S + OFF_QKVP;
    float* wop  = S + OFF_WOP;
    float* upp  = S + OFF_UPP;
    float* dwnp = S + OFF_DWNP;
    float* cosT = S + OFF_COS;
    float* sinT = S + OFF_SIN;

    const dim3 blk(256);
    const int GEMM_SMEM = 4 * 512 * 16 * 2;  // 65536 bytes
    cudaFuncSetAttribute(gemm_tc_k, cudaFuncAttributeMaxDynamicSharedMemorySize, GEMM_SMEM);

    // one-time per launch: rope table + weight packs
    rope_table_k<<<128, 256>>>(cosT, sinT);
    pack_tf32_k<<<dim3(32, 2),  blk>>>(dec_w1, w1p, 1024);
    pack_tf32_k<<<dim3(8, 8),   blk>>>(dec_w2, w2p, 256);
    for (int li = 0; li < 4; li++) {
        pack_tf32_k<<<dim3(32, 24), blk>>>(Wqkv  + (size_t)li * 3145728, qkvp + (size_t)li * 3145728, 1024);
        pack_tf32_k<<<dim3(32, 8),  blk>>>(Wo    + (size_t)li * 1048576, wop  + (size_t)li * 1048576, 1024);
        pack_tf32_k<<<dim3(32, 32), blk>>>(Wup   + (size_t)li * 4194304, upp  + (size_t)li * 4194304, 1024);
        pack_tf32_k<<<dim3(64, 8),  blk>>>(Wdown + (size_t)li * 2097152, dwnp + (size_t)li * 2097152, 2048);
    }

    // decoder front-end
    pack_tf32_k<<<dim3(32, 8), blk>>>(x_input, apk, 1024);
    gemm_tc_k<<<dim3(2, 8), blk, GEMM_SMEM>>>(apk, w1p, tmp1, nullptr, 1024, 256, 1024);
    build_u_k<<<(262144 + 255) / 256, 256>>>(tmp1, u);
    pack_tf32_k<<<dim3(8, 8), blk>>>(u, apk, 256);
    gemm_tc_k<<<dim3(8, 8), blk, GEMM_SMEM>>>(apk, w2p, xdec, nullptr, 1024, 1024, 256);
    assemble_k<<<(2097152 + 255) / 256, 256>>>(x_input, xdec, pos_emb, x);

    for (int li = 0; li < 4; li++) {
        rmsnorm_k<<<2048, 256>>>(x, attn_norm_w + (size_t)li * 1024, xn);
        pack_tf32_k<<<dim3(32, 16), blk>>>(xn, apk, 1024);
        gemm_tc_k<<<dim3(24, 16), blk, GEMM_SMEM>>>(apk, qkvp + (size_t)li * 3145728, qkv, nullptr, 2048, 3072, 1024);
        qkrope_k<<<dim3(16, 1024, 2), 64>>>(qkv, cosT, sinT, qr, ktb_, vr);
        attn_k<<<dim3(128, 16, 2), 256>>>(qr, ktb_, vr, doc, atb);
        pack_tf32_k<<<dim3(32, 16), blk>>>(atb, apk, 1024);
        gemm_tc_k<<<dim3(8, 16), blk, GEMM_SMEM>>>(apk, wop + (size_t)li * 1048576, x1, x, 2048, 1024, 1024);
        rmsnorm_k<<<2048, 256>>>(x1, ffn_norm_w + (size_t)li * 1024, xn);
        pack_tf32_k<<<dim3(32, 16), blk>>>(xn, apk, 1024);
        gemm_tc_k<<<dim3(32, 16), blk, GEMM_SMEM>>>(apk, upp + (size_t)li * 4194304, up, nullptr, 2048, 4096, 1024);
        swiglu_k<<<(4194304 + 255) / 256, 256>>>(up, hb);
        pack_tf32_k<<<dim3(64, 16), blk>>>(hb, apk, 2048);
        gemm_tc_k<<<dim3(8, 16), blk, GEMM_SMEM>>>(apk, dwnp + (size_t)li * 2097152, x, x1, 2048, 1024, 2048);
    }

    gather_k<<<(1048576 + 255) / 256, 256>>>(x, (float*)d_out);
}

// round 10
// speedup vs baseline: 3.6965x; 1.0184x over previous
#include <cuda_runtime.h>
#include <math.h>
#include <stdint.h>

// Shapes (fixed): B=2, C=128, M=4, K=4, V=64, D=1024, H=16, A=64, L=4, HF=2048,
// E=8, S=1024, rows=2048

// ---------------- scratch (no allocations allowed) ----------------
__device__ float g_scratch[81854464];

static const size_t OFF_X    = 0;
static const size_t OFF_XN   = 2097152;   // (unused now)
static const size_t OFF_X1   = 4194304;
static const size_t OFF_QKV  = 6291456;
static const size_t OFF_QR   = 12582912;
static const size_t OFF_KT   = 14680064;
static const size_t OFF_VR   = 16777216;
static const size_t OFF_ATTN = 18874368;  // (unused now)
static const size_t OFF_UP   = 20971520;  // (unused now)
static const size_t OFF_HB   = 29360128;  // hb PACKED (16MB)
static const size_t OFF_TMP1 = 33554432;
static const size_t OFF_U    = 33816576;  // (unused now)
static const size_t OFF_XDEC = 34078720;
// packed tf32 buffers
static const size_t OFF_APACK = 35127296;
static const size_t OFF_W1P   = 39321600;
static const size_t OFF_W2P   = 39583744;
static const size_t OFF_QKVP  = 39845888;
static const size_t OFF_WOP   = 52428800;
static const size_t OFF_UPP   = 56623104;
static const size_t OFF_DWNP  = 73400320;
static const size_t OFF_COS   = 81788928;
static const size_t OFF_SIN   = 81821696;

__device__ __forceinline__ uint32_t f2tf32(float x) {
    uint32_t r;
    asm("cvt.rna.tf32.f32 %0, %1;" : "=r"(r) : "f"(x));
    return r;
}

// Fragment-packed layout (per 128-row x 16-col region): 512 uint4 words.
// word slot = (kb*8 + mgi)*32 + g*4 + t, word = {X[r][c], X[r+8][c], X[r][c+4], X[r+8][c+4]}
// r = rblk*128 + mgi*16 + g (+8), c = kt16*16 + kb*8 + t (+4).
// Scalar float slot for element (r, c) of a matrix with row length K:
__device__ __forceinline__ size_t pk_idx(int r, int c, int K)
{
    const int rblk = r >> 7, rm = r & 127;
    const int g = rm & 7, half = (rm >> 3) & 1, mgi = rm >> 4;
    const int kt16 = c >> 4, co = c & 15;
    const int kb = co >> 3, t = co & 3, ch = (co >> 2) & 1;
    const size_t widx = ((size_t)rblk * (K >> 4) + kt16) * 512
                      + (size_t)((kb * 8 + mgi) * 32 + g * 4 + t);
    return widx * 4 + (half + 2 * ch);
}

// ---------------- pack: row-major fp32 [R][K] -> tf32 fragment-packed --------
// perm=1: source row n -> (n&1) ? 2048 + (n>>1) : (n>>1)   (Wup interleave)
__global__ void __launch_bounds__(256) pack_tf32_k(
    const float* __restrict__ X, float* __restrict__ P, int K, int perm)
{
    const int tid  = threadIdx.x;
    const int rblk = blockIdx.y, ktb = blockIdx.x;
    const int g    = tid & 7;
    const int u32i = tid >> 3;
    const int kbb  = u32i >> 3;
    const int mgi  = u32i & 7;
    const int r0   = rblk * 128 + mgi * 16 + g;
    const int c0   = ktb * 32 + kbb * 8;

    int ra = r0, rb = r0 + 8;
    if (perm) {
        ra = (r0 & 1) ? 2048 + (r0 >> 1) : (r0 >> 1);
        rb = ((r0 + 8) & 1) ? 2048 + ((r0 + 8) >> 1) : ((r0 + 8) >> 1);
    }

    const float4 a0  = *(const float4*)(X + (size_t)ra * K + c0);
    const float4 a0h = *(const float4*)(X + (size_t)ra * K + c0 + 4);
    const float4 a1  = *(const float4*)(X + (size_t)rb * K + c0);
    const float4 a1h = *(const float4*)(X + (size_t)rb * K + c0 + 4);

    const int kt16 = ktb * 2 + (kbb >> 1);
    const int kb   = kbb & 1;
    uint4* dst = (uint4*)P + ((size_t)rblk * (K >> 4) + kt16) * 512
               + (kb * 8 + mgi) * 32 + g * 4;
    uint4 w;
    w.x = f2tf32(a0.x); w.y = f2tf32(a1.x); w.z = f2tf32(a0h.x); w.w = f2tf32(a1h.x); dst[0] = w;
    w.x = f2tf32(a0.y); w.y = f2tf32(a1.y); w.z = f2tf32(a0h.y); w.w = f2tf32(a1h.y); dst[1] = w;
    w.x = f2tf32(a0.z); w.y = f2tf32(a1.z); w.z = f2tf32(a0h.z); w.w = f2tf32(a1h.z); dst[2] = w;
    w.x = f2tf32(a0.w); w.y = f2tf32(a1.w); w.z = f2tf32(a0h.w); w.w = f2tf32(a1h.w); dst[3] = w;
}

// ---------------- TF32 tensor-core GEMM on packed operands ----------------
// C[m,n] = sum_k A[m,k]*B[n,k] (+R[m,n]). 128x128 tile, 16-K stages,
// 6-stage cp.async ring (96KB dyn smem), 256 threads (8 warps 2x4).
// mode 0: C float (+Radd). mode 1: SwiGLU epilogue -> C is PACKED hb
//   (acc cols 2t/2t+1 are a (u1,u2) pair; hb col = global_col>>1, K_hb=2048).
__global__ void __launch_bounds__(256, 2) gemm_tc_k(
    const float* __restrict__ Ap, const float* __restrict__ Bp,
    float* __restrict__ C, const float* __restrict__ Radd,
    int N, int K, int mode)
{
    extern __shared__ uint4 dynsm[];
    uint4* smA = dynsm;              // [6][512]
    uint4* smB = dynsm + 6 * 512;    // [6][512]

    const int tid = threadIdx.x, lane = tid & 31, warp = tid >> 5;
    const int wm = warp >> 2, wn = warp & 3;
    const int g = lane >> 2, t = lane & 3;
    const int slotoff = g * 4 + (t ^ ((g >> 1) & 3));
    const int NT = K >> 4;

    const uint4* gA = (const uint4*)Ap + (size_t)blockIdx.y * NT * 512;
    const uint4* gB = (const uint4*)Bp + (size_t)blockIdx.x * NT * 512;

    const int  cq  = tid & 127;
    const int  cs  = (cq >> 1) & 3;
    const bool isB = tid >= 128;
    const uint4* gsrc = (isB ? gB : gA) + cq * 4;
    unsigned sAu = (unsigned)__cvta_generic_to_shared(smA);
    unsigned sBu = (unsigned)__cvta_generic_to_shared(smB);
    const unsigned dbase = (isB ? sBu : sAu) + cq * 64;

    float acc[4][4][4];
    #pragma unroll
    for (int mf = 0; mf < 4; mf++)
        #pragma unroll
        for (int nf = 0; nf < 4; nf++)
            #pragma unroll
            for (int i = 0; i < 4; i++) acc[mf][nf][i] = 0.f;

    #define ISSUE(KT, ST) do {                                              \
        const uint4* _s = gsrc + (size_t)(KT) * 512;                        \
        unsigned _d = dbase + (ST) * 8192;                                  \
        asm volatile("cp.async.cg.shared.global [%0], [%1], 16;" ::         \
            "r"(_d + ((0 ^ cs) << 4)), "l"(_s + 0));                        \
        asm volatile("cp.async.cg.shared.global [%0], [%1], 16;" ::         \
            "r"(_d + ((1 ^ cs) << 4)), "l"(_s + 1));                        \
        asm volatile("cp.async.cg.shared.global [%0], [%1], 16;" ::         \
            "r"(_d + ((2 ^ cs) << 4)), "l"(_s + 2));                        \
        asm volatile("cp.async.cg.shared.global [%0], [%1], 16;" ::         \
            "r"(_d + ((3 ^ cs) << 4)), "l"(_s + 3));                        \
    } while (0)

    #pragma unroll
    for (int p = 0; p < 5; p++) {
        if (p < NT) ISSUE(p, p);
        asm volatile("cp.async.commit_group;");
    }

    int st = 0;
    for (int kt = 0; kt < NT; kt++) {
        asm volatile("cp.async.wait_group 4;");
        __syncthreads();
        const uint4* sa = smA + st * 512;
        const uint4* sb = smB + st * 512;
        #pragma unroll
        for (int kb = 0; kb < 2; kb++) {
            uint4 wa[4];
            #pragma unroll
            for (int mf = 0; mf < 4; mf++)
                wa[mf] = sa[(kb * 8 + wm * 4 + mf) * 32 + slotoff];
            const uint4 wb0 = sb[(kb * 8 + wn * 2 + 0) * 32 + slotoff];
            const uint4 wb1 = sb[(kb * 8 + wn * 2 + 1) * 32 + slotoff];
            const uint32_t bf[4][2] = {
                {wb0.x, wb0.z}, {wb0.y, wb0.w}, {wb1.x, wb1.z}, {wb1.y, wb1.w}};
            #pragma unroll
            for (int mf = 0; mf < 4; mf++)
                #pragma unroll
                for (int nf = 0; nf < 4; nf++) {
                    asm volatile(
                        "mma.sync.aligned.m16n8k8.row.col.f32.tf32.tf32.f32 "
                        "{%0,%1,%2,%3}, {%4,%5,%6,%7}, {%8,%9}, {%0,%1,%2,%3};\n"
                        : "+f"(acc[mf][nf][0]), "+f"(acc[mf][nf][1]),
                          "+f"(acc[mf][nf][2]), "+f"(acc[mf][nf][3])
                        : "r"(wa[mf].x), "r"(wa[mf].y), "r"(wa[mf].z), "r"(wa[mf].w),
                          "r"(bf[nf][0]), "r"(bf[nf][1]));
                }
        }
        const int ktn = kt + 5;
        if (ktn < NT) { int stn = st + 5; if (stn >= 6) stn -= 6; ISSUE(ktn, stn); }
        asm volatile("cp.async.commit_group;");
        st++; if (st == 6) st = 0;
    }
    #undef ISSUE

    const int m0 = blockIdx.y * 128;
    const int n0 = blockIdx.x * 128;
    if (mode == 1) {
        // SwiGLU + pack epilogue: acc[.][.]{0,1} = (u1,u2) row r0; {2,3} row r0+8
        uint32_t* Cp = (uint32_t*)C;
        #pragma unroll
        for (int mf = 0; mf < 4; mf++) {
            const int r0 = m0 + wm * 64 + mf * 16 + g;
            #pragma unroll
            for (int nf = 0; nf < 4; nf++) {
                const int hcol = ((n0 + wn * 32 + nf * 8) >> 1) + t;
                const float a0 = acc[mf][nf][0], b0 = acc[mf][nf][1];
                const float a1 = acc[mf][nf][2], b1 = acc[mf][nf][3];
                const float h0 = (a0 / (1.f + expf(-a0))) * b0;
                const float h1 = (a1 / (1.f + expf(-a1))) * b1;
                Cp[pk_idx(r0,     hcol, 2048)] = f2tf32(h0);
                Cp[pk_idx(r0 + 8, hcol, 2048)] = f2tf32(h1);
            }
        }
    } else {
        #pragma unroll
        for (int mf = 0; mf < 4; mf++) {
            const int r0 = m0 + wm * 64 + mf * 16 + g;
            #pragma unroll
            for (int nf = 0; nf < 4; nf++) {
                const int col = n0 + wn * 32 + nf * 8 + 2 * t;
                float2 v0 = make_float2(acc[mf][nf][0], acc[mf][nf][1]);
                float2 v1 = make_float2(acc[mf][nf][2], acc[mf][nf][3]);
                if (Radd) {
                    float2 r0v = *(const float2*)&Radd[(size_t)r0 * N + col];
                    float2 r1v = *(const float2*)&Radd[(size_t)(r0 + 8) * N + col];
                    v0.x += r0v.x; v0.y += r0v.y;
                    v1.x += r1v.x; v1.y += r1v.y;
                }
                *(float2*)&C[(size_t)r0 * N + col]       = v0;
                *(float2*)&C[(size_t)(r0 + 8) * N + col] = v1;
            }
        }
    }
}

// ---------------- RoPE table (once per launch) ----------------
__global__ void rope_table_k(float* __restrict__ ct, float* __restrict__ st_)
{
    const int idx = blockIdx.x * 256 + threadIdx.x;
    if (idx >= 32768) return;
    const int s = idx >> 5, i = idx & 31;
    const double ang = (double)s * pow(10000.0, -(double)i / 32.0);
    ct[idx]  = (float)cos(ang);
    st_[idx] = (float)sin(ang);
}

// ---------------- RMSNorm + pack (one block per row, D=1024) ----------------
__global__ void __launch_bounds__(256) rmsnorm_pack_k(
    const float* __restrict__ x, const float* __restrict__ w, float* __restrict__ P)
{
    const int row = blockIdx.x;
    const float* xr = x + (size_t)row * 1024;
    float s = 0.f;
    for (int i = threadIdx.x; i < 1024; i += 256) { float v = xr[i]; s += v * v; }
    #pragma unroll
    for (int o = 16; o; o >>= 1) s += __shfl_xor_sync(0xffffffffu, s, o);
    __shared__ float red[8];
    const int warp = threadIdx.x >> 5, lane = threadIdx.x & 31;
    if (lane == 0) red[warp] = s;
    __syncthreads();
    float tot = 0.f;
    #pragma unroll
    for (int i = 0; i < 8; i++) tot += red[i];
    const float inv = rsqrtf(tot * (1.f / 1024.f) + 1e-5f);
    const int c4 = threadIdx.x * 4;
    const float4 v = *(const float4*)(xr + c4);
    const float4 wv = *(const float4*)(w + c4);
    uint32_t* Pp = (uint32_t*)P;
    Pp[pk_idx(row, c4 + 0, 1024)] = f2tf32(v.x * inv * wv.x);
    Pp[pk_idx(row, c4 + 1, 1024)] = f2tf32(v.y * inv * wv.y);
    Pp[pk_idx(row, c4 + 2, 1024)] = f2tf32(v.z * inv * wv.z);
    Pp[pk_idx(row, c4 + 3, 1024)] = f2tf32(v.w * inv * wv.w);
}

// ---------------- l2norm + RoPE + layout shuffle ----------------
__global__ void __launch_bounds__(64) qkrope_k(
    const float* __restrict__ qkv, const float* __restrict__ cosT,
    const float* __restrict__ sinT, float* __restrict__ qr,
    float* __restrict__ kt, float* __restrict__ vr)
{
    const int h = blockIdx.x, s = blockIdx.y, b = blockIdx.z;
    const int a = threadIdx.x;
    const float* base = qkv + ((size_t)b * 1024 + s) * 3072 + h * 64 + a;
    float q = base[0];
    float k = base[1024];
    float v = base[2048];

    float sq = q * q, sk = k * k;
    #pragma unroll
    for (int o = 16; o; o >>= 1) {
        sq += __shfl_xor_sync(0xffffffffu, sq, o);
        sk += __shfl_xor_sync(0xffffffffu, sk, o);
    }
    __shared__ float red[4];
    __shared__ float sqv[64], skv[64];
    const int warp = a >> 5;
    if ((a & 31) == 0) { red[warp * 2] = sq; red[warp * 2 + 1] = sk; }
    __syncthreads();
    const float nq = sqrtf(red[0] + red[2]);
    const float nk = sqrtf(red[1] + red[3]);
    q = q / fmaxf(nq, 1e-5f);
    k = k / fmaxf(nk, 1e-5f);
    sqv[a] = q; skv[a] = k;
    __syncthreads();

    const int i = a & 31;
    const float cz = cosT[s * 32 + i];
    const float sz = sinT[s * 32 + i];
    const float qp = sqv[a ^ 32], kp = skv[a ^ 32];
    const float qo = (a < 32) ? (q * cz + qp * sz) : (q * cz - qp * sz);
    const float ko = (a < 32) ? (k * cz + kp * sz) : (k * cz - kp * sz);

    const size_t bh = (size_t)b * 16 + h;
    qr[(bh * 1024 + s) * 64 + a] = qo;
    kt[(bh * 64 + a) * 1024 + s] = ko;       // K transposed: (b,h,a,s)
    vr[(bh * 1024 + s) * 64 + a] = v;
}

// ---------------- attention with compact key list; PACKED output ------------
__global__ void __launch_bounds__(256) attn_k(
    const float* __restrict__ qr, const float* __restrict__ kt,
    const float* __restrict__ vr, const int* __restrict__ doc,
    float* __restrict__ attnP)
{
    const int qt = blockIdx.x, h = blockIdx.y, b = blockIdx.z;
    const int q0 = qt * 8;
    __shared__ float sQ[8][64];
    __shared__ float sS[8][520];
    __shared__ float sRed[4][8][64];
    __shared__ int   sDoc[128];
    __shared__ int   mbArr[128];
    __shared__ int   warpCnt[4];
    const int tid = threadIdx.x;
    if (tid < 128) sDoc[tid] = doc[b * 128 + tid];
    const size_t bh = (size_t)b * 16 + h;
    for (int i = tid; i < 8 * 64; i += 256) {
        int q = i >> 6, a = i & 63;
        sQ[q][a] = qr[(bh * 1024 + q0 + q) * 64 + a];
    }
    __syncthreads();

    const int dq = sDoc[qt];
    int flag = 0, pre = 0;
    if (tid < 128) {
        flag = (tid < qt && sDoc[tid] == dq) ? 1 : 0;
        unsigned bal = __ballot_sync(0xffffffffu, flag);
        const int l = tid & 31;
        pre = __popc(bal & ((1u << l) - 1u));
        if (l == 31) warpCnt[tid >> 5] = pre + flag;
    }
    __syncthreads();
    int nc = warpCnt[0] + warpCnt[1] + warpCnt[2] + warpCnt[3];
    if (tid < 128 && flag) {
        const int w = tid >> 5;
        int base = 0;
        for (int i = 0; i < w; i++) base += warpCnt[i];
        mbArr[base + pre] = tid;
    }
    __syncthreads();
    const int nk = nc * 4 + 8;

    const float* ktp = kt + bh * 64 * 1024;
    for (int s = tid; s < nk; s += 256) {
        const int key = (s < nc * 4) ? (mbArr[s >> 2] * 8 + (s & 3))
                                     : (q0 + s - nc * 4);
        float acc[8];
        #pragma unroll
        for (int q = 0; q < 8; q++) acc[q] = 0.f;
        #pragma unroll 8
        for (int a = 0; a < 64; a++) {
            const float kv = ktp[a * 1024 + key];
            #pragma unroll
            for (int q = 0; q < 8; q++) acc[q] += sQ[q][a] * kv;
        }
        #pragma unroll
        for (int q = 0; q < 8; q++) sS[q][s] = acc[q] * 0.125f;
    }
    __syncthreads();

    {
        const int q = tid >> 5, lane = tid & 31;
        float mx = -3.4e38f;
        for (int s = lane; s < nk; s += 32) mx = fmaxf(mx, sS[q][s]);
        #pragma unroll
        for (int o = 16; o; o >>= 1) mx = fmaxf(mx, __shfl_xor_sync(0xffffffffu, mx, o));
        float sum = 0.f;
        for (int s = lane; s < nk; s += 32) {
            const float e = expf(sS[q][s] - mx);
            sS[q][s] = e;
            sum += e;
        }
        #pragma unroll
        for (int o = 16; o; o >>= 1) sum += __shfl_xor_sync(0xffffffffu, sum, o);
        const float inv = 1.f / sum;
        for (int s = lane; s < nk; s += 32) sS[q][s] *= inv;
    }
    __syncthreads();

    const float* vp = vr + bh * 1024 * 64;
    const int a = tid & 63, chunk = tid >> 6;
    const int csz = (nk + 3) >> 2;
    const int jlo = chunk * csz;
    const int jhi = min(nk, jlo + csz);
    float acc[8];
    #pragma unroll
    for (int q = 0; q < 8; q++) acc[q] = 0.f;
    for (int j = jlo; j < jhi; j++) {
        const int key = (j < nc * 4) ? (mbArr[j >> 2] * 8 + (j & 3))
                                     : (q0 + j - nc * 4);
        const float v = vp[(size_t)key * 64 + a];
        #pragma unroll
        for (int q = 0; q < 8; q++) acc[q] += sS[q][j] * v;
    }
    #pragma unroll
    for (int q = 0; q < 8; q++) sRed[chunk][q][a] = acc[q];
    __syncthreads();
    uint32_t* Pp = (uint32_t*)attnP;
    for (int i = tid; i < 8 * 64; i += 256) {
        const int q = i >> 6, a2 = i & 63;
        const float o = sRed[0][q][a2] + sRed[1][q][a2] + sRed[2][q][a2] + sRed[3][q][a2];
        Pp[pk_idx(b * 1024 + q0 + q, h * 64 + a2, 1024)] = f2tf32(o);
    }
}

// ---------------- small elementwise kernels ----------------
__global__ void build_u_pack_k(const float* __restrict__ t1, float* __restrict__ P)
{
    const int idx = blockIdx.x * blockDim.x + threadIdx.x;
    if (idx >= 1024 * 256) return;
    const int col = idx & 255;
    const int ru  = idx >> 8;
    const int m = col >> 6, v = col & 63;
    const int k = ru & 3, bc = ru >> 2;
    const float val = t1[((size_t)bc * 4 + m) * 256 + k * 64 + v];
    ((uint32_t*)P)[pk_idx(ru, col, 256)] = f2tf32(val);
}

__global__ void assemble_k(const float* __restrict__ xin, const float* __restrict__ xdec,
                           const float* __restrict__ pe, float* __restrict__ x)
{
    const int idx = blockIdx.x * blockDim.x + threadIdx.x;
    if (idx >= 2 * 1024 * 1024) return;
    const int d  = idx & 1023;
    const int sb = idx >> 10;
    const int s_ = sb & 1023;
    const int b  = sb >> 10;
    const int c  = s_ >> 3, e = s_ & 7;
    float v;
    if (e < 4) v = xin[((size_t)(b * 512 + c * 4 + e)) * 1024 + d];
    else       v = xdec[((size_t)((b * 128 + c) * 4 + (e - 4))) * 1024 + d]
                   + pe[(e - 4) * 1024 + d];
    x[idx] = v;
}

__global__ void gather_k(const float* __restrict__ x, float* __restrict__ out)
{
    const int idx = blockIdx.x * blockDim.x + threadIdx.x;
    if (idx >= 256 * 4 * 1024) return;
    const int d = idx & 1023;
    const int t = idx >> 10;
    const int k = t & 3;
    const int g = t >> 2;
    const int c = g & 127;
    const int b = g >> 7;
    out[idx] = x[((size_t)(b * 1024 + c * 8 + 4 + k)) * 1024 + d];
}

// ---------------- launch ----------------
extern "C" void kernel_launch(void* const* d_in, const int* in_sizes, int n_in,
                              void* d_out, int out_size)
{
    const float* x_input     = (const float*)d_in[0];
    const int*   doc         = (const int*)d_in[1];
    const float* dec_w1      = (const float*)d_in[2];
    const float* dec_w2      = (const float*)d_in[3];
    const float* pos_emb     = (const float*)d_in[4];
    const float* Wqkv        = (const float*)d_in[5];
    const float* Wo          = (const float*)d_in[6];
    const float* Wup         = (const float*)d_in[7];
    const float* Wdown       = (const float*)d_in[8];
    const float* attn_norm_w = (const float*)d_in[9];
    const float* ffn_norm_w  = (const float*)d_in[10];

    float* S = nullptr;
    cudaGetSymbolAddress((void**)&S, g_scratch);
    float* x    = S + OFF_X;
    float* x1   = S + OFF_X1;
    float* qkv  = S + OFF_QKV;
    float* qr   = S + OFF_QR;
    float* ktb_ = S + OFF_KT;
    float* vr   = S + OFF_VR;
    float* hbp  = S + OFF_HB;     // packed hb (K=2048)
    float* tmp1 = S + OFF_TMP1;
    float* xdec = S + OFF_XDEC;
    float* apk  = S + OFF_APACK;
    float* w1p  = S + OFF_W1P;
    float* w2p  = S + OFF_W2P;
    float* qkvp = S + OFF_QKVP;
    float* wop  = S + OFF_WOP;
    float* upp  = S + OFF_UPP;
    float* dwnp = S + OFF_DWNP;
    float* cosT = S + OFF_COS;
    float* sinT = S + OFF_SIN;

    const dim3 blk(256);
    const int GEMM_SMEM = 12 * 512 * 16;  // 98304 bytes (6 stages x (A+B))
    cudaFuncSetAttribute(gemm_tc_k, cudaFuncAttributeMaxDynamicSharedMemorySize, GEMM_SMEM);

    // one-time per launch: rope table + weight packs
    rope_table_k<<<128, 256>>>(cosT, sinT);
    pack_tf32_k<<<dim3(32, 2),  blk>>>(dec_w1, w1p, 1024, 0);
    pack_tf32_k<<<dim3(8, 8),   blk>>>(dec_w2, w2p, 256, 0);
    for (int li = 0; li < 4; li++) {
        pack_tf32_k<<<dim3(32, 24), blk>>>(Wqkv  + (size_t)li * 3145728, qkvp + (size_t)li * 3145728, 1024, 0);
        pack_tf32_k<<<dim3(32, 8),  blk>>>(Wo    + (size_t)li * 1048576, wop  + (size_t)li * 1048576, 1024, 0);
        pack_tf32_k<<<dim3(32, 32), blk>>>(Wup   + (size_t)li * 4194304, upp  + (size_t)li * 4194304, 1024, 1);
        pack_tf32_k<<<dim3(64, 8),  blk>>>(Wdown + (size_t)li * 2097152, dwnp + (size_t)li * 2097152, 2048, 0);
    }

    // decoder front-end
    pack_tf32_k<<<dim3(32, 8), blk>>>(x_input, apk, 1024, 0);
    gemm_tc_k<<<dim3(2, 8), blk, GEMM_SMEM>>>(apk, w1p, tmp1, nullptr, 256, 1024, 0);
    build_u_pack_k<<<(262144 + 255) / 256, 256>>>(tmp1, apk);
    gemm_tc_k<<<dim3(8, 8), blk, GEMM_SMEM>>>(apk, w2p, xdec, nullptr, 1024, 256, 0);
    assemble_k<<<(2097152 + 255) / 256, 256>>>(x_input, xdec, pos_emb, x);

    for (int li = 0; li < 4; li++) {
        rmsnorm_pack_k<<<2048, 256>>>(x, attn_norm_w + (size_t)li * 1024, apk);
        gemm_tc_k<<<dim3(24, 16), blk, GEMM_SMEM>>>(apk, qkvp + (size_t)li * 3145728, qkv, nullptr, 3072, 1024, 0);
        qkrope_k<<<dim3(16, 1024, 2), 64>>>(qkv, cosT, sinT, qr, ktb_, vr);
        attn_k<<<dim3(128, 16, 2), 256>>>(qr, ktb_, vr, doc, apk);
        gemm_tc_k<<<dim3(8, 16), blk, GEMM_SMEM>>>(apk, wop + (size_t)li * 1048576, x1, x, 1024, 1024, 0);
        rmsnorm_pack_k<<<2048, 256>>>(x1, ffn_norm_w + (size_t)li * 1024, apk);
        gemm_tc_k<<<dim3(32, 16), blk, GEMM_SMEM>>>(apk, upp + (size_t)li * 4194304, hbp, nullptr, 4096, 1024, 1);
        gemm_tc_k<<<dim3(8, 16), blk, GEMM_SMEM>>>(hbp, dwnp + (size_t)li * 2097152, x, x1, 1024, 2048, 0);
    }

    gather_k<<<(1048576 + 255) / 256, 256>>>(x, (float*)d_out);
}

// round 11
// speedup vs baseline: 3.8404x; 1.0389x over previous
#include <cuda_runtime.h>
#include <math.h>
#include <stdint.h>

// Shapes (fixed): B=2, C=128, M=4, K=4, V=64, D=1024, H=16, A=64, L=4, HF=2048,
// E=8, S=1024, rows=2048

// ---------------- scratch (no allocations allowed) ----------------
__device__ float g_scratch[81854464];

static const size_t OFF_X    = 0;
static const size_t OFF_X1   = 4194304;
static const size_t OFF_QKV  = 6291456;
static const size_t OFF_QR   = 12582912;
static const size_t OFF_KT   = 14680064;
static const size_t OFF_VR   = 16777216;
static const size_t OFF_HB   = 29360128;  // hb PACKED (16MB)
static const size_t OFF_TMP1 = 33554432;
static const size_t OFF_XDEC = 34078720;
// packed tf32 buffers
static const size_t OFF_APACK = 35127296;
static const size_t OFF_W1P   = 39321600;
static const size_t OFF_W2P   = 39583744;
static const size_t OFF_QKVP  = 39845888;
static const size_t OFF_WOP   = 52428800;
static const size_t OFF_UPP   = 56623104;
static const size_t OFF_DWNP  = 73400320;
static const size_t OFF_COS   = 81788928;
static const size_t OFF_SIN   = 81821696;

__device__ __forceinline__ uint32_t f2tf32(float x) {
    uint32_t r;
    asm("cvt.rna.tf32.f32 %0, %1;" : "=r"(r) : "f"(x));
    return r;
}

// Fragment-packed layout (per 128-row x 16-col region): 512 uint4 words.
// word slot = (kb*8 + mgi)*32 + g*4 + t, word = {X[r][c], X[r+8][c], X[r][c+4], X[r+8][c+4]}
__device__ __forceinline__ size_t pk_idx(int r, int c, int K)
{
    const int rblk = r >> 7, rm = r & 127;
    const int g = rm & 7, half = (rm >> 3) & 1, mgi = rm >> 4;
    const int kt16 = c >> 4, co = c & 15;
    const int kb = co >> 3, t = co & 3, ch = (co >> 2) & 1;
    const size_t widx = ((size_t)rblk * (K >> 4) + kt16) * 512
                      + (size_t)((kb * 8 + mgi) * 32 + g * 4 + t);
    return widx * 4 + (half + 2 * ch);
}

// dest swizzle for copier word w
__device__ __forceinline__ uint32_t wswz(uint32_t w) {
    return (w & ~3u) | ((w & 3u) ^ ((w >> 3) & 3u));
}

// ---------------- pack: row-major fp32 [R][K] -> tf32 fragment-packed --------
__global__ void __launch_bounds__(256) pack_tf32_k(
    const float* __restrict__ X, float* __restrict__ P, int K, int perm)
{
    const int tid  = threadIdx.x;
    const int rblk = blockIdx.y, ktb = blockIdx.x;
    const int g    = tid & 7;
    const int u32i = tid >> 3;
    const int kbb  = u32i >> 3;
    const int mgi  = u32i & 7;
    const int r0   = rblk * 128 + mgi * 16 + g;
    const int c0   = ktb * 32 + kbb * 8;

    int ra = r0, rb = r0 + 8;
    if (perm) {
        ra = (r0 & 1) ? 2048 + (r0 >> 1) : (r0 >> 1);
        rb = ((r0 + 8) & 1) ? 2048 + ((r0 + 8) >> 1) : ((r0 + 8) >> 1);
    }

    const float4 a0  = *(const float4*)(X + (size_t)ra * K + c0);
    const float4 a0h = *(const float4*)(X + (size_t)ra * K + c0 + 4);
    const float4 a1  = *(const float4*)(X + (size_t)rb * K + c0);
    const float4 a1h = *(const float4*)(X + (size_t)rb * K + c0 + 4);

    const int kt16 = ktb * 2 + (kbb >> 1);
    const int kb   = kbb & 1;
    uint4* dst = (uint4*)P + ((size_t)rblk * (K >> 4) + kt16) * 512
               + (kb * 8 + mgi) * 32 + g * 4;
    uint4 w;
    w.x = f2tf32(a0.x); w.y = f2tf32(a1.x); w.z = f2tf32(a0h.x); w.w = f2tf32(a1h.x); dst[0] = w;
    w.x = f2tf32(a0.y); w.y = f2tf32(a1.y); w.z = f2tf32(a0h.y); w.w = f2tf32(a1h.y); dst[1] = w;
    w.x = f2tf32(a0.z); w.y = f2tf32(a1.z); w.z = f2tf32(a0h.z); w.w = f2tf32(a1h.z); dst[2] = w;
    w.x = f2tf32(a0.w); w.y = f2tf32(a1.w); w.z = f2tf32(a0h.w); w.w = f2tf32(a1h.w); dst[3] = w;
}

// ---------------- TF32 GEMM, 128x128 tile (Wo/Wdown/front-end) --------------
__global__ void __launch_bounds__(256, 2) gemm_tc_k(
    const float* __restrict__ Ap, const float* __restrict__ Bp,
    float* __restrict__ C, const float* __restrict__ Radd,
    int N, int K, int mode)
{
    extern __shared__ uint4 dynsm[];
    uint4* smA = dynsm;              // [6][512]
    uint4* smB = dynsm + 6 * 512;    // [6][512]

    const int tid = threadIdx.x, lane = tid & 31, warp = tid >> 5;
    const int wm = warp >> 2, wn = warp & 3;
    const int g = lane >> 2, t = lane & 3;
    const int slotoff = g * 4 + (t ^ ((g >> 1) & 3));
    const int NT = K >> 4;

    const uint4* gA = (const uint4*)Ap + (size_t)blockIdx.y * NT * 512;
    const uint4* gB = (const uint4*)Bp + (size_t)blockIdx.x * NT * 512;

    const int  cq  = tid & 127;
    const int  cs  = (cq >> 1) & 3;
    const bool isB = tid >= 128;
    const uint4* gsrc = (isB ? gB : gA) + cq * 4;
    unsigned sAu = (unsigned)__cvta_generic_to_shared(smA);
    unsigned sBu = (unsigned)__cvta_generic_to_shared(smB);
    const unsigned dbase = (isB ? sBu : sAu) + cq * 64;

    float acc[4][4][4];
    #pragma unroll
    for (int mf = 0; mf < 4; mf++)
        #pragma unroll
        for (int nf = 0; nf < 4; nf++)
            #pragma unroll
            for (int i = 0; i < 4; i++) acc[mf][nf][i] = 0.f;

    #define ISSUE(KT, ST) do {                                              \
        const uint4* _s = gsrc + (size_t)(KT) * 512;                        \
        unsigned _d = dbase + (ST) * 8192;                                  \
        asm volatile("cp.async.cg.shared.global [%0], [%1], 16;" ::         \
            "r"(_d + ((0 ^ cs) << 4)), "l"(_s + 0));                        \
        asm volatile("cp.async.cg.shared.global [%0], [%1], 16;" ::         \
            "r"(_d + ((1 ^ cs) << 4)), "l"(_s + 1));                        \
        asm volatile("cp.async.cg.shared.global [%0], [%1], 16;" ::         \
            "r"(_d + ((2 ^ cs) << 4)), "l"(_s + 2));                        \
        asm volatile("cp.async.cg.shared.global [%0], [%1], 16;" ::         \
            "r"(_d + ((3 ^ cs) << 4)), "l"(_s + 3));                        \
    } while (0)

    #pragma unroll
    for (int p = 0; p < 5; p++) {
        if (p < NT) ISSUE(p, p);
        asm volatile("cp.async.commit_group;");
    }

    int st = 0;
    for (int kt = 0; kt < NT; kt++) {
        asm volatile("cp.async.wait_group 4;");
        __syncthreads();
        const uint4* sa = smA + st * 512;
        const uint4* sb = smB + st * 512;
        #pragma unroll
        for (int kb = 0; kb < 2; kb++) {
            uint4 wa[4];
            #pragma unroll
            for (int mf = 0; mf < 4; mf++)
                wa[mf] = sa[(kb * 8 + wm * 4 + mf) * 32 + slotoff];
            const uint4 wb0 = sb[(kb * 8 + wn * 2 + 0) * 32 + slotoff];
            const uint4 wb1 = sb[(kb * 8 + wn * 2 + 1) * 32 + slotoff];
            const uint32_t bf[4][2] = {
                {wb0.x, wb0.z}, {wb0.y, wb0.w}, {wb1.x, wb1.z}, {wb1.y, wb1.w}};
            #pragma unroll
            for (int mf = 0; mf < 4; mf++)
                #pragma unroll
                for (int nf = 0; nf < 4; nf++) {
                    asm volatile(
                        "mma.sync.aligned.m16n8k8.row.col.f32.tf32.tf32.f32 "
                        "{%0,%1,%2,%3}, {%4,%5,%6,%7}, {%8,%9}, {%0,%1,%2,%3};\n"
                        : "+f"(acc[mf][nf][0]), "+f"(acc[mf][nf][1]),
                          "+f"(acc[mf][nf][2]), "+f"(acc[mf][nf][3])
                        : "r"(wa[mf].x), "r"(wa[mf].y), "r"(wa[mf].z), "r"(wa[mf].w),
                          "r"(bf[nf][0]), "r"(bf[nf][1]));
                }
        }
        const int ktn = kt + 5;
        if (ktn < NT) { int stn = st + 5; if (stn >= 6) stn -= 6; ISSUE(ktn, stn); }
        asm volatile("cp.async.commit_group;");
        st++; if (st == 6) st = 0;
    }
    #undef ISSUE

    const int m0 = blockIdx.y * 128;
    const int n0 = blockIdx.x * 128;
    if (mode == 1) {
        uint32_t* Cp = (uint32_t*)C;
        #pragma unroll
        for (int mf = 0; mf < 4; mf++) {
            const int r0 = m0 + wm * 64 + mf * 16 + g;
            #pragma unroll
            for (int nf = 0; nf < 4; nf++) {
                const int hcol = ((n0 + wn * 32 + nf * 8) >> 1) + t;
                const float a0 = acc[mf][nf][0], b0 = acc[mf][nf][1];
                const float a1 = acc[mf][nf][2], b1 = acc[mf][nf][3];
                const float h0 = (a0 / (1.f + expf(-a0))) * b0;
                const float h1 = (a1 / (1.f + expf(-a1))) * b1;
                Cp[pk_idx(r0,     hcol, 2048)] = f2tf32(h0);
                Cp[pk_idx(r0 + 8, hcol, 2048)] = f2tf32(h1);
            }
        }
    } else {
        #pragma unroll
        for (int mf = 0; mf < 4; mf++) {
            const int r0 = m0 + wm * 64 + mf * 16 + g;
            #pragma unroll
            for (int nf = 0; nf < 4; nf++) {
                const int col = n0 + wn * 32 + nf * 8 + 2 * t;
                float2 v0 = make_float2(acc[mf][nf][0], acc[mf][nf][1]);
                float2 v1 = make_float2(acc[mf][nf][2], acc[mf][nf][3]);
                if (Radd) {
                    float2 r0v = *(const float2*)&Radd[(size_t)r0 * N + col];
                    float2 r1v = *(const float2*)&Radd[(size_t)(r0 + 8) * N + col];
                    v0.x += r0v.x; v0.y += r0v.y;
                    v1.x += r1v.x; v1.y += r1v.y;
                }
                *(float2*)&C[(size_t)r0 * N + col]       = v0;
                *(float2*)&C[(size_t)(r0 + 8) * N + col] = v1;
            }
        }
    }
}

// ---------------- TF32 GEMM, 128x256 tile, 64x64 warp tile (QKV/Wup) --------
// Doubles FLOP per smem byte (16 vs 10.7) -> crossbar ceiling ~2x.
// 1 CTA/SM (RF-limited: 128 acc regs/thread). 6-stage ring, 24KB/stage.
__global__ void __launch_bounds__(256, 1) gemm_big_k(
    const float* __restrict__ Ap, const float* __restrict__ Bp,
    float* __restrict__ C, const float* __restrict__ Radd,
    int N, int K, int mode)
{
    extern __shared__ uint4 dynsm[];   // [6][1536]: A 512 + B 1024 words/stage
    const int tid = threadIdx.x, lane = tid & 31, warp = tid >> 5;
    const int wm = warp >> 2, wn = warp & 3;
    const int g = lane >> 2, t = lane & 3;
    const int slotoff = g * 4 + (t ^ ((g >> 1) & 3));
    const int NT = K >> 4;

    const uint4* gA  = (const uint4*)Ap + (size_t)blockIdx.y * NT * 512;
    const uint4* gB0 = (const uint4*)Bp + (size_t)(2 * blockIdx.x) * NT * 512;
    const uint4* gB1 = (const uint4*)Bp + (size_t)(2 * blockIdx.x + 1) * NT * 512;

    const unsigned sbase = (unsigned)__cvta_generic_to_shared(dynsm);
    // per-thread copier word assignments (byte offsets within regions)
    const unsigned dA0 = wswz(tid) * 16,        dA1 = wswz(tid + 256) * 16;
    const unsigned dB0 = wswz(tid) * 16,        dB1 = wswz(tid + 256) * 16;
    const unsigned dB2 = wswz(tid + 512) * 16,  dB3 = wswz(tid + 768) * 16;

    float acc[4][8][4];
    #pragma unroll
    for (int mf = 0; mf < 4; mf++)
        #pragma unroll
        for (int nf = 0; nf < 8; nf++)
            #pragma unroll
            for (int i = 0; i < 4; i++) acc[mf][nf][i] = 0.f;

    #define ISSUEB(KT, ST) do {                                             \
        const unsigned _b = sbase + (ST) * 24576;                           \
        const uint4* _a = gA  + (size_t)(KT) * 512;                         \
        const uint4* _p = gB0 + (size_t)(KT) * 512;                         \
        const uint4* _q = gB1 + (size_t)(KT) * 512;                         \
        asm volatile("cp.async.cg.shared.global [%0], [%1], 16;" ::         \
            "r"(_b + dA0), "l"(_a + tid));                                  \
        asm volatile("cp.async.cg.shared.global [%0], [%1], 16;" ::         \
            "r"(_b + dA1), "l"(_a + tid + 256));                            \
        asm volatile("cp.async.cg.shared.global [%0], [%1], 16;" ::         \
            "r"(_b + 8192 + dB0), "l"(_p + tid));                           \
        asm volatile("cp.async.cg.shared.global [%0], [%1], 16;" ::         \
            "r"(_b + 8192 + dB1), "l"(_p + tid + 256));                     \
        asm volatile("cp.async.cg.shared.global [%0], [%1], 16;" ::         \
            "r"(_b + 8192 + dB2), "l"(_q + tid));                           \
        asm volatile("cp.async.cg.shared.global [%0], [%1], 16;" ::         \
            "r"(_b + 8192 + dB3), "l"(_q + tid + 256));                     \
    } while (0)

    #pragma unroll
    for (int p = 0; p < 5; p++) {
        if (p < NT) ISSUEB(p, p);
        asm volatile("cp.async.commit_group;");
    }

    int st = 0;
    for (int kt = 0; kt < NT; kt++) {
        asm volatile("cp.async.wait_group 4;");
        __syncthreads();
        const uint4* sa = dynsm + st * 1536;
        const uint4* sb = sa + 512;
        #pragma unroll
        for (int kb = 0; kb < 2; kb++) {
            uint4 wa[4];
            #pragma unroll
            for (int mf = 0; mf < 4; mf++)
                wa[mf] = sa[(kb * 8 + wm * 4 + mf) * 32 + slotoff];
            uint4 wb[4];
            #pragma unroll
            for (int j = 0; j < 4; j++) {
                const int ng = wn * 4 + j;
                wb[j] = sb[((ng >> 3) << 9) + (kb * 8 + (ng & 7)) * 32 + slotoff];
            }
            #pragma unroll
            for (int mf = 0; mf < 4; mf++)
                #pragma unroll
                for (int j = 0; j < 4; j++) {
                    asm volatile(
                        "mma.sync.aligned.m16n8k8.row.col.f32.tf32.tf32.f32 "
                        "{%0,%1,%2,%3}, {%4,%5,%6,%7}, {%8,%9}, {%0,%1,%2,%3};\n"
                        : "+f"(acc[mf][2*j][0]), "+f"(acc[mf][2*j][1]),
                          "+f"(acc[mf][2*j][2]), "+f"(acc[mf][2*j][3])
                        : "r"(wa[mf].x), "r"(wa[mf].y), "r"(wa[mf].z), "r"(wa[mf].w),
                          "r"(wb[j].x), "r"(wb[j].z));
                    asm volatile(
                        "mma.sync.aligned.m16n8k8.row.col.f32.tf32.tf32.f32 "
                        "{%0,%1,%2,%3}, {%4,%5,%6,%7}, {%8,%9}, {%0,%1,%2,%3};\n"
                        : "+f"(acc[mf][2*j+1][0]), "+f"(acc[mf][2*j+1][1]),
                          "+f"(acc[mf][2*j+1][2]), "+f"(acc[mf][2*j+1][3])
                        : "r"(wa[mf].x), "r"(wa[mf].y), "r"(wa[mf].z), "r"(wa[mf].w),
                          "r"(wb[j].y), "r"(wb[j].w));
                }
        }
        const int ktn = kt + 5;
        if (ktn < NT) { int stn = st + 5; if (stn >= 6) stn -= 6; ISSUEB(ktn, stn); }
        asm volatile("cp.async.commit_group;");
        st++; if (st == 6) st = 0;
    }
    #undef ISSUEB

    const int m0 = blockIdx.y * 128;
    const int n0 = blockIdx.x * 256;
    if (mode == 1) {
        uint32_t* Cp = (uint32_t*)C;
        #pragma unroll
        for (int mf = 0; mf < 4; mf++) {
            const int r0 = m0 + wm * 64 + mf * 16 + g;
            #pragma unroll
            for (int nf = 0; nf < 8; nf++) {
                const int hcol = ((n0 + wn * 64 + nf * 8) >> 1) + t;
                const float a0 = acc[mf][nf][0], b0 = acc[mf][nf][1];
                const float a1 = acc[mf][nf][2], b1 = acc[mf][nf][3];
                const float h0 = (a0 / (1.f + expf(-a0))) * b0;
                const float h1 = (a1 / (1.f + expf(-a1))) * b1;
                Cp[pk_idx(r0,     hcol, 2048)] = f2tf32(h0);
                Cp[pk_idx(r0 + 8, hcol, 2048)] = f2tf32(h1);
            }
        }
    } else {
        #pragma unroll
        for (int mf = 0; mf < 4; mf++) {
            const int r0 = m0 + wm * 64 + mf * 16 + g;
            #pragma unroll
            for (int nf = 0; nf < 8; nf++) {
                const int col = n0 + wn * 64 + nf * 8 + 2 * t;
                float2 v0 = make_float2(acc[mf][nf][0], acc[mf][nf][1]);
                float2 v1 = make_float2(acc[mf][nf][2], acc[mf][nf][3]);
                if (Radd) {
                    float2 r0v = *(const float2*)&Radd[(size_t)r0 * N + col];
                    float2 r1v = *(const float2*)&Radd[(size_t)(r0 + 8) * N + col];
                    v0.x += r0v.x; v0.y += r0v.y;
                    v1.x += r1v.x; v1.y += r1v.y;
                }
                *(float2*)&C[(size_t)r0 * N + col]       = v0;
                *(float2*)&C[(size_t)(r0 + 8) * N + col] = v1;
            }
        }
    }
}

// ---------------- RoPE table (once per launch) ----------------
__global__ void rope_table_k(float* __restrict__ ct, float* __restrict__ st_)
{
    const int idx = blockIdx.x * 256 + threadIdx.x;
    if (idx >= 32768) return;
    const int s = idx >> 5, i = idx & 31;
    const double ang = (double)s * pow(10000.0, -(double)i / 32.0);
    ct[idx]  = (float)cos(ang);
    st_[idx] = (float)sin(ang);
}

// ---------------- RMSNorm + pack (one block per row, D=1024) ----------------
__global__ void __launch_bounds__(256) rmsnorm_pack_k(
    const float* __restrict__ x, const float* __restrict__ w, float* __restrict__ P)
{
    const int row = blockIdx.x;
    const float* xr = x + (size_t)row * 1024;
    float s = 0.f;
    for (int i = threadIdx.x; i < 1024; i += 256) { float v = xr[i]; s += v * v; }
    #pragma unroll
    for (int o = 16; o; o >>= 1) s += __shfl_xor_sync(0xffffffffu, s, o);
    __shared__ float red[8];
    const int warp = threadIdx.x >> 5, lane = threadIdx.x & 31;
    if (lane == 0) red[warp] = s;
    __syncthreads();
    float tot = 0.f;
    #pragma unroll
    for (int i = 0; i < 8; i++) tot += red[i];
    const float inv = rsqrtf(tot * (1.f / 1024.f) + 1e-5f);
    const int c4 = threadIdx.x * 4;
    const float4 v = *(const float4*)(xr + c4);
    const float4 wv = *(const float4*)(w + c4);
    uint32_t* Pp = (uint32_t*)P;
    Pp[pk_idx(row, c4 + 0, 1024)] = f2tf32(v.x * inv * wv.x);
    Pp[pk_idx(row, c4 + 1, 1024)] = f2tf32(v.y * inv * wv.y);
    Pp[pk_idx(row, c4 + 2, 1024)] = f2tf32(v.z * inv * wv.z);
    Pp[pk_idx(row, c4 + 3, 1024)] = f2tf32(v.w * inv * wv.w);
}

// ---------------- l2norm + RoPE + layout shuffle ----------------
__global__ void __launch_bounds__(64) qkrope_k(
    const float* __restrict__ qkv, const float* __restrict__ cosT,
    const float* __restrict__ sinT, float* __restrict__ qr,
    float* __restrict__ kt, float* __restrict__ vr)
{
    const int h = blockIdx.x, s = blockIdx.y, b = blockIdx.z;
    const int a = threadIdx.x;
    const float* base = qkv + ((size_t)b * 1024 + s) * 3072 + h * 64 + a;
    float q = base[0];
    float k = base[1024];
    float v = base[2048];

    float sq = q * q, sk = k * k;
    #pragma unroll
    for (int o = 16; o; o >>= 1) {
        sq += __shfl_xor_sync(0xffffffffu, sq, o);
        sk += __shfl_xor_sync(0xffffffffu, sk, o);
    }
    __shared__ float red[4];
    __shared__ float sqv[64], skv[64];
    const int warp = a >> 5;
    if ((a & 31) == 0) { red[warp * 2] = sq; red[warp * 2 + 1] = sk; }
    __syncthreads();
    const float nq = sqrtf(red[0] + red[2]);
    const float nk = sqrtf(red[1] + red[3]);
    q = q / fmaxf(nq, 1e-5f);
    k = k / fmaxf(nk, 1e-5f);
    sqv[a] = q; skv[a] = k;
    __syncthreads();

    const int i = a & 31;
    const float cz = cosT[s * 32 + i];
    const float sz = sinT[s * 32 + i];
    const float qp = sqv[a ^ 32], kp = skv[a ^ 32];
    const float qo = (a < 32) ? (q * cz + qp * sz) : (q * cz - qp * sz);
    const float ko = (a < 32) ? (k * cz + kp * sz) : (k * cz - kp * sz);

    const size_t bh = (size_t)b * 16 + h;
    qr[(bh * 1024 + s) * 64 + a] = qo;
    kt[(bh * 64 + a) * 1024 + s] = ko;       // K transposed: (b,h,a,s)
    vr[(bh * 1024 + s) * 64 + a] = v;
}

// ---------------- attention with compact key list; PACKED output ------------
__global__ void __launch_bounds__(256) attn_k(
    const float* __restrict__ qr, const float* __restrict__ kt,
    const float* __restrict__ vr, const int* __restrict__ doc,
    float* __restrict__ attnP)
{
    const int qt = blockIdx.x, h = blockIdx.y, b = blockIdx.z;
    const int q0 = qt * 8;
    __shared__ float sQ[8][64];
    __shared__ float sS[8][520];
    __shared__ float sRed[4][8][64];
    __shared__ int   sDoc[128];
    __shared__ int   mbArr[128];
    __shared__ int   warpCnt[4];
    const int tid = threadIdx.x;
    if (tid < 128) sDoc[tid] = doc[b * 128 + tid];
    const size_t bh = (size_t)b * 16 + h;
    for (int i = tid; i < 8 * 64; i += 256) {
        int q = i >> 6, a = i & 63;
        sQ[q][a] = qr[(bh * 1024 + q0 + q) * 64 + a];
    }
    __syncthreads();

    const int dq = sDoc[qt];
    int flag = 0, pre = 0;
    if (tid < 128) {
        flag = (tid < qt && sDoc[tid] == dq) ? 1 : 0;
        unsigned bal = __ballot_sync(0xffffffffu, flag);
        const int l = tid & 31;
        pre = __popc(bal & ((1u << l) - 1u));
        if (l == 31) warpCnt[tid >> 5] = pre + flag;
    }
    __syncthreads();
    int nc = warpCnt[0] + warpCnt[1] + warpCnt[2] + warpCnt[3];
    if (tid < 128 && flag) {
        const int w = tid >> 5;
        int base = 0;
        for (int i = 0; i < w; i++) base += warpCnt[i];
        mbArr[base + pre] = tid;
    }
    __syncthreads();
    const int nk = nc * 4 + 8;

    const float* ktp = kt + bh * 64 * 1024;
    for (int s = tid; s < nk; s += 256) {
        const int key = (s < nc * 4) ? (mbArr[s >> 2] * 8 + (s & 3))
                                     : (q0 + s - nc * 4);
        float acc[8];
        #pragma unroll
        for (int q = 0; q < 8; q++) acc[q] = 0.f;
        #pragma unroll 8
        for (int a = 0; a < 64; a++) {
            const float kv = ktp[a * 1024 + key];
            #pragma unroll
            for (int q = 0; q < 8; q++) acc[q] += sQ[q][a] * kv;
        }
        #pragma unroll
        for (int q = 0; q < 8; q++) sS[q][s] = acc[q] * 0.125f;
    }
    __syncthreads();

    {
        const int q = tid >> 5, lane = tid & 31;
        float mx = -3.4e38f;
        for (int s = lane; s < nk; s += 32) mx = fmaxf(mx, sS[q][s]);
        #pragma unroll
        for (int o = 16; o; o >>= 1) mx = fmaxf(mx, __shfl_xor_sync(0xffffffffu, mx, o));
        float sum = 0.f;
        for (int s = lane; s < nk; s += 32) {
            const float e = expf(sS[q][s] - mx);
            sS[q][s] = e;
            sum += e;
        }
        #pragma unroll
        for (int o = 16; o; o >>= 1) sum += __shfl_xor_sync(0xffffffffu, sum, o);
        const float inv = 1.f / sum;
        for (int s = lane; s < nk; s += 32) sS[q][s] *= inv;
    }
    __syncthreads();

    const float* vp = vr + bh * 1024 * 64;
    const int a = tid & 63, chunk = tid >> 6;
    const int csz = (nk + 3) >> 2;
    const int jlo = chunk * csz;
    const int jhi = min(nk, jlo + csz);
    float acc[8];
    #pragma unroll
    for (int q = 0; q < 8; q++) acc[q] = 0.f;
    for (int j = jlo; j < jhi; j++) {
        const int key = (j < nc * 4) ? (mbArr[j >> 2] * 8 + (j & 3))
                                     : (q0 + j - nc * 4);
        const float v = vp[(size_t)key * 64 + a];
        #pragma unroll
        for (int q = 0; q < 8; q++) acc[q] += sS[q][j] * v;
    }
    #pragma unroll
    for (int q = 0; q < 8; q++) sRed[chunk][q][a] = acc[q];
    __syncthreads();
    uint32_t* Pp = (uint32_t*)attnP;
    for (int i = tid; i < 8 * 64; i += 256) {
        const int q = i >> 6, a2 = i & 63;
        const float o = sRed[0][q][a2] + sRed[1][q][a2] + sRed[2][q][a2] + sRed[3][q][a2];
        Pp[pk_idx(b * 1024 + q0 + q, h * 64 + a2, 1024)] = f2tf32(o);
    }
}

// ---------------- small elementwise kernels ----------------
__global__ void build_u_pack_k(const float* __restrict__ t1, float* __restrict__ P)
{
    const int idx = blockIdx.x * blockDim.x + threadIdx.x;
    if (idx >= 1024 * 256) return;
    const int col = idx & 255;
    const int ru  = idx >> 8;
    const int m = col >> 6, v = col & 63;
    const int k = ru & 3, bc = ru >> 2;
    const float val = t1[((size_t)bc * 4 + m) * 256 + k * 64 + v];
    ((uint32_t*)P)[pk_idx(ru, col, 256)] = f2tf32(val);
}

__global__ void assemble_k(const float* __restrict__ xin, const float* __restrict__ xdec,
                           const float* __restrict__ pe, float* __restrict__ x)
{
    const int idx = blockIdx.x * blockDim.x + threadIdx.x;
    if (idx >= 2 * 1024 * 1024) return;
    const int d  = idx & 1023;
    const int sb = idx >> 10;
    const int s_ = sb & 1023;
    const int b  = sb >> 10;
    const int c  = s_ >> 3, e = s_ & 7;
    float v;
    if (e < 4) v = xin[((size_t)(b * 512 + c * 4 + e)) * 1024 + d];
    else       v = xdec[((size_t)((b * 128 + c) * 4 + (e - 4))) * 1024 + d]
                   + pe[(e - 4) * 1024 + d];
    x[idx] = v;
}

__global__ void gather_k(const float* __restrict__ x, float* __restrict__ out)
{
    const int idx = blockIdx.x * blockDim.x + threadIdx.x;
    if (idx >= 256 * 4 * 1024) return;
    const int d = idx & 1023;
    const int t = idx >> 10;
    const int k = t & 3;
    const int g = t >> 2;
    const int c = g & 127;
    const int b = g >> 7;
    out[idx] = x[((size_t)(b * 1024 + c * 8 + 4 + k)) * 1024 + d];
}

// ---------------- launch ----------------
extern "C" void kernel_launch(void* const* d_in, const int* in_sizes, int n_in,
                              void* d_out, int out_size)
{
    const float* x_input     = (const float*)d_in[0];
    const int*   doc         = (const int*)d_in[1];
    const float* dec_w1      = (const float*)d_in[2];
    const float* dec_w2      = (const float*)d_in[3];
    const float* pos_emb     = (const float*)d_in[4];
    const float* Wqkv        = (const float*)d_in[5];
    const float* Wo          = (const float*)d_in[6];
    const float* Wup         = (const float*)d_in[7];
    const float* Wdown       = (const float*)d_in[8];
    const float* attn_norm_w = (const float*)d_in[9];
    const float* ffn_norm_w  = (const float*)d_in[10];

    float* S = nullptr;
    cudaGetSymbolAddress((void**)&S, g_scratch);
    float* x    = S + OFF_X;
    float* x1   = S + OFF_X1;
    float* qkv  = S + OFF_QKV;
    float* qr   = S + OFF_QR;
    float* ktb_ = S + OFF_KT;
    float* vr   = S + OFF_VR;
    float* hbp  = S + OFF_HB;     // packed hb (K=2048)
    float* tmp1 = S + OFF_TMP1;
    float* xdec = S + OFF_XDEC;
    float* apk  = S + OFF_APACK;
    float* w1p  = S + OFF_W1P;
    float* w2p  = S + OFF_W2P;
    float* qkvp = S + OFF_QKVP;
    float* wop  = S + OFF_WOP;
    float* upp  = S + OFF_UPP;
    float* dwnp = S + OFF_DWNP;
    float* cosT = S + OFF_COS;
    float* sinT = S + OFF_SIN;

    const dim3 blk(256);
    const int GEMM_SMEM = 12 * 512 * 16;   // 98304 (old kernel, 6 stages)
    const int BIG_SMEM  = 6 * 1536 * 16;   // 147456 (big kernel, 6 stages)
    cudaFuncSetAttribute(gemm_tc_k,  cudaFuncAttributeMaxDynamicSharedMemorySize, GEMM_SMEM);
    cudaFuncSetAttribute(gemm_big_k, cudaFuncAttributeMaxDynamicSharedMemorySize, BIG_SMEM);

    // one-time per launch: rope table + weight packs
    rope_table_k<<<128, 256>>>(cosT, sinT);
    pack_tf32_k<<<dim3(32, 2),  blk>>>(dec_w1, w1p, 1024, 0);
    pack_tf32_k<<<dim3(8, 8),   blk>>>(dec_w2, w2p, 256, 0);
    for (int li = 0; li < 4; li++) {
        pack_tf32_k<<<dim3(32, 24), blk>>>(Wqkv  + (size_t)li * 3145728, qkvp + (size_t)li * 3145728, 1024, 0);
        pack_tf32_k<<<dim3(32, 8),  blk>>>(Wo    + (size_t)li * 1048576, wop  + (size_t)li * 1048576, 1024, 0);
        pack_tf32_k<<<dim3(32, 32), blk>>>(Wup   + (size_t)li * 4194304, upp  + (size_t)li * 4194304, 1024, 1);
        pack_tf32_k<<<dim3(64, 8),  blk>>>(Wdown + (size_t)li * 2097152, dwnp + (size_t)li * 2097152, 2048, 0);
    }

    // decoder front-end
    pack_tf32_k<<<dim3(32, 8), blk>>>(x_input, apk, 1024, 0);
    gemm_tc_k<<<dim3(2, 8), blk, GEMM_SMEM>>>(apk, w1p, tmp1, nullptr, 256, 1024, 0);
    build_u_pack_k<<<(262144 + 255) / 256, 256>>>(tmp1, apk);
    gemm_tc_k<<<dim3(8, 8), blk, GEMM_SMEM>>>(apk, w2p, xdec, nullptr, 1024, 256, 0);
    assemble_k<<<(2097152 + 255) / 256, 256>>>(x_input, xdec, pos_emb, x);

    for (int li = 0; li < 4; li++) {
        rmsnorm_pack_k<<<2048, 256>>>(x, attn_norm_w + (size_t)li * 1024, apk);
        gemm_big_k<<<dim3(12, 16), blk, BIG_SMEM>>>(apk, qkvp + (size_t)li * 3145728, qkv, nullptr, 3072, 1024, 0);
        qkrope_k<<<dim3(16, 1024, 2), 64>>>(qkv, cosT, sinT, qr, ktb_, vr);
        attn_k<<<dim3(128, 16, 2), 256>>>(qr, ktb_, vr, doc, apk);
        gemm_tc_k<<<dim3(8, 16), blk, GEMM_SMEM>>>(apk, wop + (size_t)li * 1048576, x1, x, 1024, 1024, 0);
        rmsnorm_pack_k<<<2048, 256>>>(x1, ffn_norm_w + (size_t)li * 1024, apk);
        gemm_big_k<<<dim3(16, 16), blk, BIG_SMEM>>>(apk, upp + (size_t)li * 4194304, hbp, nullptr, 4096, 1024, 1);
        gemm_tc_k<<<dim3(8, 16), blk, GEMM_SMEM>>>(hbp, dwnp + (size_t)li * 2097152, x, x1, 1024, 2048, 0);
    }

    gather_k<<<(1048576 + 255) / 256, 256>>>(x, (float*)d_out);
}

// round 13
// speedup vs baseline: 3.9644x; 1.0323x over previous
#include <cuda_runtime.h>
#include <math.h>
#include <stdint.h>

// Shapes (fixed): B=2, C=128, M=4, K=4, V=64, D=1024, H=16, A=64, L=4, HF=2048,
// E=8, S=1024, rows=2048

// ---------------- scratch (no allocations allowed) ----------------
__device__ float g_scratch[81854464];

static const size_t OFF_X    = 0;
static const size_t OFF_X1   = 4194304;
static const size_t OFF_QKV  = 6291456;
static const size_t OFF_QR   = 12582912;
static const size_t OFF_KT   = 14680064;
static const size_t OFF_VR   = 16777216;
static const size_t OFF_HB   = 29360128;  // hb PACKED (16MB)
static const size_t OFF_TMP1 = 33554432;
static const size_t OFF_XDEC = 34078720;
// packed tf32 buffers
static const size_t OFF_APACK = 35127296;
static const size_t OFF_W1P   = 39321600;
static const size_t OFF_W2P   = 39583744;
static const size_t OFF_QKVP  = 39845888;
static const size_t OFF_WOP   = 52428800;
static const size_t OFF_UPP   = 56623104;
static const size_t OFF_DWNP  = 73400320;
static const size_t OFF_COS   = 81788928;
static const size_t OFF_SIN   = 81821696;

__device__ __forceinline__ uint32_t f2tf32(float x) {
    uint32_t r;
    asm("cvt.rna.tf32.f32 %0, %1;" : "=r"(r) : "f"(x));
    return r;
}

// Fragment-packed layout (per 128-row x 16-col region): 512 uint4 words.
// word slot = (kb*8 + mgi)*32 + g*4 + t, word = {X[r][c], X[r+8][c], X[r][c+4], X[r+8][c+4]}
__device__ __forceinline__ size_t pk_idx(int r, int c, int K)
{
    const int rblk = r >> 7, rm = r & 127;
    const int g = rm & 7, half = (rm >> 3) & 1, mgi = rm >> 4;
    const int kt16 = c >> 4, co = c & 15;
    const int kb = co >> 3, t = co & 3, ch = (co >> 2) & 1;
    const size_t widx = ((size_t)rblk * (K >> 4) + kt16) * 512
                      + (size_t)((kb * 8 + mgi) * 32 + g * 4 + t);
    return widx * 4 + (half + 2 * ch);
}

// dest swizzle for copier word w
__device__ __forceinline__ uint32_t wswz(uint32_t w) {
    return (w & ~3u) | ((w & 3u) ^ ((w >> 3) & 3u));
}

// ---------------- pack: row-major fp32 [R][K] -> tf32 fragment-packed --------
__global__ void __launch_bounds__(256) pack_tf32_k(
    const float* __restrict__ X, float* __restrict__ P, int K, int perm)
{
    const int tid  = threadIdx.x;
    const int rblk = blockIdx.y, ktb = blockIdx.x;
    const int g    = tid & 7;
    const int u32i = tid >> 3;
    const int kbb  = u32i >> 3;
    const int mgi  = u32i & 7;
    const int r0   = rblk * 128 + mgi * 16 + g;
    const int c0   = ktb * 32 + kbb * 8;

    int ra = r0, rb = r0 + 8;
    if (perm) {
        ra = (r0 & 1) ? 2048 + (r0 >> 1) : (r0 >> 1);
        rb = ((r0 + 8) & 1) ? 2048 + ((r0 + 8) >> 1) : ((r0 + 8) >> 1);
    }

    const float4 a0  = *(const float4*)(X + (size_t)ra * K + c0);
    const float4 a0h = *(const float4*)(X + (size_t)ra * K + c0 + 4);
    const float4 a1  = *(const float4*)(X + (size_t)rb * K + c0);
    const float4 a1h = *(const float4*)(X + (size_t)rb * K + c0 + 4);

    const int kt16 = ktb * 2 + (kbb >> 1);
    const int kb   = kbb & 1;
    uint4* dst = (uint4*)P + ((size_t)rblk * (K >> 4) + kt16) * 512
               + (kb * 8 + mgi) * 32 + g * 4;
    uint4 w;
    w.x = f2tf32(a0.x); w.y = f2tf32(a1.x); w.z = f2tf32(a0h.x); w.w = f2tf32(a1h.x); dst[0] = w;
    w.x = f2tf32(a0.y); w.y = f2tf32(a1.y); w.z = f2tf32(a0h.y); w.w = f2tf32(a1h.y); dst[1] = w;
    w.x = f2tf32(a0.z); w.y = f2tf32(a1.z); w.z = f2tf32(a0h.z); w.w = f2tf32(a1h.z); dst[2] = w;
    w.x = f2tf32(a0.w); w.y = f2tf32(a1.w); w.z = f2tf32(a0h.w); w.w = f2tf32(a1h.w); dst[3] = w;
}

// ---------------- TF32 GEMM, 128x128 tile (Wo/Wdown/front-end) --------------
__global__ void __launch_bounds__(256, 2) gemm_tc_k(
    const float* __restrict__ Ap, const float* __restrict__ Bp,
    float* __restrict__ C, const float* __restrict__ Radd,
    int N, int K, int mode)
{
    extern __shared__ uint4 dynsm[];
    uint4* smA = dynsm;              // [6][512]
    uint4* smB = dynsm + 6 * 512;    // [6][512]

    const int tid = threadIdx.x, lane = tid & 31, warp = tid >> 5;
    const int wm = warp >> 2, wn = warp & 3;
    const int g = lane >> 2, t = lane & 3;
    const int slotoff = g * 4 + (t ^ ((g >> 1) & 3));
    const int NT = K >> 4;

    const uint4* gA = (const uint4*)Ap + (size_t)blockIdx.y * NT * 512;
    const uint4* gB = (const uint4*)Bp + (size_t)blockIdx.x * NT * 512;

    const int  cq  = tid & 127;
    const int  cs  = (cq >> 1) & 3;
    const bool isB = tid >= 128;
    const uint4* gsrc = (isB ? gB : gA) + cq * 4;
    unsigned sAu = (unsigned)__cvta_generic_to_shared(smA);
    unsigned sBu = (unsigned)__cvta_generic_to_shared(smB);
    const unsigned dbase = (isB ? sBu : sAu) + cq * 64;

    float acc[4][4][4];
    #pragma unroll
    for (int mf = 0; mf < 4; mf++)
        #pragma unroll
        for (int nf = 0; nf < 4; nf++)
            #pragma unroll
            for (int i = 0; i < 4; i++) acc[mf][nf][i] = 0.f;

    #define ISSUE(KT, ST) do {                                              \
        const uint4* _s = gsrc + (size_t)(KT) * 512;                        \
        unsigned _d = dbase + (ST) * 8192;                                  \
        asm volatile("cp.async.cg.shared.global [%0], [%1], 16;" ::         \
            "r"(_d + ((0 ^ cs) << 4)), "l"(_s + 0));                        \
        asm volatile("cp.async.cg.shared.global [%0], [%1], 16;" ::         \
            "r"(_d + ((1 ^ cs) << 4)), "l"(_s + 1));                        \
        asm volatile("cp.async.cg.shared.global [%0], [%1], 16;" ::         \
            "r"(_d + ((2 ^ cs) << 4)), "l"(_s + 2));                        \
        asm volatile("cp.async.cg.shared.global [%0], [%1], 16;" ::         \
            "r"(_d + ((3 ^ cs) << 4)), "l"(_s + 3));                        \
    } while (0)

    #pragma unroll
    for (int p = 0; p < 5; p++) {
        if (p < NT) ISSUE(p, p);
        asm volatile("cp.async.commit_group;");
    }

    int st = 0;
    for (int kt = 0; kt < NT; kt++) {
        asm volatile("cp.async.wait_group 4;");
        __syncthreads();
        const uint4* sa = smA + st * 512;
        const uint4* sb = smB + st * 512;
        #pragma unroll
        for (int kb = 0; kb < 2; kb++) {
            uint4 wa[4];
            #pragma unroll
            for (int mf = 0; mf < 4; mf++)
                wa[mf] = sa[(kb * 8 + wm * 4 + mf) * 32 + slotoff];
            const uint4 wb0 = sb[(kb * 8 + wn * 2 + 0) * 32 + slotoff];
            const uint4 wb1 = sb[(kb * 8 + wn * 2 + 1) * 32 + slotoff];
            const uint32_t bf[4][2] = {
                {wb0.x, wb0.z}, {wb0.y, wb0.w}, {wb1.x, wb1.z}, {wb1.y, wb1.w}};
            #pragma unroll
            for (int mf = 0; mf < 4; mf++)
                #pragma unroll
                for (int nf = 0; nf < 4; nf++) {
                    asm volatile(
                        "mma.sync.aligned.m16n8k8.row.col.f32.tf32.tf32.f32 "
                        "{%0,%1,%2,%3}, {%4,%5,%6,%7}, {%8,%9}, {%0,%1,%2,%3};\n"
                        : "+f"(acc[mf][nf][0]), "+f"(acc[mf][nf][1]),
                          "+f"(acc[mf][nf][2]), "+f"(acc[mf][nf][3])
                        : "r"(wa[mf].x), "r"(wa[mf].y), "r"(wa[mf].z), "r"(wa[mf].w),
                          "r"(bf[nf][0]), "r"(bf[nf][1]));
                }
        }
        const int ktn = kt + 5;
        if (ktn < NT) { int stn = st + 5; if (stn >= 6) stn -= 6; ISSUE(ktn, stn); }
        asm volatile("cp.async.commit_group;");
        st++; if (st == 6) st = 0;
    }
    #undef ISSUE

    const int m0 = blockIdx.y * 128;
    const int n0 = blockIdx.x * 128;
    if (mode == 1) {
        uint32_t* Cp = (uint32_t*)C;
        #pragma unroll
        for (int mf = 0; mf < 4; mf++) {
            const int r0 = m0 + wm * 64 + mf * 16 + g;
            #pragma unroll
            for (int nf = 0; nf < 4; nf++) {
                const int hcol = ((n0 + wn * 32 + nf * 8) >> 1) + t;
                const float a0 = acc[mf][nf][0], b0 = acc[mf][nf][1];
                const float a1 = acc[mf][nf][2], b1 = acc[mf][nf][3];
                const float h0 = (a0 / (1.f + expf(-a0))) * b0;
                const float h1 = (a1 / (1.f + expf(-a1))) * b1;
                Cp[pk_idx(r0,     hcol, 2048)] = f2tf32(h0);
                Cp[pk_idx(r0 + 8, hcol, 2048)] = f2tf32(h1);
            }
        }
    } else {
        #pragma unroll
        for (int mf = 0; mf < 4; mf++) {
            const int r0 = m0 + wm * 64 + mf * 16 + g;
            #pragma unroll
            for (int nf = 0; nf < 4; nf++) {
                const int col = n0 + wn * 32 + nf * 8 + 2 * t;
                float2 v0 = make_float2(acc[mf][nf][0], acc[mf][nf][1]);
                float2 v1 = make_float2(acc[mf][nf][2], acc[mf][nf][3]);
                if (Radd) {
                    float2 r0v = *(const float2*)&Radd[(size_t)r0 * N + col];
                    float2 r1v = *(const float2*)&Radd[(size_t)(r0 + 8) * N + col];
                    v0.x += r0v.x; v0.y += r0v.y;
                    v1.x += r1v.x; v1.y += r1v.y;
                }
                *(float2*)&C[(size_t)r0 * N + col]       = v0;
                *(float2*)&C[(size_t)(r0 + 8) * N + col] = v1;
            }
        }
    }
}

// ---------------- TF32 GEMM, 128x256 tile, 64x64 warp tile (QKV/Wup) --------
__global__ void __launch_bounds__(256, 1) gemm_big_k(
    const float* __restrict__ Ap, const float* __restrict__ Bp,
    float* __restrict__ C, const float* __restrict__ Radd,
    int N, int K, int mode)
{
    extern __shared__ uint4 dynsm[];   // [6][1536]: A 512 + B 1024 words/stage
    const int tid = threadIdx.x, lane = tid & 31, warp = tid >> 5;
    const int wm = warp >> 2, wn = warp & 3;
    const int g = lane >> 2, t = lane & 3;
    const int slotoff = g * 4 + (t ^ ((g >> 1) & 3));
    const int NT = K >> 4;

    const uint4* gA  = (const uint4*)Ap + (size_t)blockIdx.y * NT * 512;
    const uint4* gB0 = (const uint4*)Bp + (size_t)(2 * blockIdx.x) * NT * 512;
    const uint4* gB1 = (const uint4*)Bp + (size_t)(2 * blockIdx.x + 1) * NT * 512;

    const unsigned sbase = (unsigned)__cvta_generic_to_shared(dynsm);
    const unsigned dA0 = wswz(tid) * 16,        dA1 = wswz(tid + 256) * 16;
    const unsigned dB0 = wswz(tid) * 16,        dB1 = wswz(tid + 256) * 16;
    const unsigned dB2 = wswz(tid + 512) * 16,  dB3 = wswz(tid + 768) * 16;

    float acc[4][8][4];
    #pragma unroll
    for (int mf = 0; mf < 4; mf++)
        #pragma unroll
        for (int nf = 0; nf < 8; nf++)
            #pragma unroll
            for (int i = 0; i < 4; i++) acc[mf][nf][i] = 0.f;

    #define ISSUEB(KT, ST) do {                                             \
        const unsigned _b = sbase + (ST) * 24576;                           \
        const uint4* _a = gA  + (size_t)(KT) * 512;                         \
        const uint4* _p = gB0 + (size_t)(KT) * 512;                         \
        const uint4* _q = gB1 + (size_t)(KT) * 512;                         \
        asm volatile("cp.async.cg.shared.global [%0], [%1], 16;" ::         \
            "r"(_b + dA0), "l"(_a + tid));                                  \
        asm volatile("cp.async.cg.shared.global [%0], [%1], 16;" ::         \
            "r"(_b + dA1), "l"(_a + tid + 256));                            \
        asm volatile("cp.async.cg.shared.global [%0], [%1], 16;" ::         \
            "r"(_b + 8192 + dB0), "l"(_p + tid));                           \
        asm volatile("cp.async.cg.shared.global [%0], [%1], 16;" ::         \
            "r"(_b + 8192 + dB1), "l"(_p + tid + 256));                     \
        asm volatile("cp.async.cg.shared.global [%0], [%1], 16;" ::         \
            "r"(_b + 8192 + dB2), "l"(_q + tid));                           \
        asm volatile("cp.async.cg.shared.global [%0], [%1], 16;" ::         \
            "r"(_b + 8192 + dB3), "l"(_q + tid + 256));                     \
    } while (0)

    #pragma unroll
    for (int p = 0; p < 5; p++) {
        if (p < NT) ISSUEB(p, p);
        asm volatile("cp.async.commit_group;");
    }

    int st = 0;
    for (int kt = 0; kt < NT; kt++) {
        asm volatile("cp.async.wait_group 4;");
        __syncthreads();
        const uint4* sa = dynsm + st * 1536;
        const uint4* sb = sa + 512;
        #pragma unroll
        for (int kb = 0; kb < 2; kb++) {
            uint4 wa[4];
            #pragma unroll
            for (int mf = 0; mf < 4; mf++)
                wa[mf] = sa[(kb * 8 + wm * 4 + mf) * 32 + slotoff];
            uint4 wb[4];
            #pragma unroll
            for (int j = 0; j < 4; j++) {
                const int ng = wn * 4 + j;
                wb[j] = sb[((ng >> 3) << 9) + (kb * 8 + (ng & 7)) * 32 + slotoff];
            }
            #pragma unroll
            for (int mf = 0; mf < 4; mf++)
                #pragma unroll
                for (int j = 0; j < 4; j++) {
                    asm volatile(
                        "mma.sync.aligned.m16n8k8.row.col.f32.tf32.tf32.f32 "
                        "{%0,%1,%2,%3}, {%4,%5,%6,%7}, {%8,%9}, {%0,%1,%2,%3};\n"
                        : "+f"(acc[mf][2*j][0]), "+f"(acc[mf][2*j][1]),
                          "+f"(acc[mf][2*j][2]), "+f"(acc[mf][2*j][3])
                        : "r"(wa[mf].x), "r"(wa[mf].y), "r"(wa[mf].z), "r"(wa[mf].w),
                          "r"(wb[j].x), "r"(wb[j].z));
                    asm volatile(
                        "mma.sync.aligned.m16n8k8.row.col.f32.tf32.tf32.f32 "
                        "{%0,%1,%2,%3}, {%4,%5,%6,%7}, {%8,%9}, {%0,%1,%2,%3};\n"
                        : "+f"(acc[mf][2*j+1][0]), "+f"(acc[mf][2*j+1][1]),
                          "+f"(acc[mf][2*j+1][2]), "+f"(acc[mf][2*j+1][3])
                        : "r"(wa[mf].x), "r"(wa[mf].y), "r"(wa[mf].z), "r"(wa[mf].w),
                          "r"(wb[j].y), "r"(wb[j].w));
                }
        }
        const int ktn = kt + 5;
        if (ktn < NT) { int stn = st + 5; if (stn >= 6) stn -= 6; ISSUEB(ktn, stn); }
        asm volatile("cp.async.commit_group;");
        st++; if (st == 6) st = 0;
    }
    #undef ISSUEB

    const int m0 = blockIdx.y * 128;
    const int n0 = blockIdx.x * 256;
    if (mode == 1) {
        uint32_t* Cp = (uint32_t*)C;
        #pragma unroll
        for (int mf = 0; mf < 4; mf++) {
            const int r0 = m0 + wm * 64 + mf * 16 + g;
            #pragma unroll
            for (int nf = 0; nf < 8; nf++) {
                const int hcol = ((n0 + wn * 64 + nf * 8) >> 1) + t;
                const float a0 = acc[mf][nf][0], b0 = acc[mf][nf][1];
                const float a1 = acc[mf][nf][2], b1 = acc[mf][nf][3];
                const float h0 = (a0 / (1.f + expf(-a0))) * b0;
                const float h1 = (a1 / (1.f + expf(-a1))) * b1;
                Cp[pk_idx(r0,     hcol, 2048)] = f2tf32(h0);
                Cp[pk_idx(r0 + 8, hcol, 2048)] = f2tf32(h1);
            }
        }
    } else {
        #pragma unroll
        for (int mf = 0; mf < 4; mf++) {
            const int r0 = m0 + wm * 64 + mf * 16 + g;
            #pragma unroll
            for (int nf = 0; nf < 8; nf++) {
                const int col = n0 + wn * 64 + nf * 8 + 2 * t;
                float2 v0 = make_float2(acc[mf][nf][0], acc[mf][nf][1]);
                float2 v1 = make_float2(acc[mf][nf][2], acc[mf][nf][3]);
                if (Radd) {
                    float2 r0v = *(const float2*)&Radd[(size_t)r0 * N + col];
                    float2 r1v = *(const float2*)&Radd[(size_t)(r0 + 8) * N + col];
                    v0.x += r0v.x; v0.y += r0v.y;
                    v1.x += r1v.x; v1.y += r1v.y;
                }
                *(float2*)&C[(size_t)r0 * N + col]       = v0;
                *(float2*)&C[(size_t)(r0 + 8) * N + col] = v1;
            }
        }
    }
}

// ---------------- RoPE table (once per launch) ----------------
__global__ void rope_table_k(float* __restrict__ ct, float* __restrict__ st_)
{
    const int idx = blockIdx.x * 256 + threadIdx.x;
    if (idx >= 32768) return;
    const int s = idx >> 5, i = idx & 31;
    const double ang = (double)s * pow(10000.0, -(double)i / 32.0);
    ct[idx]  = (float)cos(ang);
    st_[idx] = (float)sin(ang);
}

// ---------------- RMSNorm + pack (one block per row, D=1024) ----------------
__global__ void __launch_bounds__(256) rmsnorm_pack_k(
    const float* __restrict__ x, const float* __restrict__ w, float* __restrict__ P)
{
    const int row = blockIdx.x;
    const float* xr = x + (size_t)row * 1024;
    float s = 0.f;
    for (int i = threadIdx.x; i < 1024; i += 256) { float v = xr[i]; s += v * v; }
    #pragma unroll
    for (int o = 16; o; o >>= 1) s += __shfl_xor_sync(0xffffffffu, s, o);
    __shared__ float red[8];
    const int warp = threadIdx.x >> 5, lane = threadIdx.x & 31;
    if (lane == 0) red[warp] = s;
    __syncthreads();
    float tot = 0.f;
    #pragma unroll
    for (int i = 0; i < 8; i++) tot += red[i];
    const float inv = rsqrtf(tot * (1.f / 1024.f) + 1e-5f);
    const int c4 = threadIdx.x * 4;
    const float4 v = *(const float4*)(xr + c4);
    const float4 wv = *(const float4*)(w + c4);
    uint32_t* Pp = (uint32_t*)P;
    Pp[pk_idx(row, c4 + 0, 1024)] = f2tf32(v.x * inv * wv.x);
    Pp[pk_idx(row, c4 + 1, 1024)] = f2tf32(v.y * inv * wv.y);
    Pp[pk_idx(row, c4 + 2, 1024)] = f2tf32(v.z * inv * wv.z);
    Pp[pk_idx(row, c4 + 3, 1024)] = f2tf32(v.w * inv * wv.w);
}

// ---------------- l2norm + RoPE + layout shuffle ----------------
__global__ void __launch_bounds__(64) qkrope_k(
    const float* __restrict__ qkv, const float* __restrict__ cosT,
    const float* __restrict__ sinT, float* __restrict__ qr,
    float* __restrict__ kt, float* __restrict__ vr)
{
    const int h = blockIdx.x, s = blockIdx.y, b = blockIdx.z;
    const int a = threadIdx.x;
    const float* base = qkv + ((size_t)b * 1024 + s) * 3072 + h * 64 + a;
    float q = base[0];
    float k = base[1024];
    float v = base[2048];

    float sq = q * q, sk = k * k;
    #pragma unroll
    for (int o = 16; o; o >>= 1) {
        sq += __shfl_xor_sync(0xffffffffu, sq, o);
        sk += __shfl_xor_sync(0xffffffffu, sk, o);
    }
    __shared__ float red[4];
    __shared__ float sqv[64], skv[64];
    const int warp = a >> 5;
    if ((a & 31) == 0) { red[warp * 2] = sq; red[warp * 2 + 1] = sk; }
    __syncthreads();
    const float nq = sqrtf(red[0] + red[2]);
    const float nk = sqrtf(red[1] + red[3]);
    q = q / fmaxf(nq, 1e-5f);
    k = k / fmaxf(nk, 1e-5f);
    sqv[a] = q; skv[a] = k;
    __syncthreads();

    const int i = a & 31;
    const float cz = cosT[s * 32 + i];
    const float sz = sinT[s * 32 + i];
    const float qp = sqv[a ^ 32], kp = skv[a ^ 32];
    const float qo = (a < 32) ? (q * cz + qp * sz) : (q * cz - qp * sz);
    const float ko = (a < 32) ? (k * cz + kp * sz) : (k * cz - kp * sz);

    const size_t bh = (size_t)b * 16 + h;
    qr[(bh * 1024 + s) * 64 + a] = qo;
    kt[(bh * 64 + a) * 1024 + s] = ko;       // K transposed: (b,h,a,s)
    vr[(bh * 1024 + s) * 64 + a] = v;
}

// ---------------- attention with compact key list; PACKED output ------------
__global__ void __launch_bounds__(256) attn_k(
    const float* __restrict__ qr, const float* __restrict__ kt,
    const float* __restrict__ vr, const int* __restrict__ doc,
    float* __restrict__ attnP)
{
    const int qt = blockIdx.x, h = blockIdx.y, b = blockIdx.z;
    const int q0 = qt * 8;
    __shared__ float sQ[8][64];
    __shared__ float sS[8][520];
    __shared__ float sRed[4][8][64];
    __shared__ int   sDoc[128];
    __shared__ int   mbArr[128];
    __shared__ int   warpCnt[4];
    const int tid = threadIdx.x;
    if (tid < 128) sDoc[tid] = doc[b * 128 + tid];
    const size_t bh = (size_t)b * 16 + h;
    for (int i = tid; i < 8 * 64; i += 256) {
        int q = i >> 6, a = i & 63;
        sQ[q][a] = qr[(bh * 1024 + q0 + q) * 64 + a];
    }
    __syncthreads();

    const int dq = sDoc[qt];
    int flag = 0, pre = 0;
    if (tid < 128) {
        flag = (tid < qt && sDoc[tid] == dq) ? 1 : 0;
        unsigned bal = __ballot_sync(0xffffffffu, flag);
        const int l = tid & 31;
        pre = __popc(bal & ((1u << l) - 1u));
        if (l == 31) warpCnt[tid >> 5] = pre + flag;
    }
    __syncthreads();
    int nc = warpCnt[0] + warpCnt[1] + warpCnt[2] + warpCnt[3];
    if (tid < 128 && flag) {
        const int w = tid >> 5;
        int base = 0;
        for (int i = 0; i < w; i++) base += warpCnt[i];
        mbArr[base + pre] = tid;
    }
    __syncthreads();
    const int nk = nc * 4 + 8;

    const float* ktp = kt + bh * 64 * 1024;
    for (int s = tid; s < nk; s += 256) {
        const int key = (s < nc * 4) ? (mbArr[s >> 2] * 8 + (s & 3))
                                     : (q0 + s - nc * 4);
        float acc[8];
        #pragma unroll
        for (int q = 0; q < 8; q++) acc[q] = 0.f;
        #pragma unroll 8
        for (int a = 0; a < 64; a++) {
            const float kv = ktp[a * 1024 + key];
            #pragma unroll
            for (int q = 0; q < 8; q++) acc[q] += sQ[q][a] * kv;
        }
        #pragma unroll
        for (int q = 0; q < 8; q++) sS[q][s] = acc[q] * 0.125f;
    }
    __syncthreads();

    {
        const int q = tid >> 5, lane = tid & 31;
        float mx = -3.4e38f;
        for (int s = lane; s < nk; s += 32) mx = fmaxf(mx, sS[q][s]);
        #pragma unroll
        for (int o = 16; o; o >>= 1) mx = fmaxf(mx, __shfl_xor_sync(0xffffffffu, mx, o));
        float sum = 0.f;
        for (int s = lane; s < nk; s += 32) {
            const float e = expf(sS[q][s] - mx);
            sS[q][s] = e;
            sum += e;
        }
        #pragma unroll
        for (int o = 16; o; o >>= 1) sum += __shfl_xor_sync(0xffffffffu, sum, o);
        const float inv = 1.f / sum;
        for (int s = lane; s < nk; s += 32) sS[q][s] *= inv;
    }
    __syncthreads();

    const float* vp = vr + bh * 1024 * 64;
    const int a = tid & 63, chunk = tid >> 6;
    const int csz = (nk + 3) >> 2;
    const int jlo = chunk * csz;
    const int jhi = min(nk, jlo + csz);
    float acc[8];
    #pragma unroll
    for (int q = 0; q < 8; q++) acc[q] = 0.f;
    for (int j = jlo; j < jhi; j++) {
        const int key = (j < nc * 4) ? (mbArr[j >> 2] * 8 + (j & 3))
                                     : (q0 + j - nc * 4);
        const float v = vp[(size_t)key * 64 + a];
        #pragma unroll
        for (int q = 0; q < 8; q++) acc[q] += sS[q][j] * v;
    }
    #pragma unroll
    for (int q = 0; q < 8; q++) sRed[chunk][q][a] = acc[q];
    __syncthreads();
    uint32_t* Pp = (uint32_t*)attnP;
    for (int i = tid; i < 8 * 64; i += 256) {
        const int q = i >> 6, a2 = i & 63;
        const float o = sRed[0][q][a2] + sRed[1][q][a2] + sRed[2][q][a2] + sRed[3][q][a2];
        Pp[pk_idx(b * 1024 + q0 + q, h * 64 + a2, 1024)] = f2tf32(o);
    }
}

// ---------------- small elementwise kernels ----------------
__global__ void build_u_pack_k(const float* __restrict__ t1, float* __restrict__ P)
{
    const int idx = blockIdx.x * blockDim.x + threadIdx.x;
    if (idx >= 1024 * 256) return;
    const int col = idx & 255;
    const int ru  = idx >> 8;
    const int m = col >> 6, v = col & 63;
    const int k = ru & 3, bc = ru >> 2;
    const float val = t1[((size_t)bc * 4 + m) * 256 + k * 64 + v];
    ((uint32_t*)P)[pk_idx(ru, col, 256)] = f2tf32(val);
}

__global__ void assemble_k(const float* __restrict__ xin, const float* __restrict__ xdec,
                           const float* __restrict__ pe, float* __restrict__ x)
{
    const int idx = blockIdx.x * blockDim.x + threadIdx.x;
    if (idx >= 2 * 1024 * 1024) return;
    const int d  = idx & 1023;
    const int sb = idx >> 10;
    const int s_ = sb & 1023;
    const int b  = sb >> 10;
    const int c  = s_ >> 3, e = s_ & 7;
    float v;
    if (e < 4) v = xin[((size_t)(b * 512 + c * 4 + e)) * 1024 + d];
    else       v = xdec[((size_t)((b * 128 + c) * 4 + (e - 4))) * 1024 + d]
                   + pe[(e - 4) * 1024 + d];
    x[idx] = v;
}

__global__ void gather_k(const float* __restrict__ x, float* __restrict__ out)
{
    const int idx = blockIdx.x * blockDim.x + threadIdx.x;
    if (idx >= 256 * 4 * 1024) return;
    const int d = idx & 1023;
    const int t = idx >> 10;
    const int k = t & 3;
    const int g = t >> 2;
    const int c = g & 127;
    const int b = g >> 7;
    out[idx] = x[((size_t)(b * 1024 + c * 8 + 4 + k)) * 1024 + d];
}

// ---------------- launch ----------------
extern "C" void kernel_launch(void* const* d_in, const int* in_sizes, int n_in,
                              void* d_out, int out_size)
{
    const float* x_input     = (const float*)d_in[0];
    const int*   doc         = (const int*)d_in[1];
    const float* dec_w1      = (const float*)d_in[2];
    const float* dec_w2      = (const float*)d_in[3];
    const float* pos_emb     = (const float*)d_in[4];
    const float* Wqkv        = (const float*)d_in[5];
    const float* Wo          = (const float*)d_in[6];
    const float* Wup         = (const float*)d_in[7];
    const float* Wdown       = (const float*)d_in[8];
    const float* attn_norm_w = (const float*)d_in[9];
    const float* ffn_norm_w  = (const float*)d_in[10];

    float* S = nullptr;
    cudaGetSymbolAddress((void**)&S, g_scratch);
    float* x    = S + OFF_X;
    float* x1   = S + OFF_X1;
    float* qkv  = S + OFF_QKV;
    float* qr   = S + OFF_QR;
    float* ktb_ = S + OFF_KT;
    float* vr   = S + OFF_VR;
    float* hbp  = S + OFF_HB;
    float* tmp1 = S + OFF_TMP1;
    float* xdec = S + OFF_XDEC;
    float* apk  = S + OFF_APACK;
    float* w1p  = S + OFF_W1P;
    float* w2p  = S + OFF_W2P;
    float* qkvp = S + OFF_QKVP;
    float* wop  = S + OFF_WOP;
    float* upp  = S + OFF_UPP;
    float* dwnp = S + OFF_DWNP;
    float* cosT = S + OFF_COS;
    float* sinT = S + OFF_SIN;

    // host-side resources, created once (uncaptured correctness call)
    static cudaStream_t s2 = nullptr;
    static cudaEvent_t evFork = nullptr;
    static cudaEvent_t evPack[4];
    static cudaEvent_t evRope = nullptr;
    if (!s2) {
        cudaStreamCreateWithFlags(&s2, cudaStreamNonBlocking);
        cudaEventCreateWithFlags(&evFork, cudaEventDisableTiming);
        cudaEventCreateWithFlags(&evRope, cudaEventDisableTiming);
        for (int i = 0; i < 4; i++)
            cudaEventCreateWithFlags(&evPack[i], cudaEventDisableTiming);
    }

    const dim3 blk(256);
    const int GEMM_SMEM = 12 * 512 * 16;   // 98304
    const int BIG_SMEM  = 6 * 1536 * 16;   // 147456
    cudaFuncSetAttribute(gemm_tc_k,  cudaFuncAttributeMaxDynamicSharedMemorySize, GEMM_SMEM);
    cudaFuncSetAttribute(gemm_big_k, cudaFuncAttributeMaxDynamicSharedMemorySize, BIG_SMEM);

    // fork side stream from the capturing stream
    cudaEventRecord(evFork, 0);
    cudaStreamWaitEvent(s2, evFork, 0);

    // side stream: rope table + all per-layer weight packs (independent branch)
    rope_table_k<<<128, 256, 0, s2>>>(cosT, sinT);
    cudaEventRecord(evRope, s2);
    for (int li = 0; li < 4; li++) {
        pack_tf32_k<<<dim3(32, 24), blk, 0, s2>>>(Wqkv  + (size_t)li * 3145728, qkvp + (size_t)li * 3145728, 1024, 0);
        pack_tf32_k<<<dim3(32, 8),  blk, 0, s2>>>(Wo    + (size_t)li * 1048576, wop  + (size_t)li * 1048576, 1024, 0);
        pack_tf32_k<<<dim3(32, 32), blk, 0, s2>>>(Wup   + (size_t)li * 4194304, upp  + (size_t)li * 4194304, 1024, 1);
        pack_tf32_k<<<dim3(64, 8),  blk, 0, s2>>>(Wdown + (size_t)li * 2097152, dwnp + (size_t)li * 2097152, 2048, 0);
        cudaEventRecord(evPack[li], s2);
    }

    // main stream: front-end (W1/W2 packed here — needed immediately)
    pack_tf32_k<<<dim3(32, 2),  blk>>>(dec_w1, w1p, 1024, 0);
    pack_tf32_k<<<dim3(8, 8),   blk>>>(dec_w2, w2p, 256, 0);
    pack_tf32_k<<<dim3(32, 8), blk>>>(x_input, apk, 1024, 0);
    gemm_tc_k<<<dim3(2, 8), blk, GEMM_SMEM>>>(apk, w1p, tmp1, nullptr, 256, 1024, 0);
    build_u_pack_k<<<(262144 + 255) / 256, 256>>>(tmp1, apk);
    gemm_tc_k<<<dim3(8, 8), blk, GEMM_SMEM>>>(apk, w2p, xdec, nullptr, 1024, 256, 0);
    assemble_k<<<(2097152 + 255) / 256, 256>>>(x_input, xdec, pos_emb, x);

    for (int li = 0; li < 4; li++) {
        rmsnorm_pack_k<<<2048, 256>>>(x, attn_norm_w + (size_t)li * 1024, apk);
        cudaStreamWaitEvent(0, evPack[li], 0);   // layer-li weights packed
        if (li == 0) cudaStreamWaitEvent(0, evRope, 0);
        gemm_big_k<<<dim3(12, 16), blk, BIG_SMEM>>>(apk, qkvp + (size_t)li * 3145728, qkv, nullptr, 3072, 1024, 0);
        qkrope_k<<<dim3(16, 1024, 2), 64>>>(qkv, cosT, sinT, qr, ktb_, vr);
        attn_k<<<dim3(128, 16, 2), 256>>>(qr, ktb_, vr, doc, apk);
        gemm_tc_k<<<dim3(8, 16), blk, GEMM_SMEM>>>(apk, wop + (size_t)li * 1048576, x1, x, 1024, 1024, 0);
        rmsnorm_pack_k<<<2048, 256>>>(x1, ffn_norm_w + (size_t)li * 1024, apk);
        gemm_big_k<<<dim3(16, 16), blk, BIG_SMEM>>>(apk, upp + (size_t)li * 4194304, hbp, nullptr, 4096, 1024, 1);
        gemm_tc_k<<<dim3(8, 16), blk, GEMM_SMEM>>>(hbp, dwnp + (size_t)li * 2097152, x, x1, 1024, 2048, 0);
    }

    gather_k<<<(1048576 + 255) / 256, 256>>>(x, (float*)d_out);
}

// round 14
// speedup vs baseline: 4.0832x; 1.0300x over previous
#include <cuda_runtime.h>
#include <math.h>
#include <stdint.h>

// Shapes (fixed): B=2, C=128, M=4, K=4, V=64, D=1024, H=16, A=64, L=4, HF=2048,
// E=8, S=1024, rows=2048

// ---------------- scratch (no allocations allowed) ----------------
__device__ float g_scratch[81854464];

static const size_t OFF_X    = 0;
static const size_t OFF_X1   = 4194304;
static const size_t OFF_QR   = 12582912;
static const size_t OFF_KT   = 14680064;
static const size_t OFF_VR   = 16777216;
static const size_t OFF_HB   = 29360128;  // hb PACKED (16MB)
static const size_t OFF_TMP1 = 33554432;
static const size_t OFF_XDEC = 34078720;
// packed tf32 buffers
static const size_t OFF_APACK = 35127296;
static const size_t OFF_W1P   = 39321600;
static const size_t OFF_W2P   = 39583744;
static const size_t OFF_QKVP  = 39845888;
static const size_t OFF_WOP   = 52428800;
static const size_t OFF_UPP   = 56623104;
static const size_t OFF_DWNP  = 73400320;
static const size_t OFF_COS   = 81788928;
static const size_t OFF_SIN   = 81821696;

__device__ __forceinline__ uint32_t f2tf32(float x) {
    uint32_t r;
    asm("cvt.rna.tf32.f32 %0, %1;" : "=r"(r) : "f"(x));
    return r;
}

// Fragment-packed layout (per 128-row x 16-col region): 512 uint4 words.
__device__ __forceinline__ size_t pk_idx(int r, int c, int K)
{
    const int rblk = r >> 7, rm = r & 127;
    const int g = rm & 7, half = (rm >> 3) & 1, mgi = rm >> 4;
    const int kt16 = c >> 4, co = c & 15;
    const int kb = co >> 3, t = co & 3, ch = (co >> 2) & 1;
    const size_t widx = ((size_t)rblk * (K >> 4) + kt16) * 512
                      + (size_t)((kb * 8 + mgi) * 32 + g * 4 + t);
    return widx * 4 + (half + 2 * ch);
}

__device__ __forceinline__ uint32_t wswz(uint32_t w) {
    return (w & ~3u) | ((w & 3u) ^ ((w >> 3) & 3u));
}

// ---------------- pack: row-major fp32 [R][K] -> tf32 fragment-packed --------
__global__ void __launch_bounds__(256) pack_tf32_k(
    const float* __restrict__ X, float* __restrict__ P, int K, int perm)
{
    const int tid  = threadIdx.x;
    const int rblk = blockIdx.y, ktb = blockIdx.x;
    const int g    = tid & 7;
    const int u32i = tid >> 3;
    const int kbb  = u32i >> 3;
    const int mgi  = u32i & 7;
    const int r0   = rblk * 128 + mgi * 16 + g;
    const int c0   = ktb * 32 + kbb * 8;

    int ra = r0, rb = r0 + 8;
    if (perm) {
        ra = (r0 & 1) ? 2048 + (r0 >> 1) : (r0 >> 1);
        rb = ((r0 + 8) & 1) ? 2048 + ((r0 + 8) >> 1) : ((r0 + 8) >> 1);
    }

    const float4 a0  = *(const float4*)(X + (size_t)ra * K + c0);
    const float4 a0h = *(const float4*)(X + (size_t)ra * K + c0 + 4);
    const float4 a1  = *(const float4*)(X + (size_t)rb * K + c0);
    const float4 a1h = *(const float4*)(X + (size_t)rb * K + c0 + 4);

    const int kt16 = ktb * 2 + (kbb >> 1);
    const int kb   = kbb & 1;
    uint4* dst = (uint4*)P + ((size_t)rblk * (K >> 4) + kt16) * 512
               + (kb * 8 + mgi) * 32 + g * 4;
    uint4 w;
    w.x = f2tf32(a0.x); w.y = f2tf32(a1.x); w.z = f2tf32(a0h.x); w.w = f2tf32(a1h.x); dst[0] = w;
    w.x = f2tf32(a0.y); w.y = f2tf32(a1.y); w.z = f2tf32(a0h.y); w.w = f2tf32(a1h.y); dst[1] = w;
    w.x = f2tf32(a0.z); w.y = f2tf32(a1.z); w.z = f2tf32(a0h.z); w.w = f2tf32(a1h.z); dst[2] = w;
    w.x = f2tf32(a0.w); w.y = f2tf32(a1.w); w.z = f2tf32(a0h.w); w.w = f2tf32(a1h.w); dst[3] = w;
}

// ---------------- TF32 GEMM, 128x128 tile (Wo/Wdown/front-end) --------------
__global__ void __launch_bounds__(256, 2) gemm_tc_k(
    const float* __restrict__ Ap, const float* __restrict__ Bp,
    float* __restrict__ C, const float* __restrict__ Radd,
    int N, int K, int mode)
{
    extern __shared__ uint4 dynsm[];
    uint4* smA = dynsm;              // [6][512]
    uint4* smB = dynsm + 6 * 512;    // [6][512]

    const int tid = threadIdx.x, lane = tid & 31, warp = tid >> 5;
    const int wm = warp >> 2, wn = warp & 3;
    const int g = lane >> 2, t = lane & 3;
    const int slotoff = g * 4 + (t ^ ((g >> 1) & 3));
    const int NT = K >> 4;

    const uint4* gA = (const uint4*)Ap + (size_t)blockIdx.y * NT * 512;
    const uint4* gB = (const uint4*)Bp + (size_t)blockIdx.x * NT * 512;

    const int  cq  = tid & 127;
    const int  cs  = (cq >> 1) & 3;
    const bool isB = tid >= 128;
    const uint4* gsrc = (isB ? gB : gA) + cq * 4;
    unsigned sAu = (unsigned)__cvta_generic_to_shared(smA);
    unsigned sBu = (unsigned)__cvta_generic_to_shared(smB);
    const unsigned dbase = (isB ? sBu : sAu) + cq * 64;

    float acc[4][4][4];
    #pragma unroll
    for (int mf = 0; mf < 4; mf++)
        #pragma unroll
        for (int nf = 0; nf < 4; nf++)
            #pragma unroll
            for (int i = 0; i < 4; i++) acc[mf][nf][i] = 0.f;

    #define ISSUE(KT, ST) do {                                              \
        const uint4* _s = gsrc + (size_t)(KT) * 512;                        \
        unsigned _d = dbase + (ST) * 8192;                                  \
        asm volatile("cp.async.cg.shared.global [%0], [%1], 16;" ::         \
            "r"(_d + ((0 ^ cs) << 4)), "l"(_s + 0));                        \
        asm volatile("cp.async.cg.shared.global [%0], [%1], 16;" ::         \
            "r"(_d + ((1 ^ cs) << 4)), "l"(_s + 1));                        \
        asm volatile("cp.async.cg.shared.global [%0], [%1], 16;" ::         \
            "r"(_d + ((2 ^ cs) << 4)), "l"(_s + 2));                        \
        asm volatile("cp.async.cg.shared.global [%0], [%1], 16;" ::         \
            "r"(_d + ((3 ^ cs) << 4)), "l"(_s + 3));                        \
    } while (0)

    #pragma unroll
    for (int p = 0; p < 5; p++) {
        if (p < NT) ISSUE(p, p);
        asm volatile("cp.async.commit_group;");
    }

    int st = 0;
    for (int kt = 0; kt < NT; kt++) {
        asm volatile("cp.async.wait_group 4;");
        __syncthreads();
        const uint4* sa = smA + st * 512;
        const uint4* sb = smB + st * 512;
        #pragma unroll
        for (int kb = 0; kb < 2; kb++) {
            uint4 wa[4];
            #pragma unroll
            for (int mf = 0; mf < 4; mf++)
                wa[mf] = sa[(kb * 8 + wm * 4 + mf) * 32 + slotoff];
            const uint4 wb0 = sb[(kb * 8 + wn * 2 + 0) * 32 + slotoff];
            const uint4 wb1 = sb[(kb * 8 + wn * 2 + 1) * 32 + slotoff];
            const uint32_t bf[4][2] = {
                {wb0.x, wb0.z}, {wb0.y, wb0.w}, {wb1.x, wb1.z}, {wb1.y, wb1.w}};
            #pragma unroll
            for (int mf = 0; mf < 4; mf++)
                #pragma unroll
                for (int nf = 0; nf < 4; nf++) {
                    asm volatile(
                        "mma.sync.aligned.m16n8k8.row.col.f32.tf32.tf32.f32 "
                        "{%0,%1,%2,%3}, {%4,%5,%6,%7}, {%8,%9}, {%0,%1,%2,%3};\n"
                        : "+f"(acc[mf][nf][0]), "+f"(acc[mf][nf][1]),
                          "+f"(acc[mf][nf][2]), "+f"(acc[mf][nf][3])
                        : "r"(wa[mf].x), "r"(wa[mf].y), "r"(wa[mf].z), "r"(wa[mf].w),
                          "r"(bf[nf][0]), "r"(bf[nf][1]));
                }
        }
        const int ktn = kt + 5;
        if (ktn < NT) { int stn = st + 5; if (stn >= 6) stn -= 6; ISSUE(ktn, stn); }
        asm volatile("cp.async.commit_group;");
        st++; if (st == 6) st = 0;
    }
    #undef ISSUE

    const int m0 = blockIdx.y * 128;
    const int n0 = blockIdx.x * 128;
    if (mode == 1) {
        uint32_t* Cp = (uint32_t*)C;
        #pragma unroll
        for (int mf = 0; mf < 4; mf++) {
            const int r0 = m0 + wm * 64 + mf * 16 + g;
            #pragma unroll
            for (int nf = 0; nf < 4; nf++) {
                const int hcol = ((n0 + wn * 32 + nf * 8) >> 1) + t;
                const float a0 = acc[mf][nf][0], b0 = acc[mf][nf][1];
                const float a1 = acc[mf][nf][2], b1 = acc[mf][nf][3];
                const float h0 = (a0 / (1.f + expf(-a0))) * b0;
                const float h1 = (a1 / (1.f + expf(-a1))) * b1;
                Cp[pk_idx(r0,     hcol, 2048)] = f2tf32(h0);
                Cp[pk_idx(r0 + 8, hcol, 2048)] = f2tf32(h1);
            }
        }
    } else {
        #pragma unroll
        for (int mf = 0; mf < 4; mf++) {
            const int r0 = m0 + wm * 64 + mf * 16 + g;
            #pragma unroll
            for (int nf = 0; nf < 4; nf++) {
                const int col = n0 + wn * 32 + nf * 8 + 2 * t;
                float2 v0 = make_float2(acc[mf][nf][0], acc[mf][nf][1]);
                float2 v1 = make_float2(acc[mf][nf][2], acc[mf][nf][3]);
                if (Radd) {
                    float2 r0v = *(const float2*)&Radd[(size_t)r0 * N + col];
                    float2 r1v = *(const float2*)&Radd[(size_t)(r0 + 8) * N + col];
                    v0.x += r0v.x; v0.y += r0v.y;
                    v1.x += r1v.x; v1.y += r1v.y;
                }
                *(float2*)&C[(size_t)r0 * N + col]       = v0;
                *(float2*)&C[(size_t)(r0 + 8) * N + col] = v1;
            }
        }
    }
}

// ---------------- TF32 GEMM, 128x256 tile, 64x64 warp tile (QKV/Wup) --------
// mode 0: plain C store. mode 1: SwiGLU->packed hb. mode 2: fused QKV epilogue
//   (l2norm + RoPE + qr/kt/vr layout stores; warp N-tile == one head).
__global__ void __launch_bounds__(256, 1) gemm_big_k(
    const float* __restrict__ Ap, const float* __restrict__ Bp,
    float* __restrict__ C, const float* __restrict__ Radd,
    int N, int K, int mode,
    const float* __restrict__ cosT, const float* __restrict__ sinT,
    float* __restrict__ qr, float* __restrict__ ktp, float* __restrict__ vrp)
{
    extern __shared__ uint4 dynsm[];   // [6][1536]: A 512 + B 1024 words/stage
    const int tid = threadIdx.x, lane = tid & 31, warp = tid >> 5;
    const int wm = warp >> 2, wn = warp & 3;
    const int g = lane >> 2, t = lane & 3;
    const int slotoff = g * 4 + (t ^ ((g >> 1) & 3));
    const int NT = K >> 4;

    const uint4* gA  = (const uint4*)Ap + (size_t)blockIdx.y * NT * 512;
    const uint4* gB0 = (const uint4*)Bp + (size_t)(2 * blockIdx.x) * NT * 512;
    const uint4* gB1 = (const uint4*)Bp + (size_t)(2 * blockIdx.x + 1) * NT * 512;

    const unsigned sbase = (unsigned)__cvta_generic_to_shared(dynsm);
    const unsigned dA0 = wswz(tid) * 16,        dA1 = wswz(tid + 256) * 16;
    const unsigned dB0 = wswz(tid) * 16,        dB1 = wswz(tid + 256) * 16;
    const unsigned dB2 = wswz(tid + 512) * 16,  dB3 = wswz(tid + 768) * 16;

    float acc[4][8][4];
    #pragma unroll
    for (int mf = 0; mf < 4; mf++)
        #pragma unroll
        for (int nf = 0; nf < 8; nf++)
            #pragma unroll
            for (int i = 0; i < 4; i++) acc[mf][nf][i] = 0.f;

    #define ISSUEB(KT, ST) do {                                             \
        const unsigned _b = sbase + (ST) * 24576;                           \
        const uint4* _a = gA  + (size_t)(KT) * 512;                         \
        const uint4* _p = gB0 + (size_t)(KT) * 512;                         \
        const uint4* _q = gB1 + (size_t)(KT) * 512;                         \
        asm volatile("cp.async.cg.shared.global [%0], [%1], 16;" ::         \
            "r"(_b + dA0), "l"(_a + tid));                                  \
        asm volatile("cp.async.cg.shared.global [%0], [%1], 16;" ::         \
            "r"(_b + dA1), "l"(_a + tid + 256));                            \
        asm volatile("cp.async.cg.shared.global [%0], [%1], 16;" ::         \
            "r"(_b + 8192 + dB0), "l"(_p + tid));                           \
        asm volatile("cp.async.cg.shared.global [%0], [%1], 16;" ::         \
            "r"(_b + 8192 + dB1), "l"(_p + tid + 256));                     \
        asm volatile("cp.async.cg.shared.global [%0], [%1], 16;" ::         \
            "r"(_b + 8192 + dB2), "l"(_q + tid));                           \
        asm volatile("cp.async.cg.shared.global [%0], [%1], 16;" ::         \
            "r"(_b + 8192 + dB3), "l"(_q + tid + 256));                     \
    } while (0)

    #pragma unroll
    for (int p = 0; p < 5; p++) {
        if (p < NT) ISSUEB(p, p);
        asm volatile("cp.async.commit_group;");
    }

    int st = 0;
    for (int kt = 0; kt < NT; kt++) {
        asm volatile("cp.async.wait_group 4;");
        __syncthreads();
        const uint4* sa = dynsm + st * 1536;
        const uint4* sb = sa + 512;
        #pragma unroll
        for (int kb = 0; kb < 2; kb++) {
            uint4 wa[4];
            #pragma unroll
            for (int mf = 0; mf < 4; mf++)
                wa[mf] = sa[(kb * 8 + wm * 4 + mf) * 32 + slotoff];
            uint4 wb[4];
            #pragma unroll
            for (int j = 0; j < 4; j++) {
                const int ng = wn * 4 + j;
                wb[j] = sb[((ng >> 3) << 9) + (kb * 8 + (ng & 7)) * 32 + slotoff];
            }
            #pragma unroll
            for (int mf = 0; mf < 4; mf++)
                #pragma unroll
                for (int j = 0; j < 4; j++) {
                    asm volatile(
                        "mma.sync.aligned.m16n8k8.row.col.f32.tf32.tf32.f32 "
                        "{%0,%1,%2,%3}, {%4,%5,%6,%7}, {%8,%9}, {%0,%1,%2,%3};\n"
                        : "+f"(acc[mf][2*j][0]), "+f"(acc[mf][2*j][1]),
                          "+f"(acc[mf][2*j][2]), "+f"(acc[mf][2*j][3])
                        : "r"(wa[mf].x), "r"(wa[mf].y), "r"(wa[mf].z), "r"(wa[mf].w),
                          "r"(wb[j].x), "r"(wb[j].z));
                    asm volatile(
                        "mma.sync.aligned.m16n8k8.row.col.f32.tf32.tf32.f32 "
                        "{%0,%1,%2,%3}, {%4,%5,%6,%7}, {%8,%9}, {%0,%1,%2,%3};\n"
                        : "+f"(acc[mf][2*j+1][0]), "+f"(acc[mf][2*j+1][1]),
                          "+f"(acc[mf][2*j+1][2]), "+f"(acc[mf][2*j+1][3])
                        : "r"(wa[mf].x), "r"(wa[mf].y), "r"(wa[mf].z), "r"(wa[mf].w),
                          "r"(wb[j].y), "r"(wb[j].w));
                }
        }
        const int ktn = kt + 5;
        if (ktn < NT) { int stn = st + 5; if (stn >= 6) stn -= 6; ISSUEB(ktn, stn); }
        asm volatile("cp.async.commit_group;");
        st++; if (st == 6) st = 0;
    }
    #undef ISSUEB

    const int m0 = blockIdx.y * 128;
    const int n0 = blockIdx.x * 256;
    if (mode == 2) {
        // fused QKV epilogue. Regions: bx 0-3 = Q, 4-7 = K, 8-11 = V.
        // Warp covers cols [bx*256 + wn*64, +64) = exactly head h of its region.
        const int bx = blockIdx.x;
        const int region = bx >> 2;
        const int h = (bx & 3) * 4 + wn;
        #pragma unroll
        for (int mf = 0; mf < 4; mf++) {
            #pragma unroll
            for (int half = 0; half < 2; half++) {
                const int m = m0 + wm * 64 + mf * 16 + g + half * 8;
                const int b = m >> 10, s = m & 1023;
                const size_t bh = (size_t)b * 16 + h;
                float vals[16];
                #pragma unroll
                for (int nf = 0; nf < 8; nf++) {
                    vals[nf * 2]     = acc[mf][nf][half * 2];
                    vals[nf * 2 + 1] = acc[mf][nf][half * 2 + 1];
                }
                if (region == 2) {
                    float* vb = vrp + (bh * 1024 + s) * 64;
                    #pragma unroll
                    for (int nf = 0; nf < 8; nf++) {
                        vb[nf * 8 + 2 * t]     = vals[nf * 2];
                        vb[nf * 8 + 2 * t + 1] = vals[nf * 2 + 1];
                    }
                } else {
                    float ss = 0.f;
                    #pragma unroll
                    for (int i2 = 0; i2 < 16; i2++) ss += vals[i2] * vals[i2];
                    ss += __shfl_xor_sync(0xffffffffu, ss, 1);
                    ss += __shfl_xor_sync(0xffffffffu, ss, 2);
                    const float inv = 1.f / fmaxf(sqrtf(ss), 1e-5f);
                    #pragma unroll
                    for (int nf = 0; nf < 4; nf++) {
                        #pragma unroll
                        for (int c = 0; c < 2; c++) {
                            const int a_lo = nf * 8 + 2 * t + c;
                            const float x1 = vals[nf * 2 + c] * inv;
                            const float x2 = vals[(nf + 4) * 2 + c] * inv;
                            const float cz = cosT[s * 32 + a_lo];
                            const float sz = sinT[s * 32 + a_lo];
                            const float o_lo = x1 * cz + x2 * sz;
                            const float o_hi = x2 * cz - x1 * sz;
                            if (region == 0) {
                                qr[(bh * 1024 + s) * 64 + a_lo]      = o_lo;
                                qr[(bh * 1024 + s) * 64 + a_lo + 32] = o_hi;
                            } else {
                                ktp[(bh * 64 + a_lo) * 1024 + s]        = o_lo;
                                ktp[(bh * 64 + a_lo + 32) * 1024 + s]   = o_hi;
                            }
                        }
                    }
                }
            }
        }
    } else if (mode == 1) {
        uint32_t* Cp = (uint32_t*)C;
        #pragma unroll
        for (int mf = 0; mf < 4; mf++) {
            const int r0 = m0 + wm * 64 + mf * 16 + g;
            #pragma unroll
            for (int nf = 0; nf < 8; nf++) {
                const int hcol = ((n0 + wn * 64 + nf * 8) >> 1) + t;
                const float a0 = acc[mf][nf][0], b0 = acc[mf][nf][1];
                const float a1 = acc[mf][nf][2], b1 = acc[mf][nf][3];
                const float h0 = (a0 / (1.f + expf(-a0))) * b0;
                const float h1 = (a1 / (1.f + expf(-a1))) * b1;
                Cp[pk_idx(r0,     hcol, 2048)] = f2tf32(h0);
                Cp[pk_idx(r0 + 8, hcol, 2048)] = f2tf32(h1);
            }
        }
    } else {
        #pragma unroll
        for (int mf = 0; mf < 4; mf++) {
            const int r0 = m0 + wm * 64 + mf * 16 + g;
            #pragma unroll
            for (int nf = 0; nf < 8; nf++) {
                const int col = n0 + wn * 64 + nf * 8 + 2 * t;
                float2 v0 = make_float2(acc[mf][nf][0], acc[mf][nf][1]);
                float2 v1 = make_float2(acc[mf][nf][2], acc[mf][nf][3]);
                if (Radd) {
                    float2 r0v = *(const float2*)&Radd[(size_t)r0 * N + col];
                    float2 r1v = *(const float2*)&Radd[(size_t)(r0 + 8) * N + col];
                    v0.x += r0v.x; v0.y += r0v.y;
                    v1.x += r1v.x; v1.y += r1v.y;
                }
                *(float2*)&C[(size_t)r0 * N + col]       = v0;
                *(float2*)&C[(size_t)(r0 + 8) * N + col] = v1;
            }
        }
    }
}

// ---------------- RoPE table (once per launch) ----------------
__global__ void rope_table_k(float* __restrict__ ct, float* __restrict__ st_)
{
    const int idx = blockIdx.x * 256 + threadIdx.x;
    if (idx >= 32768) return;
    const int s = idx >> 5, i = idx & 31;
    const double ang = (double)s * pow(10000.0, -(double)i / 32.0);
    ct[idx]  = (float)cos(ang);
    st_[idx] = (float)sin(ang);
}

// ---------------- RMSNorm + pack (one block per row, D=1024) ----------------
__global__ void __launch_bounds__(256) rmsnorm_pack_k(
    const float* __restrict__ x, const float* __restrict__ w, float* __restrict__ P)
{
    const int row = blockIdx.x;
    const float* xr = x + (size_t)row * 1024;
    float s = 0.f;
    for (int i = threadIdx.x; i < 1024; i += 256) { float v = xr[i]; s += v * v; }
    #pragma unroll
    for (int o = 16; o; o >>= 1) s += __shfl_xor_sync(0xffffffffu, s, o);
    __shared__ float red[8];
    const int warp = threadIdx.x >> 5, lane = threadIdx.x & 31;
    if (lane == 0) red[warp] = s;
    __syncthreads();
    float tot = 0.f;
    #pragma unroll
    for (int i = 0; i < 8; i++) tot += red[i];
    const float inv = rsqrtf(tot * (1.f / 1024.f) + 1e-5f);
    const int c4 = threadIdx.x * 4;
    const float4 v = *(const float4*)(xr + c4);
    const float4 wv = *(const float4*)(w + c4);
    uint32_t* Pp = (uint32_t*)P;
    Pp[pk_idx(row, c4 + 0, 1024)] = f2tf32(v.x * inv * wv.x);
    Pp[pk_idx(row, c4 + 1, 1024)] = f2tf32(v.y * inv * wv.y);
    Pp[pk_idx(row, c4 + 2, 1024)] = f2tf32(v.z * inv * wv.z);
    Pp[pk_idx(row, c4 + 3, 1024)] = f2tf32(v.w * inv * wv.w);
}

// ---------------- attention with compact key list; PACKED output ------------
__global__ void __launch_bounds__(256) attn_k(
    const float* __restrict__ qr, const float* __restrict__ kt,
    const float* __restrict__ vr, const int* __restrict__ doc,
    float* __restrict__ attnP)
{
    const int qt = blockIdx.x, h = blockIdx.y, b = blockIdx.z;
    const int q0 = qt * 8;
    __shared__ float sQ[8][64];
    __shared__ float sS[8][520];
    __shared__ float sRed[4][8][64];
    __shared__ int   sDoc[128];
    __shared__ int   mbArr[128];
    __shared__ int   warpCnt[4];
    const int tid = threadIdx.x;
    if (tid < 128) sDoc[tid] = doc[b * 128 + tid];
    const size_t bh = (size_t)b * 16 + h;
    for (int i = tid; i < 8 * 64; i += 256) {
        int q = i >> 6, a = i & 63;
        sQ[q][a] = qr[(bh * 1024 + q0 + q) * 64 + a];
    }
    __syncthreads();

    const int dq = sDoc[qt];
    int flag = 0, pre = 0;
    if (tid < 128) {
        flag = (tid < qt && sDoc[tid] == dq) ? 1 : 0;
        unsigned bal = __ballot_sync(0xffffffffu, flag);
        const int l = tid & 31;
        pre = __popc(bal & ((1u << l) - 1u));
        if (l == 31) warpCnt[tid >> 5] = pre + flag;
    }
    __syncthreads();
    int nc = warpCnt[0] + warpCnt[1] + warpCnt[2] + warpCnt[3];
    if (tid < 128 && flag) {
        const int w = tid >> 5;
        int base = 0;
        for (int i = 0; i < w; i++) base += warpCnt[i];
        mbArr[base + pre] = tid;
    }
    __syncthreads();
    const int nk = nc * 4 + 8;

    const float* ktp = kt + bh * 64 * 1024;
    for (int s = tid; s < nk; s += 256) {
        const int key = (s < nc * 4) ? (mbArr[s >> 2] * 8 + (s & 3))
                                     : (q0 + s - nc * 4);
        float acc[8];
        #pragma unroll
        for (int q = 0; q < 8; q++) acc[q] = 0.f;
        #pragma unroll 8
        for (int a = 0; a < 64; a++) {
            const float kv = ktp[a * 1024 + key];
            #pragma unroll
            for (int q = 0; q < 8; q++) acc[q] += sQ[q][a] * kv;
        }
        #pragma unroll
        for (int q = 0; q < 8; q++) sS[q][s] = acc[q] * 0.125f;
    }
    __syncthreads();

    {
        const int q = tid >> 5, lane = tid & 31;
        float mx = -3.4e38f;
        for (int s = lane; s < nk; s += 32) mx = fmaxf(mx, sS[q][s]);
        #pragma unroll
        for (int o = 16; o; o >>= 1) mx = fmaxf(mx, __shfl_xor_sync(0xffffffffu, mx, o));
        float sum = 0.f;
        for (int s = lane; s < nk; s += 32) {
            const float e = expf(sS[q][s] - mx);
            sS[q][s] = e;
            sum += e;
        }
        #pragma unroll
        for (int o = 16; o; o >>= 1) sum += __shfl_xor_sync(0xffffffffu, sum, o);
        const float inv = 1.f / sum;
        for (int s = lane; s < nk; s += 32) sS[q][s] *= inv;
    }
    __syncthreads();

    const float* vp = vr + bh * 1024 * 64;
    const int a = tid & 63, chunk = tid >> 6;
    const int csz = (nk + 3) >> 2;
    const int jlo = chunk * csz;
    const int jhi = min(nk, jlo + csz);
    float acc[8];
    #pragma unroll
    for (int q = 0; q < 8; q++) acc[q] = 0.f;
    for (int j = jlo; j < jhi; j++) {
        const int key = (j < nc * 4) ? (mbArr[j >> 2] * 8 + (j & 3))
                                     : (q0 + j - nc * 4);
        const float v = vp[(size_t)key * 64 + a];
        #pragma unroll
        for (int q = 0; q < 8; q++) acc[q] += sS[q][j] * v;
    }
    #pragma unroll
    for (int q = 0; q < 8; q++) sRed[chunk][q][a] = acc[q];
    __syncthreads();
    uint32_t* Pp = (uint32_t*)attnP;
    for (int i = tid; i < 8 * 64; i += 256) {
        const int q = i >> 6, a2 = i & 63;
        const float o = sRed[0][q][a2] + sRed[1][q][a2] + sRed[2][q][a2] + sRed[3][q][a2];
        Pp[pk_idx(b * 1024 + q0 + q, h * 64 + a2, 1024)] = f2tf32(o);
    }
}

// ---------------- small elementwise kernels ----------------
__global__ void build_u_pack_k(const float* __restrict__ t1, float* __restrict__ P)
{
    const int idx = blockIdx.x * blockDim.x + threadIdx.x;
    if (idx >= 1024 * 256) return;
    const int col = idx & 255;
    const int ru  = idx >> 8;
    const int m = col >> 6, v = col & 63;
    const int k = ru & 3, bc = ru >> 2;
    const float val = t1[((size_t)bc * 4 + m) * 256 + k * 64 + v];
    ((uint32_t*)P)[pk_idx(ru, col, 256)] = f2tf32(val);
}

__global__ void assemble_k(const float* __restrict__ xin, const float* __restrict__ xdec,
                           const float* __restrict__ pe, float* __restrict__ x)
{
    const int idx = blockIdx.x * blockDim.x + threadIdx.x;
    if (idx >= 2 * 1024 * 1024) return;
    const int d  = idx & 1023;
    const int sb = idx >> 10;
    const int s_ = sb & 1023;
    const int b  = sb >> 10;
    const int c  = s_ >> 3, e = s_ & 7;
    float v;
    if (e < 4) v = xin[((size_t)(b * 512 + c * 4 + e)) * 1024 + d];
    else       v = xdec[((size_t)((b * 128 + c) * 4 + (e - 4))) * 1024 + d]
                   + pe[(e - 4) * 1024 + d];
    x[idx] = v;
}

__global__ void gather_k(const float* __restrict__ x, float* __restrict__ out)
{
    const int idx = blockIdx.x * blockDim.x + threadIdx.x;
    if (idx >= 256 * 4 * 1024) return;
    const int d = idx & 1023;
    const int t = idx >> 10;
    const int k = t & 3;
    const int g = t >> 2;
    const int c = g & 127;
    const int b = g >> 7;
    out[idx] = x[((size_t)(b * 1024 + c * 8 + 4 + k)) * 1024 + d];
}

// ---------------- launch ----------------
extern "C" void kernel_launch(void* const* d_in, const int* in_sizes, int n_in,
                              void* d_out, int out_size)
{
    const float* x_input     = (const float*)d_in[0];
    const int*   doc         = (const int*)d_in[1];
    const float* dec_w1      = (const float*)d_in[2];
    const float* dec_w2      = (const float*)d_in[3];
    const float* pos_emb     = (const float*)d_in[4];
    const float* Wqkv        = (const float*)d_in[5];
    const float* Wo          = (const float*)d_in[6];
    const float* Wup         = (const float*)d_in[7];
    const float* Wdown       = (const float*)d_in[8];
    const float* attn_norm_w = (const float*)d_in[9];
    const float* ffn_norm_w  = (const float*)d_in[10];

    float* S = nullptr;
    cudaGetSymbolAddress((void**)&S, g_scratch);
    float* x    = S + OFF_X;
    float* x1   = S + OFF_X1;
    float* qr   = S + OFF_QR;
    float* ktb_ = S + OFF_KT;
    float* vr   = S + OFF_VR;
    float* hbp  = S + OFF_HB;
    float* tmp1 = S + OFF_TMP1;
    float* xdec = S + OFF_XDEC;
    float* apk  = S + OFF_APACK;
    float* w1p  = S + OFF_W1P;
    float* w2p  = S + OFF_W2P;
    float* qkvp = S + OFF_QKVP;
    float* wop  = S + OFF_WOP;
    float* upp  = S + OFF_UPP;
    float* dwnp = S + OFF_DWNP;
    float* cosT = S + OFF_COS;
    float* sinT = S + OFF_SIN;

    // host-side resources, created once (uncaptured correctness call)
    static cudaStream_t s2 = nullptr;
    static cudaEvent_t evFork = nullptr;
    static cudaEvent_t evPack[4];
    static cudaEvent_t evRope = nullptr;
    if (!s2) {
        cudaStreamCreateWithFlags(&s2, cudaStreamNonBlocking);
        cudaEventCreateWithFlags(&evFork, cudaEventDisableTiming);
        cudaEventCreateWithFlags(&evRope, cudaEventDisableTiming);
        for (int i = 0; i < 4; i++)
            cudaEventCreateWithFlags(&evPack[i], cudaEventDisableTiming);
    }

    const dim3 blk(256);
    const int GEMM_SMEM = 12 * 512 * 16;   // 98304
    const int BIG_SMEM  = 6 * 1536 * 16;   // 147456
    cudaFuncSetAttribute(gemm_tc_k,  cudaFuncAttributeMaxDynamicSharedMemorySize, GEMM_SMEM);
    cudaFuncSetAttribute(gemm_big_k, cudaFuncAttributeMaxDynamicSharedMemorySize, BIG_SMEM);

    // fork side stream from the capturing stream
    cudaEventRecord(evFork, 0);
    cudaStreamWaitEvent(s2, evFork, 0);

    // side stream: rope table + all per-layer weight packs (independent branch)
    rope_table_k<<<128, 256, 0, s2>>>(cosT, sinT);
    cudaEventRecord(evRope, s2);
    for (int li = 0; li < 4; li++) {
        pack_tf32_k<<<dim3(32, 24), blk, 0, s2>>>(Wqkv  + (size_t)li * 3145728, qkvp + (size_t)li * 3145728, 1024, 0);
        pack_tf32_k<<<dim3(32, 8),  blk, 0, s2>>>(Wo    + (size_t)li * 1048576, wop  + (size_t)li * 1048576, 1024, 0);
        pack_tf32_k<<<dim3(32, 32), blk, 0, s2>>>(Wup   + (size_t)li * 4194304, upp  + (size_t)li * 4194304, 1024, 1);
        pack_tf32_k<<<dim3(64, 8),  blk, 0, s2>>>(Wdown + (size_t)li * 2097152, dwnp + (size_t)li * 2097152, 2048, 0);
        cudaEventRecord(evPack[li], s2);
    }

    // main stream: front-end
    pack_tf32_k<<<dim3(32, 2),  blk>>>(dec_w1, w1p, 1024, 0);
    pack_tf32_k<<<dim3(8, 8),   blk>>>(dec_w2, w2p, 256, 0);
    pack_tf32_k<<<dim3(32, 8), blk>>>(x_input, apk, 1024, 0);
    gemm_tc_k<<<dim3(2, 8), blk, GEMM_SMEM>>>(apk, w1p, tmp1, nullptr, 256, 1024, 0);
    build_u_pack_k<<<(262144 + 255) / 256, 256>>>(tmp1, apk);
    gemm_tc_k<<<dim3(8, 8), blk, GEMM_SMEM>>>(apk, w2p, xdec, nullptr, 1024, 256, 0);
    assemble_k<<<(2097152 + 255) / 256, 256>>>(x_input, xdec, pos_emb, x);

    for (int li = 0; li < 4; li++) {
        rmsnorm_pack_k<<<2048, 256>>>(x, attn_norm_w + (size_t)li * 1024, apk);
        cudaStreamWaitEvent(0, evPack[li], 0);   // layer-li weights packed
        if (li == 0) cudaStreamWaitEvent(0, evRope, 0);
        // QKV with fused l2norm+RoPE+layout epilogue (mode 2)
        gemm_big_k<<<dim3(12, 16), blk, BIG_SMEM>>>(
            apk, qkvp + (size_t)li * 3145728, nullptr, nullptr, 3072, 1024, 2,
            cosT, sinT, qr, ktb_, vr);
        attn_k<<<dim3(128, 16, 2), 256>>>(qr, ktb_, vr, doc, apk);
        gemm_tc_k<<<dim3(8, 16), blk, GEMM_SMEM>>>(apk, wop + (size_t)li * 1048576, x1, x, 1024, 1024, 0);
        rmsnorm_pack_k<<<2048, 256>>>(x1, ffn_norm_w + (size_t)li * 1024, apk);
        gemm_big_k<<<dim3(16, 16), blk, BIG_SMEM>>>(
            apk, upp + (size_t)li * 4194304, hbp, nullptr, 4096, 1024, 1,
            nullptr, nullptr, nullptr, nullptr, nullptr);
        gemm_tc_k<<<dim3(8, 16), blk, GEMM_SMEM>>>(hbp, dwnp + (size_t)li * 2097152, x, x1, 1024, 2048, 0);
    }

    gather_k<<<(1048576 + 255) / 256, 256>>>(x, (float*)d_out);
}

// round 15
// speedup vs baseline: 4.6574x; 1.1406x over previous
#include <cuda_runtime.h>
#include <math.h>
#include <stdint.h>

// Shapes (fixed): B=2, C=128, M=4, K=4, V=64, D=1024, H=16, A=64, L=4, HF=2048,
// E=8, S=1024, rows=2048

// ---------------- scratch (no allocations allowed) ----------------
__device__ float g_scratch[81854464];

static const size_t OFF_X    = 0;
static const size_t OFF_X1   = 4194304;
static const size_t OFF_QR   = 12582912;
static const size_t OFF_KT   = 14680064;
static const size_t OFF_VR   = 16777216;
static const size_t OFF_HB   = 29360128;  // hb PACKED (16MB)
static const size_t OFF_TMP1 = 33554432;
static const size_t OFF_XDEC = 34078720;
// packed tf32 buffers
static const size_t OFF_APACK = 35127296;
static const size_t OFF_W1P   = 39321600;
static const size_t OFF_W2P   = 39583744;
static const size_t OFF_QKVP  = 39845888;
static const size_t OFF_WOP   = 52428800;
static const size_t OFF_UPP   = 56623104;
static const size_t OFF_DWNP  = 73400320;
static const size_t OFF_COS   = 81788928;
static const size_t OFF_SIN   = 81821696;

__device__ __forceinline__ uint32_t f2tf32(float x) {
    uint32_t r;
    asm("cvt.rna.tf32.f32 %0, %1;" : "=r"(r) : "f"(x));
    return r;
}

// Fragment-packed layout (per 128-row x 16-col region): 512 uint4 words.
__device__ __forceinline__ size_t pk_idx(int r, int c, int K)
{
    const int rblk = r >> 7, rm = r & 127;
    const int g = rm & 7, half = (rm >> 3) & 1, mgi = rm >> 4;
    const int kt16 = c >> 4, co = c & 15;
    const int kb = co >> 3, t = co & 3, ch = (co >> 2) & 1;
    const size_t widx = ((size_t)rblk * (K >> 4) + kt16) * 512
                      + (size_t)((kb * 8 + mgi) * 32 + g * 4 + t);
    return widx * 4 + (half + 2 * ch);
}

__device__ __forceinline__ uint32_t wswz(uint32_t w) {
    return (w & ~3u) | ((w & 3u) ^ ((w >> 3) & 3u));
}

// ---------------- pack: row-major fp32 [R][K] -> tf32 fragment-packed --------
__global__ void __launch_bounds__(256) pack_tf32_k(
    const float* __restrict__ X, float* __restrict__ P, int K, int perm)
{
    const int tid  = threadIdx.x;
    const int rblk = blockIdx.y, ktb = blockIdx.x;
    const int g    = tid & 7;
    const int u32i = tid >> 3;
    const int kbb  = u32i >> 3;
    const int mgi  = u32i & 7;
    const int r0   = rblk * 128 + mgi * 16 + g;
    const int c0   = ktb * 32 + kbb * 8;

    int ra = r0, rb = r0 + 8;
    if (perm) {
        ra = (r0 & 1) ? 2048 + (r0 >> 1) : (r0 >> 1);
        rb = ((r0 + 8) & 1) ? 2048 + ((r0 + 8) >> 1) : ((r0 + 8) >> 1);
    }

    const float4 a0  = *(const float4*)(X + (size_t)ra * K + c0);
    const float4 a0h = *(const float4*)(X + (size_t)ra * K + c0 + 4);
    const float4 a1  = *(const float4*)(X + (size_t)rb * K + c0);
    const float4 a1h = *(const float4*)(X + (size_t)rb * K + c0 + 4);

    const int kt16 = ktb * 2 + (kbb >> 1);
    const int kb   = kbb & 1;
    uint4* dst = (uint4*)P + ((size_t)rblk * (K >> 4) + kt16) * 512
               + (kb * 8 + mgi) * 32 + g * 4;
    uint4 w;
    w.x = f2tf32(a0.x); w.y = f2tf32(a1.x); w.z = f2tf32(a0h.x); w.w = f2tf32(a1h.x); dst[0] = w;
    w.x = f2tf32(a0.y); w.y = f2tf32(a1.y); w.z = f2tf32(a0h.y); w.w = f2tf32(a1h.y); dst[1] = w;
    w.x = f2tf32(a0.z); w.y = f2tf32(a1.z); w.z = f2tf32(a0h.z); w.w = f2tf32(a1h.z); dst[2] = w;
    w.x = f2tf32(a0.w); w.y = f2tf32(a1.w); w.z = f2tf32(a0h.w); w.w = f2tf32(a1h.w); dst[3] = w;
}

// ---------------- unified TF32 GEMM: 128x128 tile, 4 warps of 64x64 ---------
// 128 threads, 4-stage cp.async ring (64KB), occupancy 2.
// 16 FLOP/smem-byte (4 A-frag + 4 B-frag LDS.128 per kb feed 32 MMAs).
// mode 0: C float (+Radd). mode 1: SwiGLU -> packed hb. mode 2: fused QKV
//   epilogue (l2norm + RoPE + qr/kt/vr stores; warp N-tile == one head).
__global__ void __launch_bounds__(128, 2) gemm_v2_k(
    const float* __restrict__ Ap, const float* __restrict__ Bp,
    float* __restrict__ C, const float* __restrict__ Radd,
    int N, int K, int mode,
    const float* __restrict__ cosT, const float* __restrict__ sinT,
    float* __restrict__ qr, float* __restrict__ ktp, float* __restrict__ vrp)
{
    extern __shared__ uint4 dynsm[];   // [4][1024]: A 512 + B 512 words/stage
    const int tid = threadIdx.x, lane = tid & 31, warp = tid >> 5;
    const int wm = warp >> 1, wn = warp & 1;
    const int g = lane >> 2, t = lane & 3;
    const int slotoff = g * 4 + (t ^ ((g >> 1) & 3));
    const int NT = K >> 4;

    const uint4* gA = (const uint4*)Ap + (size_t)blockIdx.y * NT * 512;
    const uint4* gB = (const uint4*)Bp + (size_t)blockIdx.x * NT * 512;

    const unsigned sbase = (unsigned)__cvta_generic_to_shared(dynsm);
    const unsigned d0 = wswz(tid) * 16;
    const unsigned d1 = wswz(tid + 128) * 16;
    const unsigned d2 = wswz(tid + 256) * 16;
    const unsigned d3 = wswz(tid + 384) * 16;

    float acc[4][8][4];
    #pragma unroll
    for (int mf = 0; mf < 4; mf++)
        #pragma unroll
        for (int nf = 0; nf < 8; nf++)
            #pragma unroll
            for (int i = 0; i < 4; i++) acc[mf][nf][i] = 0.f;

    #define ISSUE2(KT, ST) do {                                             \
        const uint4* _a = gA + (size_t)(KT) * 512;                          \
        const uint4* _p = gB + (size_t)(KT) * 512;                          \
        const unsigned _d = sbase + (ST) * 16384;                           \
        asm volatile("cp.async.cg.shared.global [%0], [%1], 16;" ::         \
            "r"(_d + d0), "l"(_a + tid));                                   \
        asm volatile("cp.async.cg.shared.global [%0], [%1], 16;" ::         \
            "r"(_d + d1), "l"(_a + tid + 128));                             \
        asm volatile("cp.async.cg.shared.global [%0], [%1], 16;" ::         \
            "r"(_d + d2), "l"(_a + tid + 256));                             \
        asm volatile("cp.async.cg.shared.global [%0], [%1], 16;" ::         \
            "r"(_d + d3), "l"(_a + tid + 384));                             \
        asm volatile("cp.async.cg.shared.global [%0], [%1], 16;" ::         \
            "r"(_d + 8192 + d0), "l"(_p + tid));                            \
        asm volatile("cp.async.cg.shared.global [%0], [%1], 16;" ::         \
            "r"(_d + 8192 + d1), "l"(_p + tid + 128));                      \
        asm volatile("cp.async.cg.shared.global [%0], [%1], 16;" ::         \
            "r"(_d + 8192 + d2), "l"(_p + tid + 256));                      \
        asm volatile("cp.async.cg.shared.global [%0], [%1], 16;" ::         \
            "r"(_d + 8192 + d3), "l"(_p + tid + 384));                      \
    } while (0)

    #pragma unroll
    for (int p = 0; p < 3; p++) {
        if (p < NT) ISSUE2(p, p);
        asm volatile("cp.async.commit_group;");
    }

    int st = 0;
    for (int kt = 0; kt < NT; kt++) {
        asm volatile("cp.async.wait_group 2;");
        __syncthreads();
        const uint4* sa = dynsm + st * 1024;
        const uint4* sb = sa + 512;
        #pragma unroll
        for (int kb = 0; kb < 2; kb++) {
            uint4 wa[4];
            #pragma unroll
            for (int mf = 0; mf < 4; mf++)
                wa[mf] = sa[(kb * 8 + wm * 4 + mf) * 32 + slotoff];
            uint4 wb[4];
            #pragma unroll
            for (int j = 0; j < 4; j++)
                wb[j] = sb[(kb * 8 + wn * 4 + j) * 32 + slotoff];
            #pragma unroll
            for (int mf = 0; mf < 4; mf++)
                #pragma unroll
                for (int j = 0; j < 4; j++) {
                    asm volatile(
                        "mma.sync.aligned.m16n8k8.row.col.f32.tf32.tf32.f32 "
                        "{%0,%1,%2,%3}, {%4,%5,%6,%7}, {%8,%9}, {%0,%1,%2,%3};\n"
                        : "+f"(acc[mf][2*j][0]), "+f"(acc[mf][2*j][1]),
                          "+f"(acc[mf][2*j][2]), "+f"(acc[mf][2*j][3])
                        : "r"(wa[mf].x), "r"(wa[mf].y), "r"(wa[mf].z), "r"(wa[mf].w),
                          "r"(wb[j].x), "r"(wb[j].z));
                    asm volatile(
                        "mma.sync.aligned.m16n8k8.row.col.f32.tf32.tf32.f32 "
                        "{%0,%1,%2,%3}, {%4,%5,%6,%7}, {%8,%9}, {%0,%1,%2,%3};\n"
                        : "+f"(acc[mf][2*j+1][0]), "+f"(acc[mf][2*j+1][1]),
                          "+f"(acc[mf][2*j+1][2]), "+f"(acc[mf][2*j+1][3])
                        : "r"(wa[mf].x), "r"(wa[mf].y), "r"(wa[mf].z), "r"(wa[mf].w),
                          "r"(wb[j].y), "r"(wb[j].w));
                }
        }
        const int ktn = kt + 3;
        if (ktn < NT) ISSUE2(ktn, (st + 3) & 3);
        asm volatile("cp.async.commit_group;");
        st = (st + 1) & 3;
    }
    #undef ISSUE2

    const int m0 = blockIdx.y * 128;
    const int n0 = blockIdx.x * 128;
    if (mode == 2) {
        // fused QKV epilogue. CTA covers 128 cols = 2 heads; warp wn = one head.
        // bx 0-7 = Q, 8-15 = K, 16-23 = V.
        const int bx = blockIdx.x;
        const int region = bx >> 3;
        const int h = (bx & 7) * 2 + wn;
        #pragma unroll
        for (int mf = 0; mf < 4; mf++) {
            #pragma unroll
            for (int half = 0; half < 2; half++) {
                const int m = m0 + wm * 64 + mf * 16 + g + half * 8;
                const int b = m >> 10, s = m & 1023;
                const size_t bh = (size_t)b * 16 + h;
                float vals[16];
                #pragma unroll
                for (int nf = 0; nf < 8; nf++) {
                    vals[nf * 2]     = acc[mf][nf][half * 2];
                    vals[nf * 2 + 1] = acc[mf][nf][half * 2 + 1];
                }
                if (region == 2) {
                    float* vb = vrp + (bh * 1024 + s) * 64;
                    #pragma unroll
                    for (int nf = 0; nf < 8; nf++) {
                        vb[nf * 8 + 2 * t]     = vals[nf * 2];
                        vb[nf * 8 + 2 * t + 1] = vals[nf * 2 + 1];
                    }
                } else {
                    float ss = 0.f;
                    #pragma unroll
                    for (int i2 = 0; i2 < 16; i2++) ss += vals[i2] * vals[i2];
                    ss += __shfl_xor_sync(0xffffffffu, ss, 1);
                    ss += __shfl_xor_sync(0xffffffffu, ss, 2);
                    const float inv = 1.f / fmaxf(sqrtf(ss), 1e-5f);
                    #pragma unroll
                    for (int nf = 0; nf < 4; nf++) {
                        #pragma unroll
                        for (int c = 0; c < 2; c++) {
                            const int a_lo = nf * 8 + 2 * t + c;
                            const float x1 = vals[nf * 2 + c] * inv;
                            const float x2 = vals[(nf + 4) * 2 + c] * inv;
                            const float cz = cosT[s * 32 + a_lo];
                            const float sz = sinT[s * 32 + a_lo];
                            const float o_lo = x1 * cz + x2 * sz;
                            const float o_hi = x2 * cz - x1 * sz;
                            if (region == 0) {
                                qr[(bh * 1024 + s) * 64 + a_lo]      = o_lo;
                                qr[(bh * 1024 + s) * 64 + a_lo + 32] = o_hi;
                            } else {
                                ktp[(bh * 64 + a_lo) * 1024 + s]        = o_lo;
                                ktp[(bh * 64 + a_lo + 32) * 1024 + s]   = o_hi;
                            }
                        }
                    }
                }
            }
        }
    } else if (mode == 1) {
        uint32_t* Cp = (uint32_t*)C;
        #pragma unroll
        for (int mf = 0; mf < 4; mf++) {
            const int r0 = m0 + wm * 64 + mf * 16 + g;
            #pragma unroll
            for (int nf = 0; nf < 8; nf++) {
                const int hcol = ((n0 + wn * 64 + nf * 8) >> 1) + t;
                const float a0 = acc[mf][nf][0], b0 = acc[mf][nf][1];
                const float a1 = acc[mf][nf][2], b1 = acc[mf][nf][3];
                const float h0 = (a0 / (1.f + expf(-a0))) * b0;
                const float h1 = (a1 / (1.f + expf(-a1))) * b1;
                Cp[pk_idx(r0,     hcol, 2048)] = f2tf32(h0);
                Cp[pk_idx(r0 + 8, hcol, 2048)] = f2tf32(h1);
            }
        }
    } else {
        #pragma unroll
        for (int mf = 0; mf < 4; mf++) {
            const int r0 = m0 + wm * 64 + mf * 16 + g;
            #pragma unroll
            for (int nf = 0; nf < 8; nf++) {
                const int col = n0 + wn * 64 + nf * 8 + 2 * t;
                float2 v0 = make_float2(acc[mf][nf][0], acc[mf][nf][1]);
                float2 v1 = make_float2(acc[mf][nf][2], acc[mf][nf][3]);
                if (Radd) {
                    float2 r0v = *(const float2*)&Radd[(size_t)r0 * N + col];
                    float2 r1v = *(const float2*)&Radd[(size_t)(r0 + 8) * N + col];
                    v0.x += r0v.x; v0.y += r0v.y;
                    v1.x += r1v.x; v1.y += r1v.y;
                }
                *(float2*)&C[(size_t)r0 * N + col]       = v0;
                *(float2*)&C[(size_t)(r0 + 8) * N + col] = v1;
            }
        }
    }
}

// ---------------- RoPE table (once per launch) ----------------
__global__ void rope_table_k(float* __restrict__ ct, float* __restrict__ st_)
{
    const int idx = blockIdx.x * 256 + threadIdx.x;
    if (idx >= 32768) return;
    const int s = idx >> 5, i = idx & 31;
    const double ang = (double)s * pow(10000.0, -(double)i / 32.0);
    ct[idx]  = (float)cos(ang);
    st_[idx] = (float)sin(ang);
}

// ---------------- RMSNorm + pack (one block per row, D=1024) ----------------
__global__ void __launch_bounds__(256) rmsnorm_pack_k(
    const float* __restrict__ x, const float* __restrict__ w, float* __restrict__ P)
{
    const int row = blockIdx.x;
    const float* xr = x + (size_t)row * 1024;
    float s = 0.f;
    for (int i = threadIdx.x; i < 1024; i += 256) { float v = xr[i]; s += v * v; }
    #pragma unroll
    for (int o = 16; o; o >>= 1) s += __shfl_xor_sync(0xffffffffu, s, o);
    __shared__ float red[8];
    const int warp = threadIdx.x >> 5, lane = threadIdx.x & 31;
    if (lane == 0) red[warp] = s;
    __syncthreads();
    float tot = 0.f;
    #pragma unroll
    for (int i = 0; i < 8; i++) tot += red[i];
    const float inv = rsqrtf(tot * (1.f / 1024.f) + 1e-5f);
    const int c4 = threadIdx.x * 4;
    const float4 v = *(const float4*)(xr + c4);
    const float4 wv = *(const float4*)(w + c4);
    uint32_t* Pp = (uint32_t*)P;
    Pp[pk_idx(row, c4 + 0, 1024)] = f2tf32(v.x * inv * wv.x);
    Pp[pk_idx(row, c4 + 1, 1024)] = f2tf32(v.y * inv * wv.y);
    Pp[pk_idx(row, c4 + 2, 1024)] = f2tf32(v.z * inv * wv.z);
    Pp[pk_idx(row, c4 + 3, 1024)] = f2tf32(v.w * inv * wv.w);
}

// ---------------- attention with compact key list; PACKED output ------------
__global__ void __launch_bounds__(256) attn_k(
    const float* __restrict__ qr, const float* __restrict__ kt,
    const float* __restrict__ vr, const int* __restrict__ doc,
    float* __restrict__ attnP)
{
    const int qt = blockIdx.x, h = blockIdx.y, b = blockIdx.z;
    const int q0 = qt * 8;
    __shared__ float sQ[8][64];
    __shared__ float sS[8][520];
    __shared__ float sRed[4][8][64];
    __shared__ int   sDoc[128];
    __shared__ int   mbArr[128];
    __shared__ int   warpCnt[4];
    const int tid = threadIdx.x;
    if (tid < 128) sDoc[tid] = doc[b * 128 + tid];
    const size_t bh = (size_t)b * 16 + h;
    for (int i = tid; i < 8 * 64; i += 256) {
        int q = i >> 6, a = i & 63;
        sQ[q][a] = qr[(bh * 1024 + q0 + q) * 64 + a];
    }
    __syncthreads();

    const int dq = sDoc[qt];
    int flag = 0, pre = 0;
    if (tid < 128) {
        flag = (tid < qt && sDoc[tid] == dq) ? 1 : 0;
        unsigned bal = __ballot_sync(0xffffffffu, flag);
        const int l = tid & 31;
        pre = __popc(bal & ((1u << l) - 1u));
        if (l == 31) warpCnt[tid >> 5] = pre + flag;
    }
    __syncthreads();
    int nc = warpCnt[0] + warpCnt[1] + warpCnt[2] + warpCnt[3];
    if (tid < 128 && flag) {
        const int w = tid >> 5;
        int base = 0;
        for (int i = 0; i < w; i++) base += warpCnt[i];
        mbArr[base + pre] = tid;
    }
    __syncthreads();
    const int nk = nc * 4 + 8;

    const float* ktp = kt + bh * 64 * 1024;
    for (int s = tid; s < nk; s += 256) {
        const int key = (s < nc * 4) ? (mbArr[s >> 2] * 8 + (s & 3))
                                     : (q0 + s - nc * 4);
        float acc[8];
        #pragma unroll
        for (int q = 0; q < 8; q++) acc[q] = 0.f;
        #pragma unroll 8
        for (int a = 0; a < 64; a++) {
            const float kv = ktp[a * 1024 + key];
            #pragma unroll
            for (int q = 0; q < 8; q++) acc[q] += sQ[q][a] * kv;
        }
        #pragma unroll
        for (int q = 0; q < 8; q++) sS[q][s] = acc[q] * 0.125f;
    }
    __syncthreads();

    {
        const int q = tid >> 5, lane = tid & 31;
        float mx = -3.4e38f;
        for (int s = lane; s < nk; s += 32) mx = fmaxf(mx, sS[q][s]);
        #pragma unroll
        for (int o = 16; o; o >>= 1) mx = fmaxf(mx, __shfl_xor_sync(0xffffffffu, mx, o));
        float sum = 0.f;
        for (int s = lane; s < nk; s += 32) {
            const float e = expf(sS[q][s] - mx);
            sS[q][s] = e;
            sum += e;
        }
        #pragma unroll
        for (int o = 16; o; o >>= 1) sum += __shfl_xor_sync(0xffffffffu, sum, o);
        const float inv = 1.f / sum;
        for (int s = lane; s < nk; s += 32) sS[q][s] *= inv;
    }
    __syncthreads();

    const float* vp = vr + bh * 1024 * 64;
    const int a = tid & 63, chunk = tid >> 6;
    const int csz = (nk + 3) >> 2;
    const int jlo = chunk * csz;
    const int jhi = min(nk, jlo + csz);
    float acc[8];
    #pragma unroll
    for (int q = 0; q < 8; q++) acc[q] = 0.f;
    for (int j = jlo; j < jhi; j++) {
        const int key = (j < nc * 4) ? (mbArr[j >> 2] * 8 + (j & 3))
                                     : (q0 + j - nc * 4);
        const float v = vp[(size_t)key * 64 + a];
        #pragma unroll
        for (int q = 0; q < 8; q++) acc[q] += sS[q][j] * v;
    }
    #pragma unroll
    for (int q = 0; q < 8; q++) sRed[chunk][q][a] = acc[q];
    __syncthreads();
    uint32_t* Pp = (uint32_t*)attnP;
    for (int i = tid; i < 8 * 64; i += 256) {
        const int q = i >> 6, a2 = i & 63;
        const float o = sRed[0][q][a2] + sRed[1][q][a2] + sRed[2][q][a2] + sRed[3][q][a2];
        Pp[pk_idx(b * 1024 + q0 + q, h * 64 + a2, 1024)] = f2tf32(o);
    }
}

// ---------------- small elementwise kernels ----------------
__global__ void build_u_pack_k(const float* __restrict__ t1, float* __restrict__ P)
{
    const int idx = blockIdx.x * blockDim.x + threadIdx.x;
    if (idx >= 1024 * 256) return;
    const int col = idx & 255;
    const int ru  = idx >> 8;
    const int m = col >> 6, v = col & 63;
    const int k = ru & 3, bc = ru >> 2;
    const float val = t1[((size_t)bc * 4 + m) * 256 + k * 64 + v];
    ((uint32_t*)P)[pk_idx(ru, col, 256)] = f2tf32(val);
}

__global__ void assemble_k(const float* __restrict__ xin, const float* __restrict__ xdec,
                           const float* __restrict__ pe, float* __restrict__ x)
{
    const int idx = blockIdx.x * blockDim.x + threadIdx.x;
    if (idx >= 2 * 1024 * 1024) return;
    const int d  = idx & 1023;
    const int sb = idx >> 10;
    const int s_ = sb & 1023;
    const int b  = sb >> 10;
    const int c  = s_ >> 3, e = s_ & 7;
    float v;
    if (e < 4) v = xin[((size_t)(b * 512 + c * 4 + e)) * 1024 + d];
    else       v = xdec[((size_t)((b * 128 + c) * 4 + (e - 4))) * 1024 + d]
                   + pe[(e - 4) * 1024 + d];
    x[idx] = v;
}

__global__ void gather_k(const float* __restrict__ x, float* __restrict__ out)
{
    const int idx = blockIdx.x * blockDim.x + threadIdx.x;
    if (idx >= 256 * 4 * 1024) return;
    const int d = idx & 1023;
    const int t = idx >> 10;
    const int k = t & 3;
    const int g = t >> 2;
    const int c = g & 127;
    const int b = g >> 7;
    out[idx] = x[((size_t)(b * 1024 + c * 8 + 4 + k)) * 1024 + d];
}

// ---------------- launch ----------------
extern "C" void kernel_launch(void* const* d_in, const int* in_sizes, int n_in,
                              void* d_out, int out_size)
{
    const float* x_input     = (const float*)d_in[0];
    const int*   doc         = (const int*)d_in[1];
    const float* dec_w1      = (const float*)d_in[2];
    const float* dec_w2      = (const float*)d_in[3];
    const float* pos_emb     = (const float*)d_in[4];
    const float* Wqkv        = (const float*)d_in[5];
    const float* Wo          = (const float*)d_in[6];
    const float* Wup         = (const float*)d_in[7];
    const float* Wdown       = (const float*)d_in[8];
    const float* attn_norm_w = (const float*)d_in[9];
    const float* ffn_norm_w  = (const float*)d_in[10];

    float* S = nullptr;
    cudaGetSymbolAddress((void**)&S, g_scratch);
    float* x    = S + OFF_X;
    float* x1   = S + OFF_X1;
    float* qr   = S + OFF_QR;
    float* ktb_ = S + OFF_KT;
    float* vr   = S + OFF_VR;
    float* hbp  = S + OFF_HB;
    float* tmp1 = S + OFF_TMP1;
    float* xdec = S + OFF_XDEC;
    float* apk  = S + OFF_APACK;
    float* w1p  = S + OFF_W1P;
    float* w2p  = S + OFF_W2P;
    float* qkvp = S + OFF_QKVP;
    float* wop  = S + OFF_WOP;
    float* upp  = S + OFF_UPP;
    float* dwnp = S + OFF_DWNP;
    float* cosT = S + OFF_COS;
    float* sinT = S + OFF_SIN;

    // host-side resources, created once (uncaptured correctness call)
    static cudaStream_t s2 = nullptr;
    static cudaEvent_t evFork = nullptr;
    static cudaEvent_t evPack[4];
    static cudaEvent_t evRope = nullptr;
    if (!s2) {
        cudaStreamCreateWithFlags(&s2, cudaStreamNonBlocking);
        cudaEventCreateWithFlags(&evFork, cudaEventDisableTiming);
        cudaEventCreateWithFlags(&evRope, cudaEventDisableTiming);
        for (int i = 0; i < 4; i++)
            cudaEventCreateWithFlags(&evPack[i], cudaEventDisableTiming);
    }

    const dim3 blk(256);
    const int V2_SMEM = 4 * 1024 * 16;     // 65536 bytes (4 stages x (A+B))
    cudaFuncSetAttribute(gemm_v2_k, cudaFuncAttributeMaxDynamicSharedMemorySize, V2_SMEM);

    // fork side stream from the capturing stream
    cudaEventRecord(evFork, 0);
    cudaStreamWaitEvent(s2, evFork, 0);

    // side stream: rope table + all per-layer weight packs (independent branch)
    rope_table_k<<<128, 256, 0, s2>>>(cosT, sinT);
    cudaEventRecord(evRope, s2);
    for (int li = 0; li < 4; li++) {
        pack_tf32_k<<<dim3(32, 24), blk, 0, s2>>>(Wqkv  + (size_t)li * 3145728, qkvp + (size_t)li * 3145728, 1024, 0);
        pack_tf32_k<<<dim3(32, 8),  blk, 0, s2>>>(Wo    + (size_t)li * 1048576, wop  + (size_t)li * 1048576, 1024, 0);
        pack_tf32_k<<<dim3(32, 32), blk, 0, s2>>>(Wup   + (size_t)li * 4194304, upp  + (size_t)li * 4194304, 1024, 1);
        pack_tf32_k<<<dim3(64, 8),  blk, 0, s2>>>(Wdown + (size_t)li * 2097152, dwnp + (size_t)li * 2097152, 2048, 0);
        cudaEventRecord(evPack[li], s2);
    }

    // main stream: front-end
    pack_tf32_k<<<dim3(32, 2),  blk>>>(dec_w1, w1p, 1024, 0);
    pack_tf32_k<<<dim3(8, 8),   blk>>>(dec_w2, w2p, 256, 0);
    pack_tf32_k<<<dim3(32, 8), blk>>>(x_input, apk, 1024, 0);
    gemm_v2_k<<<dim3(2, 8), 128, V2_SMEM>>>(apk, w1p, tmp1, nullptr, 256, 1024, 0,
        nullptr, nullptr, nullptr, nullptr, nullptr);
    build_u_pack_k<<<(262144 + 255) / 256, 256>>>(tmp1, apk);
    gemm_v2_k<<<dim3(8, 8), 128, V2_SMEM>>>(apk, w2p, xdec, nullptr, 1024, 256, 0,
        nullptr, nullptr, nullptr, nullptr, nullptr);
    assemble_k<<<(2097152 + 255) / 256, 256>>>(x_input, xdec, pos_emb, x);

    for (int li = 0; li < 4; li++) {
        rmsnorm_pack_k<<<2048, 256>>>(x, attn_norm_w + (size_t)li * 1024, apk);
        cudaStreamWaitEvent(0, evPack[li], 0);   // layer-li weights packed
        if (li == 0) cudaStreamWaitEvent(0, evRope, 0);
        // QKV with fused l2norm+RoPE+layout epilogue (mode 2)
        gemm_v2_k<<<dim3(24, 16), 128, V2_SMEM>>>(
            apk, qkvp + (size_t)li * 3145728, nullptr, nullptr, 3072, 1024, 2,
            cosT, sinT, qr, ktb_, vr);
        attn_k<<<dim3(128, 16, 2), 256>>>(qr, ktb_, vr, doc, apk);
        gemm_v2_k<<<dim3(8, 16), 128, V2_SMEM>>>(apk, wop + (size_t)li * 1048576, x1, x, 1024, 1024, 0,
            nullptr, nullptr, nullptr, nullptr, nullptr);
        rmsnorm_pack_k<<<2048, 256>>>(x1, ffn_norm_w + (size_t)li * 1024, apk);
        gemm_v2_k<<<dim3(32, 16), 128, V2_SMEM>>>(
            apk, upp + (size_t)li * 4194304, hbp, nullptr, 4096, 1024, 1,
            nullptr, nullptr, nullptr, nullptr, nullptr);
        gemm_v2_k<<<dim3(8, 16), 128, V2_SMEM>>>(hbp, dwnp + (size_t)li * 2097152, x, x1, 1024, 2048, 0,
            nullptr, nullptr, nullptr, nullptr, nullptr);
    }

    gather_k<<<(1048576 + 255) / 256, 256>>>(x, (float*)d_out);
}